// round 6
// baseline (speedup 1.0000x reference)
#include <cuda_runtime.h>
#include <math.h>

#define BB 64
#define SS 256
#define HH 768
#define G4 3072          // 4*H
#define TT 255           // decode steps
#define SLEN (2*SS+2)    // 514
#define WLEN (SS+1)      // 257
#define NB_LSTM 96
#define NB_DEC  289

// ------------------- device scratch (BSS zero-initialized) -------------------
__device__ float g_gi_f[(size_t)SS*BB*G4];
__device__ float g_gi_b[(size_t)SS*BB*G4];
__device__ float g_lstm_out[(size_t)BB*SS*2*HH];  // [b][t][2H]
__device__ float g_pre1[(size_t)TT*BB*G4];        // x_prev @ subw_Wih.T + b
__device__ float g_sh[(size_t)BB*SLEN*HH];
__device__ float g_sc[(size_t)BB*SLEN*HH];
__device__ float g_wh[(size_t)BB*WLEN*HH];
__device__ float g_wc[(size_t)BB*WLEN*HH];
__device__ float g_bpart[3*BB*G4];
__device__ float g_hstate[4*BB*HH];
__device__ float g_cstate[2*BB*HH];
__device__ float g_h1[BB*HH];
__device__ float g_c1[BB*HH];
__device__ float g_whbuf[BB*HH];
__device__ float g_ccur[TT*BB*2];
__device__ int   g_spa[TT*BB];
__device__ int   g_wpa[TT*BB];

// monotonic grid-barrier ticket (never reset; replay-safe via base snapshots)
__device__ unsigned g_tick;
__device__ unsigned g_base_lstm;
__device__ unsigned g_base_dec;

__device__ __forceinline__ float sigf(float x){ return 1.f/(1.f+expf(-x)); }

__device__ __forceinline__ void gbar(unsigned target)
{
    __syncthreads();
    if (threadIdx.x == 0) {
        __threadfence();
        atomicAdd(&g_tick, 1u);
        volatile unsigned* vt = &g_tick;
        while (*vt < target) __nanosleep(64);
        __threadfence();
    }
    __syncthreads();
}

// ------------------- zero per-launch states + snapshot lstm barrier base ------
__global__ void zero_states()
{
    int gt = blockIdx.x*blockDim.x + threadIdx.x;
    if (gt == 0) g_base_lstm = g_tick;
    int stride = gridDim.x*blockDim.x;
    for (int i = gt; i < 4*BB*HH; i += stride) g_hstate[i]=0.f;
    for (int i = gt; i < 2*BB*HH; i += stride) g_cstate[i]=0.f;
}

// ------------------- precompute stack pointers from golds -------------------
__global__ void ptr_kernel(const int* __restrict__ golds)
{
    int b = threadIdx.x;
    if (b >= BB) return;
    int sp = 0, wp = 0;
    for (int t = 0; t < TT; t++) {
        g_spa[t*BB+b] = sp;
        g_wpa[t*BB+b] = wp;
        int g = golds[b*SS + t + 1];
        sp += (g==0) ? 1 : 2;
        wp += (g==0) ? 0 : 1;
    }
}

// ------------------- big GEMM: 128x128 tile, 8x8 per thread -------------------
__global__ __launch_bounds__(256) void gemm_big(
    const float* __restrict__ A, const float* __restrict__ W,
    const float* __restrict__ bias, float* __restrict__ C, int K, int Mtot)
{
    __shared__ float As[8][132];
    __shared__ float Ws[8][132];
    const int tid = threadIdx.x;
    const int bm = blockIdx.y << 7, bn = blockIdx.x << 7;
    const int lrow = tid >> 1, lk = (tid & 1) << 2;
    const int ar = bm + lrow;
    const float* arow = A + ((size_t)(ar & 63) * SS + (ar >> 6)) * K;
    const float* wrow = W + (size_t)(bn + lrow) * K;
    const bool aval = ar < Mtot;
    const int tx = tid & 15, ty = tid >> 4;
    float acc[8][8] = {};
    for (int k0 = 0; k0 < K; k0 += 8) {
        float4 av = aval ? *(const float4*)(arow + k0 + lk) : make_float4(0.f,0.f,0.f,0.f);
        float4 wv = *(const float4*)(wrow + k0 + lk);
        __syncthreads();
        As[lk+0][lrow]=av.x; As[lk+1][lrow]=av.y; As[lk+2][lrow]=av.z; As[lk+3][lrow]=av.w;
        Ws[lk+0][lrow]=wv.x; Ws[lk+1][lrow]=wv.y; Ws[lk+2][lrow]=wv.z; Ws[lk+3][lrow]=wv.w;
        __syncthreads();
        #pragma unroll
        for (int kk = 0; kk < 8; kk++) {
            float af[8], wf[8];
            *(float4*)&af[0] = *(const float4*)&As[kk][ty<<3];
            *(float4*)&af[4] = *(const float4*)&As[kk][(ty<<3)+4];
            *(float4*)&wf[0] = *(const float4*)&Ws[kk][tx<<3];
            *(float4*)&wf[4] = *(const float4*)&Ws[kk][(tx<<3)+4];
            #pragma unroll
            for (int i=0;i<8;i++)
                #pragma unroll
                for (int j=0;j<8;j++) acc[i][j] += af[i]*wf[j];
        }
    }
    #pragma unroll
    for (int i=0;i<8;i++) {
        int row = bm + (ty<<3) + i;
        if (row < Mtot) {
            #pragma unroll
            for (int j=0;j<8;j++) {
                int col = bn + (tx<<3) + j;
                C[(size_t)row*G4 + col] = acc[i][j] + bias[col];
            }
        }
    }
}

// ------------------- 768-K accumulator (64b x 16j x 4 gates) ------------------
__device__ __forceinline__ void accum_seg(
    float acc[4][4], const float* __restrict__ srcrow, const float* __restrict__ wrow,
    float (*hs)[64], float (*ws)[64], int tid)
{
    const int lrow = tid >> 2, lk4 = (tid & 3) << 2;
    const int jj = tid & 15, mg = tid >> 4;
    for (int k0 = 0; k0 < HH; k0 += 32) {
        float4 h1v = *(const float4*)(srcrow + k0 + lk4);
        float4 h2v = *(const float4*)(srcrow + k0 + 16 + lk4);
        float4 w1v = *(const float4*)(wrow + k0 + lk4);
        float4 w2v = *(const float4*)(wrow + k0 + 16 + lk4);
        __syncthreads();
        hs[lk4+0][lrow]=h1v.x; hs[lk4+1][lrow]=h1v.y; hs[lk4+2][lrow]=h1v.z; hs[lk4+3][lrow]=h1v.w;
        hs[16+lk4+0][lrow]=h2v.x; hs[16+lk4+1][lrow]=h2v.y; hs[16+lk4+2][lrow]=h2v.z; hs[16+lk4+3][lrow]=h2v.w;
        ws[lk4+0][lrow]=w1v.x; ws[lk4+1][lrow]=w1v.y; ws[lk4+2][lrow]=w1v.z; ws[lk4+3][lrow]=w1v.w;
        ws[16+lk4+0][lrow]=w2v.x; ws[16+lk4+1][lrow]=w2v.y; ws[16+lk4+2][lrow]=w2v.z; ws[16+lk4+3][lrow]=w2v.w;
        __syncthreads();
        #pragma unroll
        for (int kk = 0; kk < 32; kk++) {
            float4 a = *(const float4*)&hs[kk][mg<<2];
            float4 w = *(const float4*)&ws[kk][jj<<2];
            float aa[4]={a.x,a.y,a.z,a.w}, wwv[4]={w.x,w.y,w.z,w.w};
            #pragma unroll
            for (int mi=0;mi<4;mi++)
                #pragma unroll
                for (int g=0;g<4;g++) acc[mi][g] += aa[mi]*wwv[g];
        }
    }
}

// ------------------- persistent BiLSTM: 96 blocks, 256 steps ------------------
__global__ __launch_bounds__(256, 1) void lstm_persist(
    const float* __restrict__ Whh_f, const float* __restrict__ Whh_b)
{
    __shared__ float hs[32][64], ws[32][64];
    const int tid = threadIdx.x;
    const int bid = blockIdx.x;
    const int dir = bid / 48;
    const int j0 = (bid % 48) << 4;
    const unsigned base = g_base_lstm;
    const float* Whh = dir ? Whh_b : Whh_f;
    const float* gibase = dir ? g_gi_b : g_gi_f;
    float* cst = g_cstate + (size_t)dir*BB*HH;
    const int lrow = tid >> 2;
    const float* wrow = Whh + (size_t)((lrow&3)*HH + j0 + (lrow>>2)) * HH;
    const int jj = tid & 15, mg = tid >> 4;
    const int j = j0 + jj;

    for (int t = 0; t < SS; t++) {
        const int tt = dir ? (SS-1-t) : t;
        const float* gi = gibase + (size_t)tt*BB*G4;
        const float* hin = g_hstate + (size_t)(dir*2 + (t&1))*BB*HH;
        float* hout = g_hstate + (size_t)(dir*2 + ((t&1)^1))*BB*HH;
        const float* srcrow = hin + lrow*HH;
        float acc[4][4] = {};
        accum_seg(acc, srcrow, wrow, hs, ws, tid);
        #pragma unroll
        for (int mi=0; mi<4; mi++) {
            int b = (mg<<2) + mi;
            float vi = gi[b*G4 +        j] + acc[mi][0];
            float vf = gi[b*G4 + HH +   j] + acc[mi][1];
            float vg = gi[b*G4 + 2*HH + j] + acc[mi][2];
            float vo = gi[b*G4 + 3*HH + j] + acc[mi][3];
            float c = sigf(vf)*cst[b*HH+j] + sigf(vi)*tanhf(vg);
            float h = sigf(vo)*tanhf(c);
            cst[b*HH+j] = c;
            hout[b*HH+j] = h;
            g_lstm_out[((size_t)b*SS + tt)*(2*HH) + dir*HH + j] = h;
        }
        if (t < SS-1) gbar(base + (unsigned)(t+1)*NB_LSTM);
    }
}

// ------------- narrow-tile 768-K accumulator (64b x 8j x 4 gates) -------------
__device__ __forceinline__ void accum_narrow(
    float acc[2][4], const float* __restrict__ srcrow, const float* __restrict__ wrow,
    float* hs, float* ws, int tid)
{
    const int ar = tid >> 2, ak = (tid & 3) << 2;
    const int wr_ = tid >> 3, wk = (tid & 7) << 2;
    const int jj = tid & 7, mg = tid >> 3;
    for (int k0 = 0; k0 < HH; k0 += 32) {
        float4 a1 = *(const float4*)(srcrow + k0 + ak);
        float4 a2 = *(const float4*)(srcrow + k0 + 16 + ak);
        float4 wv = *(const float4*)(wrow + k0 + wk);
        __syncthreads();
        hs[(ak+0)*66+ar]=a1.x; hs[(ak+1)*66+ar]=a1.y; hs[(ak+2)*66+ar]=a1.z; hs[(ak+3)*66+ar]=a1.w;
        hs[(16+ak+0)*66+ar]=a2.x; hs[(16+ak+1)*66+ar]=a2.y; hs[(16+ak+2)*66+ar]=a2.z; hs[(16+ak+3)*66+ar]=a2.w;
        ws[(wk+0)*36+wr_]=wv.x; ws[(wk+1)*36+wr_]=wv.y; ws[(wk+2)*36+wr_]=wv.z; ws[(wk+3)*36+wr_]=wv.w;
        __syncthreads();
        #pragma unroll
        for (int kk = 0; kk < 32; kk++) {
            float2 a = *(const float2*)&hs[kk*66 + (mg<<1)];
            float4 w = *(const float4*)&ws[kk*36 + (jj<<2)];
            float wwv[4]={w.x,w.y,w.z,w.w};
            #pragma unroll
            for (int g=0; g<4; g++) { acc[0][g] += a.x*wwv[g]; acc[1][g] += a.y*wwv[g]; }
        }
    }
}

// ------------------- persistent decode: 289 blocks, 255 steps -----------------
__global__ __launch_bounds__(256, 2) void decode_persist(
    const float* __restrict__ subw_Whh,
    const float* __restrict__ word_Wih, const float* __restrict__ word_Whh,
    const float* __restrict__ word_b,
    const float* __restrict__ clsW, float* __restrict__ out)
{
    __shared__ float hs[32*66];
    __shared__ float ws[32*36];
    __shared__ int idx_s[BB];
    const int tid = threadIdx.x;
    const int bid = blockIdx.x;
    const unsigned base = g_base_dec;

    for (int t = 0; t <= TT; t++) {
        // ---------- phase A ----------
        if (bid < 96 && t < TT) {
            // subword cell, tile j0 = bid*8
            if (tid < BB) idx_s[tid] = g_spa[t*BB + tid];
            __syncthreads();
            const int j0 = bid << 3;
            const float* gi = g_pre1 + (size_t)t*BB*G4;
            const int ar = tid >> 2;
            const float* srcrow = g_sh + ((size_t)ar*SLEN + idx_s[ar]) * HH;
            const int wr_ = tid >> 3;
            const float* wrow = subw_Whh + (size_t)((wr_&3)*HH + j0 + (wr_>>2)) * HH;
            float acc[2][4] = {};
            accum_narrow(acc, srcrow, wrow, hs, ws, tid);
            const int jj = tid & 7, mg = tid >> 3;
            const int j = j0 + jj;
            #pragma unroll
            for (int mi=0; mi<2; mi++) {
                int b = (mg<<1) + mi;
                int sp = idx_s[b];
                float vi = gi[b*G4 +        j] + acc[mi][0];
                float vf = gi[b*G4 + HH +   j] + acc[mi][1];
                float vg = gi[b*G4 + 2*HH + j] + acc[mi][2];
                float vo = gi[b*G4 + 3*HH + j] + acc[mi][3];
                float c = sigf(vf)*g_sc[((size_t)b*SLEN + sp)*HH + j] + sigf(vi)*tanhf(vg);
                float h = sigf(vo)*tanhf(c);
                g_sh[((size_t)b*SLEN + sp + 1)*HH + j] = h;
                g_sc[((size_t)b*SLEN + sp + 1)*HH + j] = c;
                g_h1[b*HH+j] = h;
                g_c1[b*HH+j] = c;
            }
        } else if (bid >= 96 && bid < 288 && t > 0) {
            // epilogue for step u = t-1: sum partials + word cell
            const int u = t - 1;
            const int tile = bid - 96;          // 0..191
            const int b = tile / 3;
            const int j = (tile % 3)*256 + tid;
            const int wp = g_wpa[u*BB + b];
            float v[4];
            #pragma unroll
            for (int g=0; g<4; g++) {
                int n = g*HH + j;
                v[g] = word_b[n] + g_bpart[(size_t)b*G4 + n]
                                 + g_bpart[(size_t)(BB + b)*G4 + n]
                                 + g_bpart[(size_t)(2*BB + b)*G4 + n];
            }
            float c = sigf(v[1])*g_wc[((size_t)b*WLEN + wp)*HH + j] + sigf(v[0])*tanhf(v[2]);
            float h = sigf(v[3])*tanhf(c);
            g_wh[((size_t)b*WLEN + wp + 1)*HH + j] = h;
            g_wc[((size_t)b*WLEN + wp + 1)*HH + j] = c;
            g_whbuf[b*HH + j] = h;
        }
        gbar(base + (unsigned)(2*t+1)*NB_DEC);

        // ---------- phase B ----------
        if (bid < 288 && t < TT) {
            // word-cell GEMM partials, K split in 3 segments
            const int seg = bid / 96;
            const int j0 = (bid % 96) << 3;
            if (tid < BB) idx_s[tid] = g_wpa[t*BB + tid];
            __syncthreads();
            const int ar = tid >> 2;
            const int wr_ = tid >> 3;
            const int wn = (wr_&3)*HH + j0 + (wr_>>2);
            const float* srcrow;
            const float* wrow;
            if (seg == 0)      { srcrow = g_h1 + ar*HH;  wrow = word_Wih + (size_t)wn*(2*HH); }
            else if (seg == 1) { srcrow = g_c1 + ar*HH;  wrow = word_Wih + (size_t)wn*(2*HH) + HH; }
            else               { srcrow = g_wh + ((size_t)ar*WLEN + idx_s[ar])*HH;
                                 wrow = word_Whh + (size_t)wn*HH; }
            float acc[2][4] = {};
            accum_narrow(acc, srcrow, wrow, hs, ws, tid);
            const int jj = tid & 7, mg = tid >> 3;
            const int j = j0 + jj;
            float* part = g_bpart + (size_t)seg*BB*G4;
            #pragma unroll
            for (int mi=0; mi<2; mi++) {
                int b = (mg<<1) + mi;
                #pragma unroll
                for (int g=0; g<4; g++)
                    part[(size_t)b*G4 + g*HH + j] = acc[mi][g];
            }
        } else if (bid == 288 && t > 0) {
            // classifier for step u = t-1 -> output position u+1 = t
            const int u = t - 1;
            if (tid < 128) {
                int b = tid >> 1, c = tid & 1;
                const float* w = clsW + c*(3*HH);
                const float* hb = g_whbuf + b*HH;
                float s0 = g_ccur[u*BB*2 + (b<<1) + c], s1=0.f, s2=0.f, s3=0.f;
                #pragma unroll 4
                for (int k = 0; k < HH; k += 4) {
                    s0 += hb[k]*w[k];   s1 += hb[k+1]*w[k+1];
                    s2 += hb[k+2]*w[k+2]; s3 += hb[k+3]*w[k+3];
                }
                out[((size_t)b*SS + u + 1)*2 + c] = s0+s1+s2+s3;
            }
        }
        if (t < TT) gbar(base + (unsigned)(2*t+2)*NB_DEC);
    }
}

// -------- x_cur classifier halves + first row + decode barrier base snapshot ---
__global__ void ccur_kernel(const float* __restrict__ clsW, const float* __restrict__ clsb,
                            float* __restrict__ out)
{
    int gt = blockIdx.x*blockDim.x + threadIdx.x;
    if (gt == 0) g_base_dec = g_tick;
    int gw = gt >> 5, lane = gt & 31;
    if (gw < TT*BB*2) {
        int t = gw >> 7, rem = gw & 127, b = rem >> 1, c = rem & 1;
        const float* x = g_lstm_out + ((size_t)b*SS + t + 1)*(2*HH);
        const float* w = clsW + c*(3*HH) + HH;
        float s = 0.f;
        for (int k = lane; k < 2*HH; k += 32) s += x[k]*w[k];
        #pragma unroll
        for (int o = 16; o; o >>= 1) s += __shfl_xor_sync(0xffffffffu, s, o);
        if (lane == 0) g_ccur[gw] = s + clsb[c];
    }
    if (gt < 128) {
        int b = gt >> 1, c = gt & 1;
        out[(size_t)b*SS*2 + c] = c ? 1.f : -1.f;
    }
}

// ------------------- launch -------------------
extern "C" void kernel_launch(void* const* d_in, const int* in_sizes, int n_in,
                              void* d_out, int out_size)
{
    const int dictOrder = (in_sizes[1] == BB*SS);
    const float* hsin = (const float*)d_in[0];
    const int* golds;
    const float *Wih_f,*Whh_f,*b_f,*Wih_b,*Whh_b,*b_b;
    const float *subw_Wih,*subw_Whh,*subw_b,*word_Wih,*word_Whh,*word_b,*clsW,*clsb;
    if (dictOrder) {
        golds    = (const int*)  d_in[1];
        Wih_f    = (const float*)d_in[2];  Whh_f   = (const float*)d_in[3];
        b_f      = (const float*)d_in[4];  Wih_b   = (const float*)d_in[5];
        Whh_b    = (const float*)d_in[6];  b_b     = (const float*)d_in[7];
        subw_Wih = (const float*)d_in[8];  subw_Whh= (const float*)d_in[9];
        subw_b   = (const float*)d_in[10]; word_Wih= (const float*)d_in[11];
        word_Whh = (const float*)d_in[12]; word_b  = (const float*)d_in[13];
        clsW     = (const float*)d_in[14]; clsb    = (const float*)d_in[15];
    } else {
        Wih_f    = (const float*)d_in[1];  Whh_f   = (const float*)d_in[2];
        b_f      = (const float*)d_in[3];  Wih_b   = (const float*)d_in[4];
        Whh_b    = (const float*)d_in[5];  b_b     = (const float*)d_in[6];
        subw_Wih = (const float*)d_in[7];  subw_Whh= (const float*)d_in[8];
        subw_b   = (const float*)d_in[9];  word_Wih= (const float*)d_in[10];
        word_Whh = (const float*)d_in[11]; word_b  = (const float*)d_in[12];
        clsW     = (const float*)d_in[13]; clsb    = (const float*)d_in[14];
        golds    = (const int*)  d_in[15];
    }
    float* out = (float*)d_out;

    float *p_gif, *p_gib, *p_lo, *p_pre1;
    cudaGetSymbolAddress((void**)&p_gif,  g_gi_f);
    cudaGetSymbolAddress((void**)&p_gib,  g_gi_b);
    cudaGetSymbolAddress((void**)&p_lo,   g_lstm_out);
    cudaGetSymbolAddress((void**)&p_pre1, g_pre1);

    zero_states<<<96, 256>>>();
    ptr_kernel<<<1, 64>>>(golds);

    // input-gate precompute: (16384,768)@(768,3072)+b, both directions
    gemm_big<<<dim3(24, 128), 256>>>(hsin, Wih_f, b_f, p_gif, HH, BB*SS);
    gemm_big<<<dim3(24, 128), 256>>>(hsin, Wih_b, b_b, p_gib, HH, BB*SS);

    // persistent BiLSTM recurrence (256 steps inside)
    lstm_persist<<<NB_LSTM, 256>>>(Whh_f, Whh_b);

    // subword input precompute: (16320,1536)@(1536,3072)+b
    gemm_big<<<dim3(24, 128), 256>>>(p_lo, subw_Wih, subw_b, p_pre1, 2*HH, TT*BB);

    // classifier x_cur halves + first output row + decode barrier base
    ccur_kernel<<<4080, 256>>>(clsW, clsb, out);

    // persistent decode (255 steps + tail inside)
    decode_persist<<<NB_DEC, 256>>>(subw_Whh, word_Wih, word_Whh, word_b, clsW, out);
}

// round 7
// speedup vs baseline: 1.5734x; 1.5734x over previous
#include <cuda_runtime.h>
#include <math.h>

#define BB 64
#define SS 256
#define HH 768
#define G4 3072          // 4*H
#define TT 255           // decode steps
#define SLEN (2*SS+2)    // 514
#define WLEN (SS+1)      // 257
#define NB_LSTM 96
#define NB_DEC  289

typedef unsigned long long u64t;
__device__ __forceinline__ u64t pack2(float lo, float hi){
    u64t r; asm("mov.b64 %0,{%1,%2};" : "=l"(r) : "f"(lo), "f"(hi)); return r;
}
__device__ __forceinline__ void fma2(u64t &d, u64t a, u64t b){
    asm("fma.rn.f32x2 %0,%1,%2,%0;" : "+l"(d) : "l"(a), "l"(b));
}
__device__ __forceinline__ void unpack2(u64t v, float &a, float &b){
    asm("mov.b64 {%0,%1},%2;" : "=f"(a), "=f"(b) : "l"(v));
}

// ------------------- device scratch (BSS zero-initialized) -------------------
__device__ float g_gi_f[(size_t)SS*BB*G4];
__device__ float g_gi_b[(size_t)SS*BB*G4];
__device__ float g_lstm_out[(size_t)BB*SS*2*HH];  // [b][t][2H]
__device__ float g_pre1[(size_t)TT*BB*G4];        // x_prev @ subw_Wih.T + b
__device__ float g_sh[(size_t)BB*SLEN*HH];
__device__ float g_sc[(size_t)BB*SLEN*HH];
__device__ float g_wh[(size_t)BB*WLEN*HH];
__device__ float g_wc[(size_t)BB*WLEN*HH];
__device__ float g_bpart[3*BB*G4];
__device__ float g_hstate[4*BB*HH];
__device__ float g_cstate[2*BB*HH];
__device__ float g_h1[BB*HH];
__device__ float g_c1[BB*HH];
__device__ float g_whbuf[BB*HH];
__device__ float g_ccur[TT*BB*2];
__device__ int   g_spa[TT*BB];
__device__ int   g_wpa[TT*BB];

// monotonic grid-barrier ticket (never reset; replay-safe via base snapshots)
__device__ unsigned g_tick;
__device__ unsigned g_base_lstm;
__device__ unsigned g_base_dec;

__device__ __forceinline__ float sigf(float x){ return 1.f/(1.f+expf(-x)); }

__device__ __forceinline__ void gbar(unsigned target)
{
    __syncthreads();
    if (threadIdx.x == 0) {
        __threadfence();
        atomicAdd(&g_tick, 1u);
        volatile unsigned* vt = &g_tick;
        while (*vt < target) __nanosleep(64);
        __threadfence();
    }
    __syncthreads();
}

// ------------------- zero per-launch states + snapshot lstm barrier base ------
__global__ void zero_states()
{
    int gt = blockIdx.x*blockDim.x + threadIdx.x;
    if (gt == 0) g_base_lstm = g_tick;
    int stride = gridDim.x*blockDim.x;
    for (int i = gt; i < 4*BB*HH; i += stride) g_hstate[i]=0.f;
    for (int i = gt; i < 2*BB*HH; i += stride) g_cstate[i]=0.f;
}

// ------------------- precompute stack pointers from golds -------------------
__global__ void ptr_kernel(const int* __restrict__ golds)
{
    int b = threadIdx.x;
    if (b >= BB) return;
    int sp = 0, wp = 0;
    for (int t = 0; t < TT; t++) {
        g_spa[t*BB+b] = sp;
        g_wpa[t*BB+b] = wp;
        int g = golds[b*SS + t + 1];
        sp += (g==0) ? 1 : 2;
        wp += (g==0) ? 0 : 1;
    }
}

// ------------------- big GEMM: 128x128 tile, 8x8 per thread, f32x2 ------------
__global__ __launch_bounds__(256) void gemm_big(
    const float* __restrict__ A, const float* __restrict__ W,
    const float* __restrict__ bias, float* __restrict__ C, int K, int Mtot)
{
    __shared__ float As[8][132];
    __shared__ float Ws[8][132];
    const int tid = threadIdx.x;
    const int bm = blockIdx.y << 7, bn = blockIdx.x << 7;
    const int lrow = tid >> 1, lk = (tid & 1) << 2;
    const int ar = bm + lrow;
    const float* arow = A + ((size_t)(ar & 63) * SS + (ar >> 6)) * K;
    const float* wrow = W + (size_t)(bn + lrow) * K;
    const bool aval = ar < Mtot;
    const int tx = tid & 15, ty = tid >> 4;
    u64t acc2[8][4] = {};
    for (int k0 = 0; k0 < K; k0 += 8) {
        float4 av = aval ? *(const float4*)(arow + k0 + lk) : make_float4(0.f,0.f,0.f,0.f);
        float4 wv = *(const float4*)(wrow + k0 + lk);
        __syncthreads();
        As[lk+0][lrow]=av.x; As[lk+1][lrow]=av.y; As[lk+2][lrow]=av.z; As[lk+3][lrow]=av.w;
        Ws[lk+0][lrow]=wv.x; Ws[lk+1][lrow]=wv.y; Ws[lk+2][lrow]=wv.z; Ws[lk+3][lrow]=wv.w;
        __syncthreads();
        #pragma unroll
        for (int kk = 0; kk < 8; kk++) {
            float4 a0 = *(const float4*)&As[kk][ty<<3];
            float4 a1 = *(const float4*)&As[kk][(ty<<3)+4];
            float4 w0 = *(const float4*)&Ws[kk][tx<<3];
            float4 w1 = *(const float4*)&Ws[kk][(tx<<3)+4];
            u64t w2[4] = { pack2(w0.x,w0.y), pack2(w0.z,w0.w),
                           pack2(w1.x,w1.y), pack2(w1.z,w1.w) };
            float aa[8] = {a0.x,a0.y,a0.z,a0.w,a1.x,a1.y,a1.z,a1.w};
            #pragma unroll
            for (int i=0;i<8;i++) {
                u64t ad = pack2(aa[i], aa[i]);
                fma2(acc2[i][0], ad, w2[0]);
                fma2(acc2[i][1], ad, w2[1]);
                fma2(acc2[i][2], ad, w2[2]);
                fma2(acc2[i][3], ad, w2[3]);
            }
        }
    }
    #pragma unroll
    for (int i=0;i<8;i++) {
        int row = bm + (ty<<3) + i;
        if (row < Mtot) {
            #pragma unroll
            for (int p=0;p<4;p++) {
                float v0, v1; unpack2(acc2[i][p], v0, v1);
                int col = bn + (tx<<3) + (p<<1);
                C[(size_t)row*G4 + col]     = v0 + bias[col];
                C[(size_t)row*G4 + col + 1] = v1 + bias[col+1];
            }
        }
    }
}

// ------------------- 768-K accumulator (64b x 16j x 4 gates), f32x2 -----------
// acc2[mi][0] = (gate0, gate1), acc2[mi][1] = (gate2, gate3)
__device__ __forceinline__ void accum_seg(
    u64t acc2[4][2], const float* __restrict__ srcrow, const float* __restrict__ wrow,
    float (*hs)[64], float (*ws)[64], int tid)
{
    const int lrow = tid >> 2, lk4 = (tid & 3) << 2;
    const int jj = tid & 15, mg = tid >> 4;
    for (int k0 = 0; k0 < HH; k0 += 32) {
        float4 h1v = *(const float4*)(srcrow + k0 + lk4);
        float4 h2v = *(const float4*)(srcrow + k0 + 16 + lk4);
        float4 w1v = *(const float4*)(wrow + k0 + lk4);
        float4 w2v = *(const float4*)(wrow + k0 + 16 + lk4);
        __syncthreads();
        hs[lk4+0][lrow]=h1v.x; hs[lk4+1][lrow]=h1v.y; hs[lk4+2][lrow]=h1v.z; hs[lk4+3][lrow]=h1v.w;
        hs[16+lk4+0][lrow]=h2v.x; hs[16+lk4+1][lrow]=h2v.y; hs[16+lk4+2][lrow]=h2v.z; hs[16+lk4+3][lrow]=h2v.w;
        ws[lk4+0][lrow]=w1v.x; ws[lk4+1][lrow]=w1v.y; ws[lk4+2][lrow]=w1v.z; ws[lk4+3][lrow]=w1v.w;
        ws[16+lk4+0][lrow]=w2v.x; ws[16+lk4+1][lrow]=w2v.y; ws[16+lk4+2][lrow]=w2v.z; ws[16+lk4+3][lrow]=w2v.w;
        __syncthreads();
        #pragma unroll
        for (int kk = 0; kk < 32; kk++) {
            float4 a = *(const float4*)&hs[kk][mg<<2];
            float4 w = *(const float4*)&ws[kk][jj<<2];
            u64t w01 = pack2(w.x,w.y), w23 = pack2(w.z,w.w);
            float aa[4]={a.x,a.y,a.z,a.w};
            #pragma unroll
            for (int mi=0;mi<4;mi++) {
                u64t ad = pack2(aa[mi], aa[mi]);
                fma2(acc2[mi][0], ad, w01);
                fma2(acc2[mi][1], ad, w23);
            }
        }
    }
}

// ------------------- persistent BiLSTM: 96 blocks, 256 steps ------------------
__global__ __launch_bounds__(256, 1) void lstm_persist(
    const float* __restrict__ Whh_f, const float* __restrict__ Whh_b)
{
    __shared__ float hs[32][64], ws[32][64];
    const int tid = threadIdx.x;
    const int bid = blockIdx.x;
    const int dir = bid / 48;
    const int j0 = (bid % 48) << 4;
    const unsigned base = g_base_lstm;
    const float* Whh = dir ? Whh_b : Whh_f;
    const float* gibase = dir ? g_gi_b : g_gi_f;
    float* cst = g_cstate + (size_t)dir*BB*HH;
    const int lrow = tid >> 2;
    const float* wrow = Whh + (size_t)((lrow&3)*HH + j0 + (lrow>>2)) * HH;
    const int jj = tid & 15, mg = tid >> 4;
    const int j = j0 + jj;

    for (int t = 0; t < SS; t++) {
        const int tt = dir ? (SS-1-t) : t;
        const float* gi = gibase + (size_t)tt*BB*G4;
        const float* hin = g_hstate + (size_t)(dir*2 + (t&1))*BB*HH;
        float* hout = g_hstate + (size_t)(dir*2 + ((t&1)^1))*BB*HH;
        const float* srcrow = hin + lrow*HH;
        u64t acc2[4][2] = {};
        accum_seg(acc2, srcrow, wrow, hs, ws, tid);
        #pragma unroll
        for (int mi=0; mi<4; mi++) {
            int b = (mg<<2) + mi;
            float a0,a1,a2,a3;
            unpack2(acc2[mi][0], a0, a1);
            unpack2(acc2[mi][1], a2, a3);
            float vi = gi[b*G4 +        j] + a0;
            float vf = gi[b*G4 + HH +   j] + a1;
            float vg = gi[b*G4 + 2*HH + j] + a2;
            float vo = gi[b*G4 + 3*HH + j] + a3;
            float c = sigf(vf)*cst[b*HH+j] + sigf(vi)*tanhf(vg);
            float h = sigf(vo)*tanhf(c);
            cst[b*HH+j] = c;
            hout[b*HH+j] = h;
            g_lstm_out[((size_t)b*SS + tt)*(2*HH) + dir*HH + j] = h;
        }
        if (t < SS-1) gbar(base + (unsigned)(t+1)*NB_LSTM);
    }
}

// ------------- narrow-tile 768-K accumulator (64b x 8j x 4 gates), f32x2 ------
__device__ __forceinline__ void accum_narrow(
    u64t acc2[2][2], const float* __restrict__ srcrow, const float* __restrict__ wrow,
    float* hs, float* ws, int tid)
{
    const int ar = tid >> 2, ak = (tid & 3) << 2;
    const int wr_ = tid >> 3, wk = (tid & 7) << 2;
    const int jj = tid & 7, mg = tid >> 3;
    for (int k0 = 0; k0 < HH; k0 += 32) {
        float4 a1 = *(const float4*)(srcrow + k0 + ak);
        float4 a2 = *(const float4*)(srcrow + k0 + 16 + ak);
        float4 wv = *(const float4*)(wrow + k0 + wk);
        __syncthreads();
        hs[(ak+0)*66+ar]=a1.x; hs[(ak+1)*66+ar]=a1.y; hs[(ak+2)*66+ar]=a1.z; hs[(ak+3)*66+ar]=a1.w;
        hs[(16+ak+0)*66+ar]=a2.x; hs[(16+ak+1)*66+ar]=a2.y; hs[(16+ak+2)*66+ar]=a2.z; hs[(16+ak+3)*66+ar]=a2.w;
        ws[(wk+0)*36+wr_]=wv.x; ws[(wk+1)*36+wr_]=wv.y; ws[(wk+2)*36+wr_]=wv.z; ws[(wk+3)*36+wr_]=wv.w;
        __syncthreads();
        #pragma unroll
        for (int kk = 0; kk < 32; kk++) {
            float2 a = *(const float2*)&hs[kk*66 + (mg<<1)];
            float4 w = *(const float4*)&ws[kk*36 + (jj<<2)];
            u64t w01 = pack2(w.x,w.y), w23 = pack2(w.z,w.w);
            u64t ad0 = pack2(a.x,a.x), ad1 = pack2(a.y,a.y);
            fma2(acc2[0][0], ad0, w01); fma2(acc2[0][1], ad0, w23);
            fma2(acc2[1][0], ad1, w01); fma2(acc2[1][1], ad1, w23);
        }
    }
}

// ------------------- persistent decode: 289 blocks, 255 steps -----------------
__global__ __launch_bounds__(256, 2) void decode_persist(
    const float* __restrict__ subw_Whh,
    const float* __restrict__ word_Wih, const float* __restrict__ word_Whh,
    const float* __restrict__ word_b,
    const float* __restrict__ clsW, float* __restrict__ out)
{
    __shared__ float hs[32*66];
    __shared__ float ws[32*36];
    __shared__ int idx_s[BB];
    const int tid = threadIdx.x;
    const int bid = blockIdx.x;
    const unsigned base = g_base_dec;

    for (int t = 0; t <= TT; t++) {
        // ---------- phase A ----------
        if (bid < 96 && t < TT) {
            // subword cell, tile j0 = bid*8
            if (tid < BB) idx_s[tid] = g_spa[t*BB + tid];
            __syncthreads();
            const int j0 = bid << 3;
            const float* gi = g_pre1 + (size_t)t*BB*G4;
            const int ar = tid >> 2;
            const float* srcrow = g_sh + ((size_t)ar*SLEN + idx_s[ar]) * HH;
            const int wr_ = tid >> 3;
            const float* wrow = subw_Whh + (size_t)((wr_&3)*HH + j0 + (wr_>>2)) * HH;
            u64t acc2[2][2] = {};
            accum_narrow(acc2, srcrow, wrow, hs, ws, tid);
            const int jj = tid & 7, mg = tid >> 3;
            const int j = j0 + jj;
            #pragma unroll
            for (int mi=0; mi<2; mi++) {
                int b = (mg<<1) + mi;
                int sp = idx_s[b];
                float a0,a1,a2,a3;
                unpack2(acc2[mi][0], a0, a1);
                unpack2(acc2[mi][1], a2, a3);
                float vi = gi[b*G4 +        j] + a0;
                float vf = gi[b*G4 + HH +   j] + a1;
                float vg = gi[b*G4 + 2*HH + j] + a2;
                float vo = gi[b*G4 + 3*HH + j] + a3;
                float c = sigf(vf)*g_sc[((size_t)b*SLEN + sp)*HH + j] + sigf(vi)*tanhf(vg);
                float h = sigf(vo)*tanhf(c);
                g_sh[((size_t)b*SLEN + sp + 1)*HH + j] = h;
                g_sc[((size_t)b*SLEN + sp + 1)*HH + j] = c;
                g_h1[b*HH+j] = h;
                g_c1[b*HH+j] = c;
            }
        } else if (bid >= 96 && bid < 288 && t > 0) {
            // epilogue for step u = t-1: sum partials + word cell
            const int u = t - 1;
            const int tile = bid - 96;          // 0..191
            const int b = tile / 3;
            const int j = (tile % 3)*256 + tid;
            const int wp = g_wpa[u*BB + b];
            float v[4];
            #pragma unroll
            for (int g=0; g<4; g++) {
                int n = g*HH + j;
                v[g] = word_b[n] + g_bpart[(size_t)b*G4 + n]
                                 + g_bpart[(size_t)(BB + b)*G4 + n]
                                 + g_bpart[(size_t)(2*BB + b)*G4 + n];
            }
            float c = sigf(v[1])*g_wc[((size_t)b*WLEN + wp)*HH + j] + sigf(v[0])*tanhf(v[2]);
            float h = sigf(v[3])*tanhf(c);
            g_wh[((size_t)b*WLEN + wp + 1)*HH + j] = h;
            g_wc[((size_t)b*WLEN + wp + 1)*HH + j] = c;
            g_whbuf[b*HH + j] = h;
        }
        gbar(base + (unsigned)(2*t+1)*NB_DEC);

        // ---------- phase B ----------
        if (bid < 288 && t < TT) {
            // word-cell GEMM partials, K split in 3 segments
            const int seg = bid / 96;
            const int j0 = (bid % 96) << 3;
            if (tid < BB) idx_s[tid] = g_wpa[t*BB + tid];
            __syncthreads();
            const int ar = tid >> 2;
            const int wr_ = tid >> 3;
            const int wn = (wr_&3)*HH + j0 + (wr_>>2);
            const float* srcrow;
            const float* wrow;
            if (seg == 0)      { srcrow = g_h1 + ar*HH;  wrow = word_Wih + (size_t)wn*(2*HH); }
            else if (seg == 1) { srcrow = g_c1 + ar*HH;  wrow = word_Wih + (size_t)wn*(2*HH) + HH; }
            else               { srcrow = g_wh + ((size_t)ar*WLEN + idx_s[ar])*HH;
                                 wrow = word_Whh + (size_t)wn*HH; }
            u64t acc2[2][2] = {};
            accum_narrow(acc2, srcrow, wrow, hs, ws, tid);
            const int jj = tid & 7, mg = tid >> 3;
            const int j = j0 + jj;
            float* part = g_bpart + (size_t)seg*BB*G4;
            #pragma unroll
            for (int mi=0; mi<2; mi++) {
                int b = (mg<<1) + mi;
                float a0,a1,a2,a3;
                unpack2(acc2[mi][0], a0, a1);
                unpack2(acc2[mi][1], a2, a3);
                part[(size_t)b*G4 +          j] = a0;
                part[(size_t)b*G4 +   HH +   j] = a1;
                part[(size_t)b*G4 + 2*HH +   j] = a2;
                part[(size_t)b*G4 + 3*HH +   j] = a3;
            }
        } else if (bid == 288 && t > 0) {
            // classifier for step u = t-1 -> output position u+1 = t
            const int u = t - 1;
            if (tid < 128) {
                int b = tid >> 1, c = tid & 1;
                const float* w = clsW + c*(3*HH);
                const float* hb = g_whbuf + b*HH;
                float s0 = g_ccur[u*BB*2 + (b<<1) + c], s1=0.f, s2=0.f, s3=0.f;
                #pragma unroll 4
                for (int k = 0; k < HH; k += 4) {
                    s0 += hb[k]*w[k];   s1 += hb[k+1]*w[k+1];
                    s2 += hb[k+2]*w[k+2]; s3 += hb[k+3]*w[k+3];
                }
                out[((size_t)b*SS + u + 1)*2 + c] = s0+s1+s2+s3;
            }
        }
        if (t < TT) gbar(base + (unsigned)(2*t+2)*NB_DEC);
    }
}

// -------- x_cur classifier halves + first row + decode barrier base snapshot ---
__global__ void ccur_kernel(const float* __restrict__ clsW, const float* __restrict__ clsb,
                            float* __restrict__ out)
{
    int gt = blockIdx.x*blockDim.x + threadIdx.x;
    if (gt == 0) g_base_dec = g_tick;
    int gw = gt >> 5, lane = gt & 31;
    if (gw < TT*BB*2) {
        int t = gw >> 7, rem = gw & 127, b = rem >> 1, c = rem & 1;
        const float* x = g_lstm_out + ((size_t)b*SS + t + 1)*(2*HH);
        const float* w = clsW + c*(3*HH) + HH;
        float s = 0.f;
        for (int k = lane; k < 2*HH; k += 32) s += x[k]*w[k];
        #pragma unroll
        for (int o = 16; o; o >>= 1) s += __shfl_xor_sync(0xffffffffu, s, o);
        if (lane == 0) g_ccur[gw] = s + clsb[c];
    }
    if (gt < 128) {
        int b = gt >> 1, c = gt & 1;
        out[(size_t)b*SS*2 + c] = c ? 1.f : -1.f;
    }
}

// ------------------- launch -------------------
extern "C" void kernel_launch(void* const* d_in, const int* in_sizes, int n_in,
                              void* d_out, int out_size)
{
    const int dictOrder = (in_sizes[1] == BB*SS);
    const float* hsin = (const float*)d_in[0];
    const int* golds;
    const float *Wih_f,*Whh_f,*b_f,*Wih_b,*Whh_b,*b_b;
    const float *subw_Wih,*subw_Whh,*subw_b,*word_Wih,*word_Whh,*word_b,*clsW,*clsb;
    if (dictOrder) {
        golds    = (const int*)  d_in[1];
        Wih_f    = (const float*)d_in[2];  Whh_f   = (const float*)d_in[3];
        b_f      = (const float*)d_in[4];  Wih_b   = (const float*)d_in[5];
        Whh_b    = (const float*)d_in[6];  b_b     = (const float*)d_in[7];
        subw_Wih = (const float*)d_in[8];  subw_Whh= (const float*)d_in[9];
        subw_b   = (const float*)d_in[10]; word_Wih= (const float*)d_in[11];
        word_Whh = (const float*)d_in[12]; word_b  = (const float*)d_in[13];
        clsW     = (const float*)d_in[14]; clsb    = (const float*)d_in[15];
    } else {
        Wih_f    = (const float*)d_in[1];  Whh_f   = (const float*)d_in[2];
        b_f      = (const float*)d_in[3];  Wih_b   = (const float*)d_in[4];
        Whh_b    = (const float*)d_in[5];  b_b     = (const float*)d_in[6];
        subw_Wih = (const float*)d_in[7];  subw_Whh= (const float*)d_in[8];
        subw_b   = (const float*)d_in[9];  word_Wih= (const float*)d_in[10];
        word_Whh = (const float*)d_in[11]; word_b  = (const float*)d_in[12];
        clsW     = (const float*)d_in[13]; clsb    = (const float*)d_in[14];
        golds    = (const int*)  d_in[15];
    }
    float* out = (float*)d_out;

    float *p_gif, *p_gib, *p_lo, *p_pre1;
    cudaGetSymbolAddress((void**)&p_gif,  g_gi_f);
    cudaGetSymbolAddress((void**)&p_gib,  g_gi_b);
    cudaGetSymbolAddress((void**)&p_lo,   g_lstm_out);
    cudaGetSymbolAddress((void**)&p_pre1, g_pre1);

    zero_states<<<96, 256>>>();
    ptr_kernel<<<1, 64>>>(golds);

    // input-gate precompute: (16384,768)@(768,3072)+b, both directions
    gemm_big<<<dim3(24, 128), 256>>>(hsin, Wih_f, b_f, p_gif, HH, BB*SS);
    gemm_big<<<dim3(24, 128), 256>>>(hsin, Wih_b, b_b, p_gib, HH, BB*SS);

    // persistent BiLSTM recurrence (256 steps inside)
    lstm_persist<<<NB_LSTM, 256>>>(Whh_f, Whh_b);

    // subword input precompute: (16320,1536)@(1536,3072)+b
    gemm_big<<<dim3(24, 128), 256>>>(p_lo, subw_Wih, subw_b, p_pre1, 2*HH, TT*BB);

    // classifier x_cur halves + first output row + decode barrier base
    ccur_kernel<<<4080, 256>>>(clsW, clsb, out);

    // persistent decode (255 steps + tail inside)
    decode_persist<<<NB_DEC, 256>>>(subw_Whh, word_Wih, word_Whh, word_b, clsW, out);
}

// round 8
// speedup vs baseline: 1.6240x; 1.0322x over previous
#include <cuda_runtime.h>
#include <math.h>

#define BB 64
#define SS 256
#define HH 768
#define G4 3072          // 4*H
#define TT 255           // decode steps
#define SLEN (2*SS+2)    // 514
#define WLEN (SS+1)      // 257
#define NB_LSTM 192
#define NB_DEC  289

typedef unsigned long long u64t;
__device__ __forceinline__ u64t pack2(float lo, float hi){
    u64t r; asm("mov.b64 %0,{%1,%2};" : "=l"(r) : "f"(lo), "f"(hi)); return r;
}
__device__ __forceinline__ void fma2(u64t &d, u64t a, u64t b){
    asm("fma.rn.f32x2 %0,%1,%2,%0;" : "+l"(d) : "l"(a), "l"(b));
}
__device__ __forceinline__ void unpack2(u64t v, float &a, float &b){
    asm("mov.b64 {%0,%1},%2;" : "=f"(a), "=f"(b) : "l"(v));
}

// ------------------- device scratch (BSS zero-initialized) -------------------
__device__ float g_gi_f[(size_t)SS*BB*G4];
__device__ float g_gi_b[(size_t)SS*BB*G4];
__device__ float g_lstm_out[(size_t)BB*SS*2*HH];  // [b][t][2H]
__device__ float g_pre1[(size_t)TT*BB*G4];        // x_prev @ subw_Wih.T + b
__device__ float g_sh[(size_t)BB*SLEN*HH];
__device__ float g_sc[(size_t)BB*SLEN*HH];
__device__ float g_wh[(size_t)BB*WLEN*HH];
__device__ float g_wc[(size_t)BB*WLEN*HH];
__device__ float g_bpart[3*BB*G4];
__device__ float g_hstate[4*BB*HH];
__device__ float g_cstate[2*BB*HH];
__device__ float g_h1[BB*HH];
__device__ float g_c1[BB*HH];
__device__ float g_whbuf[BB*HH];
__device__ float g_ccur[TT*BB*2];
__device__ int   g_spa[TT*BB];
__device__ int   g_wpa[TT*BB];

// monotonic grid-barrier ticket (never reset; replay-safe via base snapshots)
__device__ unsigned g_tick;
__device__ unsigned g_base_lstm;
__device__ unsigned g_base_dec;

__device__ __forceinline__ float sigf(float x){ return 1.f/(1.f+expf(-x)); }

__device__ __forceinline__ void gbar(unsigned target)
{
    __syncthreads();
    if (threadIdx.x == 0) {
        __threadfence();
        atomicAdd(&g_tick, 1u);
        volatile unsigned* vt = &g_tick;
        while (*vt < target) __nanosleep(64);
        __threadfence();
    }
    __syncthreads();
}

// ------------------- zero per-launch states + snapshot lstm barrier base ------
__global__ void zero_states()
{
    int gt = blockIdx.x*blockDim.x + threadIdx.x;
    if (gt == 0) g_base_lstm = g_tick;
    int stride = gridDim.x*blockDim.x;
    for (int i = gt; i < 4*BB*HH; i += stride) g_hstate[i]=0.f;
    for (int i = gt; i < 2*BB*HH; i += stride) g_cstate[i]=0.f;
}

// ------------------- precompute stack pointers from golds -------------------
__global__ void ptr_kernel(const int* __restrict__ golds)
{
    int b = threadIdx.x;
    if (b >= BB) return;
    int sp = 0, wp = 0;
    for (int t = 0; t < TT; t++) {
        g_spa[t*BB+b] = sp;
        g_wpa[t*BB+b] = wp;
        int g = golds[b*SS + t + 1];
        sp += (g==0) ? 1 : 2;
        wp += (g==0) ? 0 : 1;
    }
}

// ---------- big GEMM: 128x128 tile, 8x8 per thread, f32x2, prefetched ---------
__global__ __launch_bounds__(256) void gemm_big(
    const float* __restrict__ A, const float* __restrict__ W,
    const float* __restrict__ bias, float* __restrict__ C, int K, int Mtot)
{
    __shared__ float As[8][132];
    __shared__ float Ws[8][132];
    const int tid = threadIdx.x;
    const int bm = blockIdx.y << 7, bn = blockIdx.x << 7;
    const int lrow = tid >> 1, lk = (tid & 1) << 2;
    const int ar = bm + lrow;
    const float* arow = A + ((size_t)(ar & 63) * SS + (ar >> 6)) * K;
    const float* wrow = W + (size_t)(bn + lrow) * K;
    const bool aval = ar < Mtot;
    const int tx = tid & 15, ty = tid >> 4;
    u64t acc2[8][4] = {};
    float4 av = aval ? *(const float4*)(arow + lk) : make_float4(0.f,0.f,0.f,0.f);
    float4 wv = *(const float4*)(wrow + lk);
    for (int k0 = 0; k0 < K; k0 += 8) {
        __syncthreads();
        As[lk+0][lrow]=av.x; As[lk+1][lrow]=av.y; As[lk+2][lrow]=av.z; As[lk+3][lrow]=av.w;
        Ws[lk+0][lrow]=wv.x; Ws[lk+1][lrow]=wv.y; Ws[lk+2][lrow]=wv.z; Ws[lk+3][lrow]=wv.w;
        __syncthreads();
        if (k0 + 8 < K) {
            av = aval ? *(const float4*)(arow + k0 + 8 + lk) : make_float4(0.f,0.f,0.f,0.f);
            wv = *(const float4*)(wrow + k0 + 8 + lk);
        }
        #pragma unroll
        for (int kk = 0; kk < 8; kk++) {
            float4 a0 = *(const float4*)&As[kk][ty<<3];
            float4 a1 = *(const float4*)&As[kk][(ty<<3)+4];
            float4 w0 = *(const float4*)&Ws[kk][tx<<3];
            float4 w1 = *(const float4*)&Ws[kk][(tx<<3)+4];
            u64t w2[4] = { pack2(w0.x,w0.y), pack2(w0.z,w0.w),
                           pack2(w1.x,w1.y), pack2(w1.z,w1.w) };
            float aa[8] = {a0.x,a0.y,a0.z,a0.w,a1.x,a1.y,a1.z,a1.w};
            #pragma unroll
            for (int i=0;i<8;i++) {
                u64t ad = pack2(aa[i], aa[i]);
                fma2(acc2[i][0], ad, w2[0]);
                fma2(acc2[i][1], ad, w2[1]);
                fma2(acc2[i][2], ad, w2[2]);
                fma2(acc2[i][3], ad, w2[3]);
            }
        }
    }
    #pragma unroll
    for (int i=0;i<8;i++) {
        int row = bm + (ty<<3) + i;
        if (row < Mtot) {
            #pragma unroll
            for (int p=0;p<4;p++) {
                float v0, v1; unpack2(acc2[i][p], v0, v1);
                int col = bn + (tx<<3) + (p<<1);
                C[(size_t)row*G4 + col]     = v0 + bias[col];
                C[(size_t)row*G4 + col + 1] = v1 + bias[col+1];
            }
        }
    }
}

// ------- narrow-tile 768-K accumulator (64b x 8j x 4 gates), f32x2, prefetch --
__device__ __forceinline__ void accum_narrow(
    u64t acc2[2][2], const float* __restrict__ srcrow, const float* __restrict__ wrow,
    float* hs, float* ws, int tid)
{
    const int ar = tid >> 2, ak = (tid & 3) << 2;
    const int wr_ = tid >> 3, wk = (tid & 7) << 2;
    const int jj = tid & 7, mg = tid >> 3;
    float4 a1 = *(const float4*)(srcrow + ak);
    float4 a2 = *(const float4*)(srcrow + 16 + ak);
    float4 wv = *(const float4*)(wrow + wk);
    #pragma unroll 1
    for (int k0 = 0; k0 < HH; k0 += 32) {
        __syncthreads();
        hs[(ak+0)*66+ar]=a1.x; hs[(ak+1)*66+ar]=a1.y; hs[(ak+2)*66+ar]=a1.z; hs[(ak+3)*66+ar]=a1.w;
        hs[(16+ak+0)*66+ar]=a2.x; hs[(16+ak+1)*66+ar]=a2.y; hs[(16+ak+2)*66+ar]=a2.z; hs[(16+ak+3)*66+ar]=a2.w;
        ws[(wk+0)*36+wr_]=wv.x; ws[(wk+1)*36+wr_]=wv.y; ws[(wk+2)*36+wr_]=wv.z; ws[(wk+3)*36+wr_]=wv.w;
        __syncthreads();
        if (k0 + 32 < HH) {
            a1 = *(const float4*)(srcrow + k0 + 32 + ak);
            a2 = *(const float4*)(srcrow + k0 + 48 + ak);
            wv = *(const float4*)(wrow + k0 + 32 + wk);
        }
        #pragma unroll
        for (int kk = 0; kk < 32; kk++) {
            float2 a = *(const float2*)&hs[kk*66 + (mg<<1)];
            float4 w = *(const float4*)&ws[kk*36 + (jj<<2)];
            u64t w01 = pack2(w.x,w.y), w23 = pack2(w.z,w.w);
            u64t ad0 = pack2(a.x,a.x), ad1 = pack2(a.y,a.y);
            fma2(acc2[0][0], ad0, w01); fma2(acc2[0][1], ad0, w23);
            fma2(acc2[1][0], ad1, w01); fma2(acc2[1][1], ad1, w23);
        }
    }
}

// ------------------- persistent BiLSTM: 192 blocks, 256 steps -----------------
__global__ __launch_bounds__(256, 2) void lstm_persist(
    const float* __restrict__ Whh_f, const float* __restrict__ Whh_b)
{
    __shared__ float hs[32*66];
    __shared__ float ws[32*36];
    const int tid = threadIdx.x;
    const int bid = blockIdx.x;
    const int dir = bid / 96;
    const int j0 = (bid % 96) << 3;
    const unsigned base = g_base_lstm;
    const float* Whh = dir ? Whh_b : Whh_f;
    const float* gibase = dir ? g_gi_b : g_gi_f;
    float* cst = g_cstate + (size_t)dir*BB*HH;
    const int ar = tid >> 2;
    const int wr_ = tid >> 3;
    const float* wrow = Whh + (size_t)((wr_&3)*HH + j0 + (wr_>>2)) * HH;
    const int jj = tid & 7, mg = tid >> 3;
    const int j = j0 + jj;

    for (int t = 0; t < SS; t++) {
        const int tt = dir ? (SS-1-t) : t;
        const float* gi = gibase + (size_t)tt*BB*G4;
        const float* hin = g_hstate + (size_t)(dir*2 + (t&1))*BB*HH;
        float* hout = g_hstate + (size_t)(dir*2 + ((t&1)^1))*BB*HH;
        const float* srcrow = hin + ar*HH;
        u64t acc2[2][2] = {};
        accum_narrow(acc2, srcrow, wrow, hs, ws, tid);
        #pragma unroll
        for (int mi=0; mi<2; mi++) {
            int b = (mg<<1) + mi;
            float a0,a1,a2,a3;
            unpack2(acc2[mi][0], a0, a1);
            unpack2(acc2[mi][1], a2, a3);
            float vi = gi[b*G4 +        j] + a0;
            float vf = gi[b*G4 + HH +   j] + a1;
            float vg = gi[b*G4 + 2*HH + j] + a2;
            float vo = gi[b*G4 + 3*HH + j] + a3;
            float c = sigf(vf)*cst[b*HH+j] + sigf(vi)*tanhf(vg);
            float h = sigf(vo)*tanhf(c);
            cst[b*HH+j] = c;
            hout[b*HH+j] = h;
            g_lstm_out[((size_t)b*SS + tt)*(2*HH) + dir*HH + j] = h;
        }
        if (t < SS-1) gbar(base + (unsigned)(t+1)*NB_LSTM);
    }
}

// ------------------- persistent decode: 289 blocks, 255 steps -----------------
__global__ __launch_bounds__(256, 2) void decode_persist(
    const float* __restrict__ subw_Whh,
    const float* __restrict__ word_Wih, const float* __restrict__ word_Whh,
    const float* __restrict__ word_b,
    const float* __restrict__ clsW, float* __restrict__ out)
{
    __shared__ float hs[32*66];
    __shared__ float ws[32*36];
    __shared__ int idx_s[BB];
    const int tid = threadIdx.x;
    const int bid = blockIdx.x;
    const unsigned base = g_base_dec;

    for (int t = 0; t <= TT; t++) {
        // ---------- phase A ----------
        if (bid < 96 && t < TT) {
            // subword cell, tile j0 = bid*8
            if (tid < BB) idx_s[tid] = g_spa[t*BB + tid];
            __syncthreads();
            const int j0 = bid << 3;
            const float* gi = g_pre1 + (size_t)t*BB*G4;
            const int ar = tid >> 2;
            const float* srcrow = g_sh + ((size_t)ar*SLEN + idx_s[ar]) * HH;
            const int wr_ = tid >> 3;
            const float* wrow = subw_Whh + (size_t)((wr_&3)*HH + j0 + (wr_>>2)) * HH;
            u64t acc2[2][2] = {};
            accum_narrow(acc2, srcrow, wrow, hs, ws, tid);
            const int jj = tid & 7, mg = tid >> 3;
            const int j = j0 + jj;
            #pragma unroll
            for (int mi=0; mi<2; mi++) {
                int b = (mg<<1) + mi;
                int sp = idx_s[b];
                float a0,a1,a2,a3;
                unpack2(acc2[mi][0], a0, a1);
                unpack2(acc2[mi][1], a2, a3);
                float vi = gi[b*G4 +        j] + a0;
                float vf = gi[b*G4 + HH +   j] + a1;
                float vg = gi[b*G4 + 2*HH + j] + a2;
                float vo = gi[b*G4 + 3*HH + j] + a3;
                float c = sigf(vf)*g_sc[((size_t)b*SLEN + sp)*HH + j] + sigf(vi)*tanhf(vg);
                float h = sigf(vo)*tanhf(c);
                g_sh[((size_t)b*SLEN + sp + 1)*HH + j] = h;
                g_sc[((size_t)b*SLEN + sp + 1)*HH + j] = c;
                g_h1[b*HH+j] = h;
                g_c1[b*HH+j] = c;
            }
        } else if (bid >= 96 && bid < 288 && t > 0) {
            // epilogue for step u = t-1: sum partials + word cell
            const int u = t - 1;
            const int tile = bid - 96;          // 0..191
            const int b = tile / 3;
            const int j = (tile % 3)*256 + tid;
            const int wp = g_wpa[u*BB + b];
            float v[4];
            #pragma unroll
            for (int g=0; g<4; g++) {
                int n = g*HH + j;
                v[g] = word_b[n] + g_bpart[(size_t)b*G4 + n]
                                 + g_bpart[(size_t)(BB + b)*G4 + n]
                                 + g_bpart[(size_t)(2*BB + b)*G4 + n];
            }
            float c = sigf(v[1])*g_wc[((size_t)b*WLEN + wp)*HH + j] + sigf(v[0])*tanhf(v[2]);
            float h = sigf(v[3])*tanhf(c);
            g_wh[((size_t)b*WLEN + wp + 1)*HH + j] = h;
            g_wc[((size_t)b*WLEN + wp + 1)*HH + j] = c;
            g_whbuf[b*HH + j] = h;
        }
        gbar(base + (unsigned)(2*t+1)*NB_DEC);

        // ---------- phase B ----------
        if (bid < 288 && t < TT) {
            // word-cell GEMM partials, K split in 3 segments
            const int seg = bid / 96;
            const int j0 = (bid % 96) << 3;
            if (tid < BB) idx_s[tid] = g_wpa[t*BB + tid];
            __syncthreads();
            const int ar = tid >> 2;
            const int wr_ = tid >> 3;
            const int wn = (wr_&3)*HH + j0 + (wr_>>2);
            const float* srcrow;
            const float* wrow;
            if (seg == 0)      { srcrow = g_h1 + ar*HH;  wrow = word_Wih + (size_t)wn*(2*HH); }
            else if (seg == 1) { srcrow = g_c1 + ar*HH;  wrow = word_Wih + (size_t)wn*(2*HH) + HH; }
            else               { srcrow = g_wh + ((size_t)ar*WLEN + idx_s[ar])*HH;
                                 wrow = word_Whh + (size_t)wn*HH; }
            u64t acc2[2][2] = {};
            accum_narrow(acc2, srcrow, wrow, hs, ws, tid);
            const int jj = tid & 7, mg = tid >> 3;
            const int j = j0 + jj;
            float* part = g_bpart + (size_t)seg*BB*G4;
            #pragma unroll
            for (int mi=0; mi<2; mi++) {
                int b = (mg<<1) + mi;
                float a0,a1,a2,a3;
                unpack2(acc2[mi][0], a0, a1);
                unpack2(acc2[mi][1], a2, a3);
                part[(size_t)b*G4 +          j] = a0;
                part[(size_t)b*G4 +   HH +   j] = a1;
                part[(size_t)b*G4 + 2*HH +   j] = a2;
                part[(size_t)b*G4 + 3*HH +   j] = a3;
            }
        } else if (bid == 288 && t > 0) {
            // classifier for step u = t-1 -> output position u+1 = t
            const int u = t - 1;
            if (tid < 128) {
                int b = tid >> 1, c = tid & 1;
                const float* w = clsW + c*(3*HH);
                const float* hb = g_whbuf + b*HH;
                float s0 = g_ccur[u*BB*2 + (b<<1) + c], s1=0.f, s2=0.f, s3=0.f;
                #pragma unroll 4
                for (int k = 0; k < HH; k += 4) {
                    s0 += hb[k]*w[k];   s1 += hb[k+1]*w[k+1];
                    s2 += hb[k+2]*w[k+2]; s3 += hb[k+3]*w[k+3];
                }
                out[((size_t)b*SS + u + 1)*2 + c] = s0+s1+s2+s3;
            }
        }
        if (t < TT) gbar(base + (unsigned)(2*t+2)*NB_DEC);
    }
}

// -------- x_cur classifier halves + first row + decode barrier base snapshot ---
__global__ void ccur_kernel(const float* __restrict__ clsW, const float* __restrict__ clsb,
                            float* __restrict__ out)
{
    int gt = blockIdx.x*blockDim.x + threadIdx.x;
    if (gt == 0) g_base_dec = g_tick;
    int gw = gt >> 5, lane = gt & 31;
    if (gw < TT*BB*2) {
        int t = gw >> 7, rem = gw & 127, b = rem >> 1, c = rem & 1;
        const float* x = g_lstm_out + ((size_t)b*SS + t + 1)*(2*HH);
        const float* w = clsW + c*(3*HH) + HH;
        float s = 0.f;
        for (int k = lane; k < 2*HH; k += 32) s += x[k]*w[k];
        #pragma unroll
        for (int o = 16; o; o >>= 1) s += __shfl_xor_sync(0xffffffffu, s, o);
        if (lane == 0) g_ccur[gw] = s + clsb[c];
    }
    if (gt < 128) {
        int b = gt >> 1, c = gt & 1;
        out[(size_t)b*SS*2 + c] = c ? 1.f : -1.f;
    }
}

// ------------------- launch -------------------
extern "C" void kernel_launch(void* const* d_in, const int* in_sizes, int n_in,
                              void* d_out, int out_size)
{
    const int dictOrder = (in_sizes[1] == BB*SS);
    const float* hsin = (const float*)d_in[0];
    const int* golds;
    const float *Wih_f,*Whh_f,*b_f,*Wih_b,*Whh_b,*b_b;
    const float *subw_Wih,*subw_Whh,*subw_b,*word_Wih,*word_Whh,*word_b,*clsW,*clsb;
    if (dictOrder) {
        golds    = (const int*)  d_in[1];
        Wih_f    = (const float*)d_in[2];  Whh_f   = (const float*)d_in[3];
        b_f      = (const float*)d_in[4];  Wih_b   = (const float*)d_in[5];
        Whh_b    = (const float*)d_in[6];  b_b     = (const float*)d_in[7];
        subw_Wih = (const float*)d_in[8];  subw_Whh= (const float*)d_in[9];
        subw_b   = (const float*)d_in[10]; word_Wih= (const float*)d_in[11];
        word_Whh = (const float*)d_in[12]; word_b  = (const float*)d_in[13];
        clsW     = (const float*)d_in[14]; clsb    = (const float*)d_in[15];
    } else {
        Wih_f    = (const float*)d_in[1];  Whh_f   = (const float*)d_in[2];
        b_f      = (const float*)d_in[3];  Wih_b   = (const float*)d_in[4];
        Whh_b    = (const float*)d_in[5];  b_b     = (const float*)d_in[6];
        subw_Wih = (const float*)d_in[7];  subw_Whh= (const float*)d_in[8];
        subw_b   = (const float*)d_in[9];  word_Wih= (const float*)d_in[10];
        word_Whh = (const float*)d_in[11]; word_b  = (const float*)d_in[12];
        clsW     = (const float*)d_in[13]; clsb    = (const float*)d_in[14];
        golds    = (const int*)  d_in[15];
    }
    float* out = (float*)d_out;

    float *p_gif, *p_gib, *p_lo, *p_pre1;
    cudaGetSymbolAddress((void**)&p_gif,  g_gi_f);
    cudaGetSymbolAddress((void**)&p_gib,  g_gi_b);
    cudaGetSymbolAddress((void**)&p_lo,   g_lstm_out);
    cudaGetSymbolAddress((void**)&p_pre1, g_pre1);

    zero_states<<<96, 256>>>();
    ptr_kernel<<<1, 64>>>(golds);

    // input-gate precompute: (16384,768)@(768,3072)+b, both directions
    gemm_big<<<dim3(24, 128), 256>>>(hsin, Wih_f, b_f, p_gif, HH, BB*SS);
    gemm_big<<<dim3(24, 128), 256>>>(hsin, Wih_b, b_b, p_gib, HH, BB*SS);

    // persistent BiLSTM recurrence (256 steps inside)
    lstm_persist<<<NB_LSTM, 256>>>(Whh_f, Whh_b);

    // subword input precompute: (16320,1536)@(1536,3072)+b
    gemm_big<<<dim3(24, 128), 256>>>(p_lo, subw_Wih, subw_b, p_pre1, 2*HH, TT*BB);

    // classifier x_cur halves + first output row + decode barrier base
    ccur_kernel<<<4080, 256>>>(clsW, clsb, out);

    // persistent decode (255 steps + tail inside)
    decode_persist<<<NB_DEC, 256>>>(subw_Whh, word_Wih, word_Whh, word_b, clsW, out);
}

// round 14
// speedup vs baseline: 1.7875x; 1.1007x over previous
#include <cuda_runtime.h>
#include <cuda_bf16.h>
#include <cstdint>
#include <math.h>

#define BB 64
#define SS 256
#define HH 768
#define G4 3072          // 4*H
#define TT 255           // decode steps
#define SLEN (2*SS+2)    // 514
#define WLEN (SS+1)      // 257
#define NB_LSTM 192
#define NB_DEC  289

typedef unsigned long long u64t;
__device__ __forceinline__ u64t pack2(float lo, float hi){
    u64t r; asm("mov.b64 %0,{%1,%2};" : "=l"(r) : "f"(lo), "f"(hi)); return r;
}
__device__ __forceinline__ void fma2(u64t &d, u64t a, u64t b){
    asm("fma.rn.f32x2 %0,%1,%2,%0;" : "+l"(d) : "l"(a), "l"(b));
}
__device__ __forceinline__ void unpack2(u64t v, float &a, float &b){
    asm("mov.b64 {%0,%1},%2;" : "=f"(a), "=f"(b) : "l"(v));
}

// ------------------- device scratch (BSS zero-initialized) -------------------
__device__ float g_gi_f[(size_t)SS*BB*G4];
__device__ float g_gi_b[(size_t)SS*BB*G4];
__device__ float g_lstm_out[(size_t)BB*SS*2*HH];  // [b][t][2H]
__device__ float g_pre1[(size_t)TT*BB*G4];        // x_prev @ subw_Wih.T + b
__device__ float g_sh[(size_t)BB*SLEN*HH];
__device__ float g_sc[(size_t)BB*SLEN*HH];
__device__ float g_wh[(size_t)BB*WLEN*HH];
__device__ float g_wc[(size_t)BB*WLEN*HH];
__device__ float g_bpart[3*BB*G4];
__device__ float g_hstate[4*BB*HH];
__device__ float g_cstate[2*BB*HH];
__device__ float g_h1[BB*HH];
__device__ float g_c1[BB*HH];
__device__ float g_whbuf[BB*HH];
__device__ float g_ccur[TT*BB*2];
__device__ int   g_spa[TT*BB];
__device__ int   g_wpa[TT*BB];

// split-bf16 operand buffers for tensor-core GEMMs
__device__ __nv_bfloat16 g_Ah[(size_t)16384*1536];
__device__ __nv_bfloat16 g_Al[(size_t)16384*1536];
__device__ __nv_bfloat16 g_Wbh[(size_t)3072*1536];
__device__ __nv_bfloat16 g_Wbl[(size_t)3072*1536];

// monotonic grid-barrier ticket (never reset; replay-safe via base snapshots)
__device__ unsigned g_tick;
__device__ unsigned g_base_lstm;
__device__ unsigned g_base_dec;

__device__ __forceinline__ float sigf(float x){ return 1.f/(1.f+expf(-x)); }

__device__ __forceinline__ void gbar(unsigned target)
{
    __syncthreads();
    if (threadIdx.x == 0) {
        __threadfence();
        atomicAdd(&g_tick, 1u);
        volatile unsigned* vt = &g_tick;
        while (*vt < target) __nanosleep(64);
        __threadfence();
    }
    __syncthreads();
}

// ---------------- split fp32 -> bf16 hi/lo ------------------------------------
__global__ void conv_split(const float* __restrict__ src,
                           __nv_bfloat16* __restrict__ hi, __nv_bfloat16* __restrict__ lo, int n)
{
    int stride = gridDim.x*blockDim.x;
    for (int i = blockIdx.x*blockDim.x + threadIdx.x; i < n; i += stride) {
        float x = src[i];
        __nv_bfloat16 h = __float2bfloat16(x);
        hi[i] = h;
        lo[i] = __float2bfloat16(x - __bfloat162float(h));
    }
}

// ---------------- mma.sync bf16 helper ----------------------------------------
__device__ __forceinline__ void mma16816(float c[4],
    uint32_t a0, uint32_t a1, uint32_t a2, uint32_t a3, uint32_t b0, uint32_t b1)
{
    asm volatile(
        "mma.sync.aligned.m16n8k16.row.col.f32.bf16.bf16.f32 "
        "{%0,%1,%2,%3}, {%4,%5,%6,%7}, {%8,%9}, {%0,%1,%2,%3};"
        : "+f"(c[0]), "+f"(c[1]), "+f"(c[2]), "+f"(c[3])
        : "r"(a0), "r"(a1), "r"(a2), "r"(a3), "r"(b0), "r"(b1));
}

// -------- tensor GEMM via mma.sync: C[r][n] = A_row(r).W[n] + bias[n] ---------
// block tile 128M x 128N, 8 warps (2x4), warp tile 64M x 32N, K chunks of 32
// split-bf16: D = Ah.Wh + Ah.Wl + Al.Wh  (fp32 accumulate)
#define MM_SA 40   // smem row stride in bf16 elems (80B: 16B-aligned, conflict-free)
__global__ __launch_bounds__(256) void gemm_mma(
    const __nv_bfloat16* __restrict__ Ah, const __nv_bfloat16* __restrict__ Al,
    const __nv_bfloat16* __restrict__ Wh, const __nv_bfloat16* __restrict__ Wl,
    const float* __restrict__ bias, float* __restrict__ C, int K, int Mtot)
{
    __shared__ __nv_bfloat16 sAh[128*MM_SA], sAl[128*MM_SA];
    __shared__ __nv_bfloat16 sWh[128*MM_SA], sWl[128*MM_SA];
    const int tid = threadIdx.x, wid = tid >> 5, lane = tid & 31;
    const int g = lane >> 2, tg = lane & 3;
    const int bm = blockIdx.y << 7, bn = blockIdx.x << 7;
    const int wm = (wid >> 2) << 6, wn = (wid & 3) << 5;
    const int lrow = tid >> 1, lhalf = tid & 1;

    const int arow_i = bm + lrow;
    const bool aval = arow_i < Mtot;
    const size_t a_off = ((size_t)(arow_i & 63)*SS + (arow_i >> 6))*K + lhalf*16;
    const size_t w_off = (size_t)(bn + lrow)*K + lhalf*16;
    const uint32_t s_st = lrow*MM_SA + lhalf*16;   // elem offset for smem stores

    float acc[4][4][4];
    #pragma unroll
    for (int mf=0; mf<4; mf++)
        #pragma unroll
        for (int nf=0; nf<4; nf++)
            #pragma unroll
            for (int q=0; q<4; q++) acc[mf][nf][q] = 0.f;

    const uint4 z4 = make_uint4(0u,0u,0u,0u);
    uint4 pah0, pah1, pal0, pal1, pwh0, pwh1, pwl0, pwl1;
    pah0 = aval ? *(const uint4*)(Ah + a_off)     : z4;
    pah1 = aval ? *(const uint4*)(Ah + a_off + 8) : z4;
    pal0 = aval ? *(const uint4*)(Al + a_off)     : z4;
    pal1 = aval ? *(const uint4*)(Al + a_off + 8) : z4;
    pwh0 = *(const uint4*)(Wh + w_off);     pwh1 = *(const uint4*)(Wh + w_off + 8);
    pwl0 = *(const uint4*)(Wl + w_off);     pwl1 = *(const uint4*)(Wl + w_off + 8);

    for (int k0 = 0; k0 < K; k0 += 32) {
        __syncthreads();
        *(uint4*)(sAh + s_st) = pah0; *(uint4*)(sAh + s_st + 8) = pah1;
        *(uint4*)(sAl + s_st) = pal0; *(uint4*)(sAl + s_st + 8) = pal1;
        *(uint4*)(sWh + s_st) = pwh0; *(uint4*)(sWh + s_st + 8) = pwh1;
        *(uint4*)(sWl + s_st) = pwl0; *(uint4*)(sWl + s_st + 8) = pwl1;
        __syncthreads();
        if (k0 + 32 < K) {
            size_t an = a_off + k0 + 32, wn2 = w_off + k0 + 32;
            pah0 = aval ? *(const uint4*)(Ah + an)     : z4;
            pah1 = aval ? *(const uint4*)(Ah + an + 8) : z4;
            pal0 = aval ? *(const uint4*)(Al + an)     : z4;
            pal1 = aval ? *(const uint4*)(Al + an + 8) : z4;
            pwh0 = *(const uint4*)(Wh + wn2);  pwh1 = *(const uint4*)(Wh + wn2 + 8);
            pwl0 = *(const uint4*)(Wl + wn2);  pwl1 = *(const uint4*)(Wl + wn2 + 8);
        }
        #pragma unroll
        for (int kh = 0; kh < 2; kh++) {
            const int kb = kh*16 + tg*2;
            uint32_t bh[4][2], bl[4][2];
            #pragma unroll
            for (int nf = 0; nf < 4; nf++) {
                const __nv_bfloat16* wr = sWh + (wn + nf*8 + g)*MM_SA;
                const __nv_bfloat16* wl2 = sWl + (wn + nf*8 + g)*MM_SA;
                bh[nf][0] = *(const uint32_t*)(wr + kb);
                bh[nf][1] = *(const uint32_t*)(wr + kb + 8);
                bl[nf][0] = *(const uint32_t*)(wl2 + kb);
                bl[nf][1] = *(const uint32_t*)(wl2 + kb + 8);
            }
            #pragma unroll
            for (int mf = 0; mf < 4; mf++) {
                const __nv_bfloat16* arh = sAh + (wm + mf*16 + g)*MM_SA;
                const __nv_bfloat16* arl = sAl + (wm + mf*16 + g)*MM_SA;
                uint32_t ah0 = *(const uint32_t*)(arh + kb);
                uint32_t ah1 = *(const uint32_t*)(arh + 8*MM_SA + kb);
                uint32_t ah2 = *(const uint32_t*)(arh + kb + 8);
                uint32_t ah3 = *(const uint32_t*)(arh + 8*MM_SA + kb + 8);
                uint32_t al0 = *(const uint32_t*)(arl + kb);
                uint32_t al1 = *(const uint32_t*)(arl + 8*MM_SA + kb);
                uint32_t al2 = *(const uint32_t*)(arl + kb + 8);
                uint32_t al3 = *(const uint32_t*)(arl + 8*MM_SA + kb + 8);
                #pragma unroll
                for (int nf = 0; nf < 4; nf++) {
                    mma16816(acc[mf][nf], ah0, ah1, ah2, ah3, bh[nf][0], bh[nf][1]);
                    mma16816(acc[mf][nf], ah0, ah1, ah2, ah3, bl[nf][0], bl[nf][1]);
                    mma16816(acc[mf][nf], al0, al1, al2, al3, bh[nf][0], bh[nf][1]);
                }
            }
        }
    }

    #pragma unroll
    for (int mf = 0; mf < 4; mf++) {
        int r0 = bm + wm + mf*16 + g;
        #pragma unroll
        for (int nf = 0; nf < 4; nf++) {
            int col = bn + wn + nf*8 + tg*2;
            float b0 = bias[col], b1 = bias[col+1];
            if (r0 < Mtot) {
                float2 v = make_float2(acc[mf][nf][0] + b0, acc[mf][nf][1] + b1);
                *(float2*)(C + (size_t)r0*G4 + col) = v;
            }
            if (r0 + 8 < Mtot) {
                float2 v = make_float2(acc[mf][nf][2] + b0, acc[mf][nf][3] + b1);
                *(float2*)(C + (size_t)(r0+8)*G4 + col) = v;
            }
        }
    }
}

// ------------------- zero per-launch states + snapshot lstm barrier base ------
__global__ void zero_states()
{
    int gt = blockIdx.x*blockDim.x + threadIdx.x;
    if (gt == 0) g_base_lstm = g_tick;
    int stride = gridDim.x*blockDim.x;
    for (int i = gt; i < 4*BB*HH; i += stride) g_hstate[i]=0.f;
    for (int i = gt; i < 2*BB*HH; i += stride) g_cstate[i]=0.f;
}

// ------------------- precompute stack pointers from golds -------------------
__global__ void ptr_kernel(const int* __restrict__ golds)
{
    int b = threadIdx.x;
    if (b >= BB) return;
    int sp = 0, wp = 0;
    for (int t = 0; t < TT; t++) {
        g_spa[t*BB+b] = sp;
        g_wpa[t*BB+b] = wp;
        int g = golds[b*SS + t + 1];
        sp += (g==0) ? 1 : 2;
        wp += (g==0) ? 0 : 1;
    }
}

// ------- narrow-tile 768-K accumulator (64b x 8j x 4 gates), f32x2, prefetch --
__device__ __forceinline__ void accum_narrow(
    u64t acc2[2][2], const float* __restrict__ srcrow, const float* __restrict__ wrow,
    float* hs, float* ws, int tid)
{
    const int ar = tid >> 2, ak = (tid & 3) << 2;
    const int wr_ = tid >> 3, wk = (tid & 7) << 2;
    const int jj = tid & 7, mg = tid >> 3;
    float4 a1 = *(const float4*)(srcrow + ak);
    float4 a2 = *(const float4*)(srcrow + 16 + ak);
    float4 wv = *(const float4*)(wrow + wk);
    #pragma unroll 1
    for (int k0 = 0; k0 < HH; k0 += 32) {
        __syncthreads();
        hs[(ak+0)*66+ar]=a1.x; hs[(ak+1)*66+ar]=a1.y; hs[(ak+2)*66+ar]=a1.z; hs[(ak+3)*66+ar]=a1.w;
        hs[(16+ak+0)*66+ar]=a2.x; hs[(16+ak+1)*66+ar]=a2.y; hs[(16+ak+2)*66+ar]=a2.z; hs[(16+ak+3)*66+ar]=a2.w;
        ws[(wk+0)*36+wr_]=wv.x; ws[(wk+1)*36+wr_]=wv.y; ws[(wk+2)*36+wr_]=wv.z; ws[(wk+3)*36+wr_]=wv.w;
        __syncthreads();
        if (k0 + 32 < HH) {
            a1 = *(const float4*)(srcrow + k0 + 32 + ak);
            a2 = *(const float4*)(srcrow + k0 + 48 + ak);
            wv = *(const float4*)(wrow + k0 + 32 + wk);
        }
        #pragma unroll
        for (int kk = 0; kk < 32; kk++) {
            float2 a = *(const float2*)&hs[kk*66 + (mg<<1)];
            float4 w = *(const float4*)&ws[kk*36 + (jj<<2)];
            u64t w01 = pack2(w.x,w.y), w23 = pack2(w.z,w.w);
            u64t ad0 = pack2(a.x,a.x), ad1 = pack2(a.y,a.y);
            fma2(acc2[0][0], ad0, w01); fma2(acc2[0][1], ad0, w23);
            fma2(acc2[1][0], ad1, w01); fma2(acc2[1][1], ad1, w23);
        }
    }
}

// ------------------- persistent BiLSTM: 192 blocks, 256 steps -----------------
__global__ __launch_bounds__(256, 2) void lstm_persist(
    const float* __restrict__ Whh_f, const float* __restrict__ Whh_b)
{
    __shared__ float hs[32*66];
    __shared__ float ws[32*36];
    const int tid = threadIdx.x;
    const int bid = blockIdx.x;
    const int dir = bid / 96;
    const int j0 = (bid % 96) << 3;
    const unsigned base = g_base_lstm;
    const float* Whh = dir ? Whh_b : Whh_f;
    const float* gibase = dir ? g_gi_b : g_gi_f;
    float* cst = g_cstate + (size_t)dir*BB*HH;
    const int ar = tid >> 2;
    const int wr_ = tid >> 3;
    const float* wrow = Whh + (size_t)((wr_&3)*HH + j0 + (wr_>>2)) * HH;
    const int jj = tid & 7, mg = tid >> 3;
    const int j = j0 + jj;

    for (int t = 0; t < SS; t++) {
        const int tt = dir ? (SS-1-t) : t;
        const float* gi = gibase + (size_t)tt*BB*G4;
        const float* hin = g_hstate + (size_t)(dir*2 + (t&1))*BB*HH;
        float* hout = g_hstate + (size_t)(dir*2 + ((t&1)^1))*BB*HH;
        const float* srcrow = hin + ar*HH;
        u64t acc2[2][2] = {};
        accum_narrow(acc2, srcrow, wrow, hs, ws, tid);
        #pragma unroll
        for (int mi=0; mi<2; mi++) {
            int b = (mg<<1) + mi;
            float a0,a1,a2,a3;
            unpack2(acc2[mi][0], a0, a1);
            unpack2(acc2[mi][1], a2, a3);
            float vi = gi[b*G4 +        j] + a0;
            float vf = gi[b*G4 + HH +   j] + a1;
            float vg = gi[b*G4 + 2*HH + j] + a2;
            float vo = gi[b*G4 + 3*HH + j] + a3;
            float c = sigf(vf)*cst[b*HH+j] + sigf(vi)*tanhf(vg);
            float h = sigf(vo)*tanhf(c);
            cst[b*HH+j] = c;
            hout[b*HH+j] = h;
            g_lstm_out[((size_t)b*SS + tt)*(2*HH) + dir*HH + j] = h;
        }
        if (t < SS-1) gbar(base + (unsigned)(t+1)*NB_LSTM);
    }
}

// ------------------- persistent decode: 289 blocks, 255 steps -----------------
__global__ __launch_bounds__(256, 2) void decode_persist(
    const float* __restrict__ subw_Whh,
    const float* __restrict__ word_Wih, const float* __restrict__ word_Whh,
    const float* __restrict__ word_b,
    const float* __restrict__ clsW, float* __restrict__ out)
{
    __shared__ float hs[32*66];
    __shared__ float ws[32*36];
    __shared__ int idx_s[BB];
    const int tid = threadIdx.x;
    const int bid = blockIdx.x;
    const unsigned base = g_base_dec;

    for (int t = 0; t <= TT; t++) {
        // ---------- phase A ----------
        if (bid < 96 && t < TT) {
            if (tid < BB) idx_s[tid] = g_spa[t*BB + tid];
            __syncthreads();
            const int j0 = bid << 3;
            const float* gi = g_pre1 + (size_t)t*BB*G4;
            const int ar = tid >> 2;
            const float* srcrow = g_sh + ((size_t)ar*SLEN + idx_s[ar]) * HH;
            const int wr_ = tid >> 3;
            const float* wrow = subw_Whh + (size_t)((wr_&3)*HH + j0 + (wr_>>2)) * HH;
            u64t acc2[2][2] = {};
            accum_narrow(acc2, srcrow, wrow, hs, ws, tid);
            const int jj = tid & 7, mg = tid >> 3;
            const int j = j0 + jj;
            #pragma unroll
            for (int mi=0; mi<2; mi++) {
                int b = (mg<<1) + mi;
                int sp = idx_s[b];
                float a0,a1,a2,a3;
                unpack2(acc2[mi][0], a0, a1);
                unpack2(acc2[mi][1], a2, a3);
                float vi = gi[b*G4 +        j] + a0;
                float vf = gi[b*G4 + HH +   j] + a1;
                float vg = gi[b*G4 + 2*HH + j] + a2;
                float vo = gi[b*G4 + 3*HH + j] + a3;
                float c = sigf(vf)*g_sc[((size_t)b*SLEN + sp)*HH + j] + sigf(vi)*tanhf(vg);
                float h = sigf(vo)*tanhf(c);
                g_sh[((size_t)b*SLEN + sp + 1)*HH + j] = h;
                g_sc[((size_t)b*SLEN + sp + 1)*HH + j] = c;
                g_h1[b*HH+j] = h;
                g_c1[b*HH+j] = c;
            }
        } else if (bid >= 96 && bid < 288 && t > 0) {
            const int u = t - 1;
            const int tile = bid - 96;          // 0..191
            const int b = tile / 3;
            const int j = (tile % 3)*256 + tid;
            const int wp = g_wpa[u*BB + b];
            float v[4];
            #pragma unroll
            for (int g=0; g<4; g++) {
                int n = g*HH + j;
                v[g] = word_b[n] + g_bpart[(size_t)b*G4 + n]
                                 + g_bpart[(size_t)(BB + b)*G4 + n]
                                 + g_bpart[(size_t)(2*BB + b)*G4 + n];
            }
            float c = sigf(v[1])*g_wc[((size_t)b*WLEN + wp)*HH + j] + sigf(v[0])*tanhf(v[2]);
            float h = sigf(v[3])*tanhf(c);
            g_wh[((size_t)b*WLEN + wp + 1)*HH + j] = h;
            g_wc[((size_t)b*WLEN + wp + 1)*HH + j] = c;
            g_whbuf[b*HH + j] = h;
        }
        gbar(base + (unsigned)(2*t+1)*NB_DEC);

        // ---------- phase B ----------
        if (bid < 288 && t < TT) {
            const int seg = bid / 96;
            const int j0 = (bid % 96) << 3;
            if (tid < BB) idx_s[tid] = g_wpa[t*BB + tid];
            __syncthreads();
            const int ar = tid >> 2;
            const int wr_ = tid >> 3;
            const int wn = (wr_&3)*HH + j0 + (wr_>>2);
            const float* srcrow;
            const float* wrow;
            if (seg == 0)      { srcrow = g_h1 + ar*HH;  wrow = word_Wih + (size_t)wn*(2*HH); }
            else if (seg == 1) { srcrow = g_c1 + ar*HH;  wrow = word_Wih + (size_t)wn*(2*HH) + HH; }
            else               { srcrow = g_wh + ((size_t)ar*WLEN + idx_s[ar])*HH;
                                 wrow = word_Whh + (size_t)wn*HH; }
            u64t acc2[2][2] = {};
            accum_narrow(acc2, srcrow, wrow, hs, ws, tid);
            const int jj = tid & 7, mg = tid >> 3;
            const int j = j0 + jj;
            float* part = g_bpart + (size_t)seg*BB*G4;
            #pragma unroll
            for (int mi=0; mi<2; mi++) {
                int b = (mg<<1) + mi;
                float a0,a1,a2,a3;
                unpack2(acc2[mi][0], a0, a1);
                unpack2(acc2[mi][1], a2, a3);
                part[(size_t)b*G4 +          j] = a0;
                part[(size_t)b*G4 +   HH +   j] = a1;
                part[(size_t)b*G4 + 2*HH +   j] = a2;
                part[(size_t)b*G4 + 3*HH +   j] = a3;
            }
        } else if (bid == 288 && t > 0) {
            const int u = t - 1;
            if (tid < 128) {
                int b = tid >> 1, c = tid & 1;
                const float* w = clsW + c*(3*HH);
                const float* hb = g_whbuf + b*HH;
                float s0 = g_ccur[u*BB*2 + (b<<1) + c], s1=0.f, s2=0.f, s3=0.f;
                #pragma unroll 4
                for (int k = 0; k < HH; k += 4) {
                    s0 += hb[k]*w[k];   s1 += hb[k+1]*w[k+1];
                    s2 += hb[k+2]*w[k+2]; s3 += hb[k+3]*w[k+3];
                }
                out[((size_t)b*SS + u + 1)*2 + c] = s0+s1+s2+s3;
            }
        }
        if (t < TT) gbar(base + (unsigned)(2*t+2)*NB_DEC);
    }
}

// -------- x_cur classifier halves + first row + decode barrier base snapshot ---
__global__ void ccur_kernel(const float* __restrict__ clsW, const float* __restrict__ clsb,
                            float* __restrict__ out)
{
    int gt = blockIdx.x*blockDim.x + threadIdx.x;
    if (gt == 0) g_base_dec = g_tick;
    int gw = gt >> 5, lane = gt & 31;
    if (gw < TT*BB*2) {
        int t = gw >> 7, rem = gw & 127, b = rem >> 1, c = rem & 1;
        const float* x = g_lstm_out + ((size_t)b*SS + t + 1)*(2*HH);
        const float* w = clsW + c*(3*HH) + HH;
        float s = 0.f;
        for (int k = lane; k < 2*HH; k += 32) s += x[k]*w[k];
        #pragma unroll
        for (int o = 16; o; o >>= 1) s += __shfl_xor_sync(0xffffffffu, s, o);
        if (lane == 0) g_ccur[gw] = s + clsb[c];
    }
    if (gt < 128) {
        int b = gt >> 1, c = gt & 1;
        out[(size_t)b*SS*2 + c] = c ? 1.f : -1.f;
    }
}

// ------------------- launch -------------------
extern "C" void kernel_launch(void* const* d_in, const int* in_sizes, int n_in,
                              void* d_out, int out_size)
{
    const int dictOrder = (in_sizes[1] == BB*SS);
    const float* hsin = (const float*)d_in[0];
    const int* golds;
    const float *Wih_f,*Whh_f,*b_f,*Wih_b,*Whh_b,*b_b;
    const float *subw_Wih,*subw_Whh,*subw_b,*word_Wih,*word_Whh,*word_b,*clsW,*clsb;
    if (dictOrder) {
        golds    = (const int*)  d_in[1];
        Wih_f    = (const float*)d_in[2];  Whh_f   = (const float*)d_in[3];
        b_f      = (const float*)d_in[4];  Wih_b   = (const float*)d_in[5];
        Whh_b    = (const float*)d_in[6];  b_b     = (const float*)d_in[7];
        subw_Wih = (const float*)d_in[8];  subw_Whh= (const float*)d_in[9];
        subw_b   = (const float*)d_in[10]; word_Wih= (const float*)d_in[11];
        word_Whh = (const float*)d_in[12]; word_b  = (const float*)d_in[13];
        clsW     = (const float*)d_in[14]; clsb    = (const float*)d_in[15];
    } else {
        Wih_f    = (const float*)d_in[1];  Whh_f   = (const float*)d_in[2];
        b_f      = (const float*)d_in[3];  Wih_b   = (const float*)d_in[4];
        Whh_b    = (const float*)d_in[5];  b_b     = (const float*)d_in[6];
        subw_Wih = (const float*)d_in[7];  subw_Whh= (const float*)d_in[8];
        subw_b   = (const float*)d_in[9];  word_Wih= (const float*)d_in[10];
        word_Whh = (const float*)d_in[11]; word_b  = (const float*)d_in[12];
        clsW     = (const float*)d_in[13]; clsb    = (const float*)d_in[14];
        golds    = (const int*)  d_in[15];
    }
    float* out = (float*)d_out;

    float *p_gif, *p_gib, *p_lo, *p_pre1;
    cudaGetSymbolAddress((void**)&p_gif,  g_gi_f);
    cudaGetSymbolAddress((void**)&p_gib,  g_gi_b);
    cudaGetSymbolAddress((void**)&p_lo,   g_lstm_out);
    cudaGetSymbolAddress((void**)&p_pre1, g_pre1);
    __nv_bfloat16 *p_Ah, *p_Al, *p_Wh, *p_Wl;
    cudaGetSymbolAddress((void**)&p_Ah, g_Ah);
    cudaGetSymbolAddress((void**)&p_Al, g_Al);
    cudaGetSymbolAddress((void**)&p_Wh, g_Wbh);
    cudaGetSymbolAddress((void**)&p_Wl, g_Wbl);

    zero_states<<<96, 256>>>();
    ptr_kernel<<<1, 64>>>(golds);

    // split inputs + weights, run tensor GEMMs for gate precompute
    conv_split<<<2048, 256>>>(hsin, p_Ah, p_Al, BB*SS*HH);
    conv_split<<<2048, 256>>>(Wih_f, p_Wh, p_Wl, G4*HH);
    gemm_mma<<<dim3(24, 128), 256>>>(p_Ah, p_Al, p_Wh, p_Wl, b_f, p_gif, HH, BB*SS);
    conv_split<<<2048, 256>>>(Wih_b, p_Wh, p_Wl, G4*HH);
    gemm_mma<<<dim3(24, 128), 256>>>(p_Ah, p_Al, p_Wh, p_Wl, b_b, p_gib, HH, BB*SS);

    // persistent BiLSTM recurrence (256 steps inside)
    lstm_persist<<<NB_LSTM, 256>>>(Whh_f, Whh_b);

    // subword input precompute on tensor cores: (16320,1536)@(1536,3072)+b
    conv_split<<<4096, 256>>>(p_lo, p_Ah, p_Al, BB*SS*2*HH);
    conv_split<<<2048, 256>>>(subw_Wih, p_Wh, p_Wl, G4*2*HH);
    gemm_mma<<<dim3(24, 128), 256>>>(p_Ah, p_Al, p_Wh, p_Wl, subw_b, p_pre1, 2*HH, TT*BB);

    // classifier x_cur halves + first output row + decode barrier base
    ccur_kernel<<<4080, 256>>>(clsW, clsb, out);

    // persistent decode (255 steps + tail inside)
    decode_persist<<<NB_DEC, 256>>>(subw_Whh, word_Wih, word_Whh, word_b, clsW, out);
}

// round 15
// speedup vs baseline: 2.4555x; 1.3737x over previous
#include <cuda_runtime.h>
#include <cuda_bf16.h>
#include <cstdint>
#include <math.h>

#define BB 64
#define SS 256
#define HH 768
#define G4 3072          // 4*H
#define TT 255           // decode steps
#define SLEN (2*SS+2)    // 514
#define WLEN (SS+1)      // 257
#define NB_LSTM 192
#define NB_DEC  289
#define SBSZ 27648       // helper smem: A hi/lo (18432B) + W hi/lo (9216B)

// ------------------- device scratch (BSS zero-initialized) -------------------
__device__ float g_gi_f[(size_t)SS*BB*G4];
__device__ float g_gi_b[(size_t)SS*BB*G4];
__device__ float g_lstm_out[(size_t)BB*SS*2*HH];  // [b][t][2H]
__device__ float g_pre1[(size_t)TT*BB*G4];        // x_prev @ subw_Wih.T + b
__device__ float g_sh[(size_t)BB*SLEN*HH];
__device__ float g_sc[(size_t)BB*SLEN*HH];
__device__ float g_wh[(size_t)BB*WLEN*HH];
__device__ float g_wc[(size_t)BB*WLEN*HH];
__device__ float g_bpart[(size_t)BB*G4];          // word pre-acts, PERMUTED cols (j*4+g)
__device__ float g_hstate[4*BB*HH];
__device__ float g_cstate[2*BB*HH];
__device__ float g_h1[BB*HH];
__device__ float g_c1[BB*HH];
__device__ float g_whbuf[BB*HH];
__device__ float g_ccur[TT*BB*2];
__device__ int   g_spa[TT*BB];
__device__ int   g_wpa[TT*BB];

// split-bf16 operand buffers for big tensor GEMMs
__device__ __align__(16) __nv_bfloat16 g_Ah[(size_t)16384*1536];
__device__ __align__(16) __nv_bfloat16 g_Al[(size_t)16384*1536];
__device__ __align__(16) __nv_bfloat16 g_Wbh[(size_t)3072*1536];
__device__ __align__(16) __nv_bfloat16 g_Wbl[(size_t)3072*1536];

// split + row-permuted (r' = j*4 + gate) weights for persistent kernels
__device__ __align__(16) __nv_bfloat16 g_PL_h[(size_t)2*G4*HH];   // lstm Whh f,b
__device__ __align__(16) __nv_bfloat16 g_PL_l[(size_t)2*G4*HH];
__device__ __align__(16) __nv_bfloat16 g_PS_h[(size_t)G4*HH];     // subw_Whh
__device__ __align__(16) __nv_bfloat16 g_PS_l[(size_t)G4*HH];
__device__ __align__(16) __nv_bfloat16 g_PWih_h[(size_t)G4*2*HH]; // word_Wih
__device__ __align__(16) __nv_bfloat16 g_PWih_l[(size_t)G4*2*HH];
__device__ __align__(16) __nv_bfloat16 g_PWhh_h[(size_t)G4*HH];   // word_Whh
__device__ __align__(16) __nv_bfloat16 g_PWhh_l[(size_t)G4*HH];

// monotonic grid-barrier ticket (never reset; replay-safe via base snapshots)
__device__ unsigned g_tick;
__device__ unsigned g_base_lstm;
__device__ unsigned g_base_dec;

__device__ __forceinline__ float sigf(float x){ return 1.f/(1.f+expf(-x)); }

__device__ __forceinline__ void gbar(unsigned target)
{
    __syncthreads();
    if (threadIdx.x == 0) {
        __threadfence();
        atomicAdd(&g_tick, 1u);
        volatile unsigned* vt = &g_tick;
        while (*vt < target) __nanosleep(64);
        __threadfence();
    }
    __syncthreads();
}

// ---------------- split fp32 -> bf16 hi/lo ------------------------------------
__global__ void conv_split(const float* __restrict__ src,
                           __nv_bfloat16* __restrict__ hi, __nv_bfloat16* __restrict__ lo, int n)
{
    int stride = gridDim.x*blockDim.x;
    for (int i = blockIdx.x*blockDim.x + threadIdx.x; i < n; i += stride) {
        float x = src[i];
        __nv_bfloat16 h = __float2bfloat16(x);
        hi[i] = h;
        lo[i] = __float2bfloat16(x - __bfloat162float(h));
    }
}

// ------- split + permute rows: dst row (j*4+g) = src row (g*HH+j) -------------
__global__ void conv_split_perm(const float* __restrict__ src,
    __nv_bfloat16* __restrict__ hi, __nv_bfloat16* __restrict__ lo, int K)
{
    int r = blockIdx.y;
    int k = blockIdx.x*blockDim.x + threadIdx.x;
    if (k >= K) return;
    int gq = r / HH, jq = r - gq*HH;
    size_t di = (size_t)(jq*4 + gq)*K + k;
    float x = src[(size_t)r*K + k];
    __nv_bfloat16 h = __float2bfloat16(x);
    hi[di] = h;
    lo[di] = __float2bfloat16(x - __bfloat162float(h));
}

// ---------------- mma.sync bf16 helper ----------------------------------------
__device__ __forceinline__ void mma16816(float c[4],
    uint32_t a0, uint32_t a1, uint32_t a2, uint32_t a3, uint32_t b0, uint32_t b1)
{
    asm volatile(
        "mma.sync.aligned.m16n8k16.row.col.f32.bf16.bf16.f32 "
        "{%0,%1,%2,%3}, {%4,%5,%6,%7}, {%8,%9}, {%0,%1,%2,%3};"
        : "+f"(c[0]), "+f"(c[1]), "+f"(c[2]), "+f"(c[3])
        : "r"(a0), "r"(a1), "r"(a2), "r"(a3), "r"(b0), "r"(b1));
}

// ===== 64M x 32N x 768K accumulation: A fp32 (gathered rows, on-the-fly split),
// ===== W pre-split bf16 hi/lo (row stride wK). 8 warps: wm=(wid/2)*16, wn=(wid&1)*16.
#define MSA 72   // smem row stride (bf16 elems); 144B, conflict-free, 16B-aligned
__device__ __forceinline__ void mma_seg(
    float (&acc)[2][4], const float* const* aptrs,
    const __nv_bfloat16* __restrict__ Wh8, const __nv_bfloat16* __restrict__ Wl8,
    int wK, char* sb, int tid)
{
    __nv_bfloat16* sA = (__nv_bfloat16*)sb;               // hi [0,64*72), lo +64*72
    __nv_bfloat16* sW = (__nv_bfloat16*)(sb + 18432);     // hi [0,32*72), lo +32*72
    const int arow = tid >> 2, akq = (tid & 3) << 4;
    const int wrow = tid >> 3, wkq = (tid & 7) << 3;
    const int lane = tid & 31, wid = tid >> 5;
    const int g = lane >> 2, tg = lane & 3;
    const int wm = (wid >> 1) << 4;
    const int wn2 = (wid & 1) << 4;
    const float* ap = aptrs[arow] + akq;
    const __nv_bfloat16* wph = Wh8 + (size_t)wrow*wK + wkq;
    const __nv_bfloat16* wpl = Wl8 + (size_t)wrow*wK + wkq;
    float4 f0 = *(const float4*)(ap),     f1 = *(const float4*)(ap+4);
    float4 f2 = *(const float4*)(ap+8),   f3 = *(const float4*)(ap+12);
    uint4 wh = *(const uint4*)wph, wl = *(const uint4*)wpl;
    #pragma unroll 1
    for (int k0 = 0; k0 < HH; k0 += 64) {
        __syncthreads();
        {
            float fs[16];
            *(float4*)&fs[0]=f0; *(float4*)&fs[4]=f1; *(float4*)&fs[8]=f2; *(float4*)&fs[12]=f3;
            __nv_bfloat16 hb[16], lb[16];
            #pragma unroll
            for (int i2=0;i2<16;i2++){
                __nv_bfloat16 h = __float2bfloat16(fs[i2]);
                hb[i2]=h; lb[i2]=__float2bfloat16(fs[i2]-__bfloat162float(h));
            }
            __nv_bfloat16* da = sA + arow*MSA + akq;
            *(uint4*)(da)   = *(uint4*)&hb[0]; *(uint4*)(da+8) = *(uint4*)&hb[8];
            __nv_bfloat16* dl = da + 64*MSA;
            *(uint4*)(dl)   = *(uint4*)&lb[0]; *(uint4*)(dl+8) = *(uint4*)&lb[8];
            __nv_bfloat16* dw = sW + wrow*MSA + wkq;
            *(uint4*)dw = wh;
            *(uint4*)(dw + 32*MSA) = wl;
        }
        __syncthreads();
        if (k0 + 64 < HH) {
            const float* ap2 = ap + k0 + 64;
            f0=*(const float4*)(ap2);   f1=*(const float4*)(ap2+4);
            f2=*(const float4*)(ap2+8); f3=*(const float4*)(ap2+12);
            wh=*(const uint4*)(wph + k0 + 64); wl=*(const uint4*)(wpl + k0 + 64);
        }
        #pragma unroll
        for (int kh = 0; kh < 4; kh++) {
            const int kb = kh*16 + tg*2;
            const __nv_bfloat16* ar_ = sA + (wm+g)*MSA + kb;
            uint32_t ah0=*(const uint32_t*)(ar_);
            uint32_t ah1=*(const uint32_t*)(ar_ + 8*MSA);
            uint32_t ah2=*(const uint32_t*)(ar_ + 8);
            uint32_t ah3=*(const uint32_t*)(ar_ + 8*MSA + 8);
            const __nv_bfloat16* al_ = ar_ + 64*MSA;
            uint32_t bl0=*(const uint32_t*)(al_);
            uint32_t bl1=*(const uint32_t*)(al_ + 8*MSA);
            uint32_t bl2=*(const uint32_t*)(al_ + 8);
            uint32_t bl3=*(const uint32_t*)(al_ + 8*MSA + 8);
            #pragma unroll
            for (int nf = 0; nf < 2; nf++) {
                const __nv_bfloat16* br_ = sW + (wn2+nf*8+g)*MSA + kb;
                uint32_t b0=*(const uint32_t*)(br_), b1=*(const uint32_t*)(br_+8);
                const __nv_bfloat16* bw_ = br_ + 32*MSA;
                uint32_t c0=*(const uint32_t*)(bw_), c1=*(const uint32_t*)(bw_+8);
                mma16816(acc[nf], ah0,ah1,ah2,ah3, b0,b1);
                mma16816(acc[nf], ah0,ah1,ah2,ah3, c0,c1);
                mma16816(acc[nf], bl0,bl1,bl2,bl3, b0,b1);
            }
        }
    }
}

__device__ __forceinline__ void dump_acc(float* sOut, float (&acc)[2][4], int tid)
{
    const int lane=tid&31, wid=tid>>5, g=lane>>2, tg=lane&3;
    const int wm=(wid>>1)<<4, wn2=(wid&1)<<4;
    #pragma unroll
    for (int nf=0; nf<2; nf++) {
        int col = wn2 + nf*8 + tg*2;
        sOut[(wm+g)*36+col]   = acc[nf][0];
        sOut[(wm+g)*36+col+1] = acc[nf][1];
        sOut[(wm+g+8)*36+col]   = acc[nf][2];
        sOut[(wm+g+8)*36+col+1] = acc[nf][3];
    }
}

// -------- big tensor GEMM via mma.sync (unchanged from round 14) --------------
#define MM_SA 40
__global__ __launch_bounds__(256) void gemm_mma(
    const __nv_bfloat16* __restrict__ Ah, const __nv_bfloat16* __restrict__ Al,
    const __nv_bfloat16* __restrict__ Wh, const __nv_bfloat16* __restrict__ Wl,
    const float* __restrict__ bias, float* __restrict__ C, int K, int Mtot)
{
    __shared__ __nv_bfloat16 sAh[128*MM_SA], sAl[128*MM_SA];
    __shared__ __nv_bfloat16 sWh[128*MM_SA], sWl[128*MM_SA];
    const int tid = threadIdx.x, wid = tid >> 5, lane = tid & 31;
    const int g = lane >> 2, tg = lane & 3;
    const int bm = blockIdx.y << 7, bn = blockIdx.x << 7;
    const int wm = (wid >> 2) << 6, wn = (wid & 3) << 5;
    const int lrow = tid >> 1, lhalf = tid & 1;

    const int arow_i = bm + lrow;
    const bool aval = arow_i < Mtot;
    const size_t a_off = ((size_t)(arow_i & 63)*SS + (arow_i >> 6))*K + lhalf*16;
    const size_t w_off = (size_t)(bn + lrow)*K + lhalf*16;
    const uint32_t s_st = lrow*MM_SA + lhalf*16;

    float acc[4][4][4];
    #pragma unroll
    for (int mf=0; mf<4; mf++)
        #pragma unroll
        for (int nf=0; nf<4; nf++)
            #pragma unroll
            for (int q=0; q<4; q++) acc[mf][nf][q] = 0.f;

    const uint4 z4 = make_uint4(0u,0u,0u,0u);
    uint4 pah0, pah1, pal0, pal1, pwh0, pwh1, pwl0, pwl1;
    pah0 = aval ? *(const uint4*)(Ah + a_off)     : z4;
    pah1 = aval ? *(const uint4*)(Ah + a_off + 8) : z4;
    pal0 = aval ? *(const uint4*)(Al + a_off)     : z4;
    pal1 = aval ? *(const uint4*)(Al + a_off + 8) : z4;
    pwh0 = *(const uint4*)(Wh + w_off);     pwh1 = *(const uint4*)(Wh + w_off + 8);
    pwl0 = *(const uint4*)(Wl + w_off);     pwl1 = *(const uint4*)(Wl + w_off + 8);

    for (int k0 = 0; k0 < K; k0 += 32) {
        __syncthreads();
        *(uint4*)(sAh + s_st) = pah0; *(uint4*)(sAh + s_st + 8) = pah1;
        *(uint4*)(sAl + s_st) = pal0; *(uint4*)(sAl + s_st + 8) = pal1;
        *(uint4*)(sWh + s_st) = pwh0; *(uint4*)(sWh + s_st + 8) = pwh1;
        *(uint4*)(sWl + s_st) = pwl0; *(uint4*)(sWl + s_st + 8) = pwl1;
        __syncthreads();
        if (k0 + 32 < K) {
            size_t an = a_off + k0 + 32, wn2 = w_off + k0 + 32;
            pah0 = aval ? *(const uint4*)(Ah + an)     : z4;
            pah1 = aval ? *(const uint4*)(Ah + an + 8) : z4;
            pal0 = aval ? *(const uint4*)(Al + an)     : z4;
            pal1 = aval ? *(const uint4*)(Al + an + 8) : z4;
            pwh0 = *(const uint4*)(Wh + wn2);  pwh1 = *(const uint4*)(Wh + wn2 + 8);
            pwl0 = *(const uint4*)(Wl + wn2);  pwl1 = *(const uint4*)(Wl + wn2 + 8);
        }
        #pragma unroll
        for (int kh = 0; kh < 2; kh++) {
            const int kb = kh*16 + tg*2;
            uint32_t bh[4][2], bl2[4][2];
            #pragma unroll
            for (int nf = 0; nf < 4; nf++) {
                const __nv_bfloat16* wr = sWh + (wn + nf*8 + g)*MM_SA;
                const __nv_bfloat16* wl3 = sWl + (wn + nf*8 + g)*MM_SA;
                bh[nf][0] = *(const uint32_t*)(wr + kb);
                bh[nf][1] = *(const uint32_t*)(wr + kb + 8);
                bl2[nf][0] = *(const uint32_t*)(wl3 + kb);
                bl2[nf][1] = *(const uint32_t*)(wl3 + kb + 8);
            }
            #pragma unroll
            for (int mf = 0; mf < 4; mf++) {
                const __nv_bfloat16* arh = sAh + (wm + mf*16 + g)*MM_SA;
                const __nv_bfloat16* arl = sAl + (wm + mf*16 + g)*MM_SA;
                uint32_t ah0 = *(const uint32_t*)(arh + kb);
                uint32_t ah1 = *(const uint32_t*)(arh + 8*MM_SA + kb);
                uint32_t ah2 = *(const uint32_t*)(arh + kb + 8);
                uint32_t ah3 = *(const uint32_t*)(arh + 8*MM_SA + kb + 8);
                uint32_t al0 = *(const uint32_t*)(arl + kb);
                uint32_t al1 = *(const uint32_t*)(arl + 8*MM_SA + kb);
                uint32_t al2 = *(const uint32_t*)(arl + kb + 8);
                uint32_t al3 = *(const uint32_t*)(arl + 8*MM_SA + kb + 8);
                #pragma unroll
                for (int nf = 0; nf < 4; nf++) {
                    mma16816(acc[mf][nf], ah0, ah1, ah2, ah3, bh[nf][0], bh[nf][1]);
                    mma16816(acc[mf][nf], ah0, ah1, ah2, ah3, bl2[nf][0], bl2[nf][1]);
                    mma16816(acc[mf][nf], al0, al1, al2, al3, bh[nf][0], bh[nf][1]);
                }
            }
        }
    }

    #pragma unroll
    for (int mf = 0; mf < 4; mf++) {
        int r0 = bm + wm + mf*16 + g;
        #pragma unroll
        for (int nf = 0; nf < 4; nf++) {
            int col = bn + wn + nf*8 + tg*2;
            float b0 = bias[col], b1 = bias[col+1];
            if (r0 < Mtot) {
                float2 v = make_float2(acc[mf][nf][0] + b0, acc[mf][nf][1] + b1);
                *(float2*)(C + (size_t)r0*G4 + col) = v;
            }
            if (r0 + 8 < Mtot) {
                float2 v = make_float2(acc[mf][nf][2] + b0, acc[mf][nf][3] + b1);
                *(float2*)(C + (size_t)(r0+8)*G4 + col) = v;
            }
        }
    }
}

// ------------------- zero per-launch states + snapshot lstm barrier base ------
__global__ void zero_states()
{
    int gt = blockIdx.x*blockDim.x + threadIdx.x;
    if (gt == 0) g_base_lstm = g_tick;
    int stride = gridDim.x*blockDim.x;
    for (int i = gt; i < 4*BB*HH; i += stride) g_hstate[i]=0.f;
    for (int i = gt; i < 2*BB*HH; i += stride) g_cstate[i]=0.f;
}

// ------------------- precompute stack pointers from golds -------------------
__global__ void ptr_kernel(const int* __restrict__ golds)
{
    int b = threadIdx.x;
    if (b >= BB) return;
    int sp = 0, wp = 0;
    for (int t = 0; t < TT; t++) {
        g_spa[t*BB+b] = sp;
        g_wpa[t*BB+b] = wp;
        int g = golds[b*SS + t + 1];
        sp += (g==0) ? 1 : 2;
        wp += (g==0) ? 0 : 1;
    }
}

// ------------------- persistent BiLSTM: 192 blocks, 256 steps -----------------
__global__ __launch_bounds__(256, 2) void lstm_persist()
{
    __shared__ __align__(16) char sb[SBSZ];
    __shared__ const float* aptrs[BB];
    const int tid = threadIdx.x, bid = blockIdx.x;
    const int dir = bid / 96;
    const int j0 = (bid % 96) << 3;
    const unsigned base = g_base_lstm;
    const float* gibase = dir ? g_gi_b : g_gi_f;
    float* cst = g_cstate + (size_t)dir*BB*HH;
    const __nv_bfloat16* Wh8 = g_PL_h + ((size_t)dir*G4 + j0*4)*HH;
    const __nv_bfloat16* Wl8 = g_PL_l + ((size_t)dir*G4 + j0*4)*HH;
    const int jj = tid & 7, mg = tid >> 3;
    const int j = j0 + jj;

    for (int t = 0; t < SS; t++) {
        const int tt = dir ? (SS-1-t) : t;
        const float* gi = gibase + (size_t)tt*BB*G4;
        const float* hin = g_hstate + (size_t)(dir*2 + (t&1))*BB*HH;
        float* hout = g_hstate + (size_t)(dir*2 + ((t&1)^1))*BB*HH;
        if (tid < BB) aptrs[tid] = hin + tid*HH;
        __syncthreads();
        float acc[2][4] = {};
        mma_seg(acc, aptrs, Wh8, Wl8, HH, sb, tid);
        float* sOut = (float*)sb;
        __syncthreads();
        dump_acc(sOut, acc, tid);
        __syncthreads();
        #pragma unroll
        for (int mi=0; mi<2; mi++) {
            int b = (mg<<1) + mi;
            float vi = gi[b*G4 +        j] + sOut[b*36 + jj*4 + 0];
            float vf = gi[b*G4 + HH +   j] + sOut[b*36 + jj*4 + 1];
            float vg = gi[b*G4 + 2*HH + j] + sOut[b*36 + jj*4 + 2];
            float vo = gi[b*G4 + 3*HH + j] + sOut[b*36 + jj*4 + 3];
            float c = sigf(vf)*cst[b*HH+j] + sigf(vi)*tanhf(vg);
            float h = sigf(vo)*tanhf(c);
            cst[b*HH+j] = c;
            hout[b*HH+j] = h;
            g_lstm_out[((size_t)b*SS + tt)*(2*HH) + dir*HH + j] = h;
        }
        if (t < SS-1) gbar(base + (unsigned)(t+1)*NB_LSTM);
    }
}

// ------------------- persistent decode: 289 blocks, 255 steps -----------------
__global__ __launch_bounds__(256, 2) void decode_persist(
    const float* __restrict__ word_b, const float* __restrict__ clsW,
    float* __restrict__ out)
{
    __shared__ __align__(16) char sb[SBSZ];
    __shared__ const float* aptrs[BB];
    __shared__ int idx_s[BB];
    const int tid = threadIdx.x, bid = blockIdx.x;
    const unsigned base = g_base_dec;
    const int j0 = (bid < 96) ? (bid << 3) : 0;

    for (int t = 0; t <= TT; t++) {
        // ---------- phase A: subword cell (blocks 0-95) + word epilogue (96-287) ----
        if (bid < 96 && t < TT) {
            if (tid < BB) {
                int sp = g_spa[t*BB + tid];
                idx_s[tid] = sp;
                aptrs[tid] = g_sh + ((size_t)tid*SLEN + sp)*HH;
            }
            __syncthreads();
            float acc[2][4] = {};
            mma_seg(acc, aptrs, g_PS_h + (size_t)(j0*4)*HH, g_PS_l + (size_t)(j0*4)*HH,
                    HH, sb, tid);
            float* sOut = (float*)sb;
            __syncthreads();
            dump_acc(sOut, acc, tid);
            __syncthreads();
            const float* gi = g_pre1 + (size_t)t*BB*G4;
            const int jj = tid & 7, mg = tid >> 3;
            const int j = j0 + jj;
            #pragma unroll
            for (int mi=0; mi<2; mi++) {
                int b = (mg<<1) + mi;
                int sp = idx_s[b];
                float vi = gi[b*G4 +        j] + sOut[b*36 + jj*4 + 0];
                float vf = gi[b*G4 + HH +   j] + sOut[b*36 + jj*4 + 1];
                float vg = gi[b*G4 + 2*HH + j] + sOut[b*36 + jj*4 + 2];
                float vo = gi[b*G4 + 3*HH + j] + sOut[b*36 + jj*4 + 3];
                float c = sigf(vf)*g_sc[((size_t)b*SLEN + sp)*HH + j] + sigf(vi)*tanhf(vg);
                float h = sigf(vo)*tanhf(c);
                g_sh[((size_t)b*SLEN + sp + 1)*HH + j] = h;
                g_sc[((size_t)b*SLEN + sp + 1)*HH + j] = c;
                g_h1[b*HH+j] = h;
                g_c1[b*HH+j] = c;
            }
        } else if (bid >= 96 && bid < 288 && t > 0) {
            // word-cell epilogue for step u = t-1 (g_bpart is permuted: col j*4+g)
            const int u = t - 1;
            const int tile = bid - 96;          // 0..191
            const int b = tile / 3;
            const int j = (tile % 3)*256 + tid;
            const int wp = g_wpa[u*BB + b];
            float4 p4 = *(const float4*)&g_bpart[(size_t)b*G4 + j*4];
            float vi = word_b[j]        + p4.x;
            float vf = word_b[HH + j]   + p4.y;
            float vg = word_b[2*HH + j] + p4.z;
            float vo = word_b[3*HH + j] + p4.w;
            float c = sigf(vf)*g_wc[((size_t)b*WLEN + wp)*HH + j] + sigf(vi)*tanhf(vg);
            float h = sigf(vo)*tanhf(c);
            g_wh[((size_t)b*WLEN + wp + 1)*HH + j] = h;
            g_wc[((size_t)b*WLEN + wp + 1)*HH + j] = c;
            g_whbuf[b*HH + j] = h;
        }
        gbar(base + (unsigned)(2*t+1)*NB_DEC);

        // ---------- phase B: word-cell GEMM K=2304 (blocks 0-95) + classifier (288) -
        if (bid < 96 && t < TT) {
            if (tid < BB) {
                idx_s[tid] = g_wpa[t*BB + tid];
                aptrs[tid] = g_h1 + tid*HH;
            }
            __syncthreads();
            float acc[2][4] = {};
            mma_seg(acc, aptrs, g_PWih_h + (size_t)(j0*4)*(2*HH),
                    g_PWih_l + (size_t)(j0*4)*(2*HH), 2*HH, sb, tid);
            __syncthreads();
            if (tid < BB) aptrs[tid] = g_c1 + tid*HH;
            __syncthreads();
            mma_seg(acc, aptrs, g_PWih_h + (size_t)(j0*4)*(2*HH) + HH,
                    g_PWih_l + (size_t)(j0*4)*(2*HH) + HH, 2*HH, sb, tid);
            __syncthreads();
            if (tid < BB) aptrs[tid] = g_wh + ((size_t)tid*WLEN + idx_s[tid])*HH;
            __syncthreads();
            mma_seg(acc, aptrs, g_PWhh_h + (size_t)(j0*4)*HH,
                    g_PWhh_l + (size_t)(j0*4)*HH, HH, sb, tid);
            // store pre-activations (permuted cols) to g_bpart
            const int lane=tid&31, wid2=tid>>5, g2=lane>>2, tg=lane&3;
            const int wm=(wid2>>1)<<4, wn2=(wid2&1)<<4;
            #pragma unroll
            for (int nf=0; nf<2; nf++) {
                int col = j0*4 + wn2 + nf*8 + tg*2;
                *(float2*)&g_bpart[(size_t)(wm+g2)*G4 + col]   = make_float2(acc[nf][0], acc[nf][1]);
                *(float2*)&g_bpart[(size_t)(wm+g2+8)*G4 + col] = make_float2(acc[nf][2], acc[nf][3]);
            }
        } else if (bid == 288 && t > 0) {
            // classifier for step u = t-1 -> output position t
            const int u = t - 1;
            if (tid < 128) {
                int b = tid >> 1, c = tid & 1;
                const float* w = clsW + c*(3*HH);
                const float* hb = g_whbuf + b*HH;
                float s0 = g_ccur[u*BB*2 + (b<<1) + c], s1=0.f, s2=0.f, s3=0.f;
                #pragma unroll 4
                for (int k = 0; k < HH; k += 4) {
                    s0 += hb[k]*w[k];     s1 += hb[k+1]*w[k+1];
                    s2 += hb[k+2]*w[k+2]; s3 += hb[k+3]*w[k+3];
                }
                out[((size_t)b*SS + u + 1)*2 + c] = s0+s1+s2+s3;
            }
        }
        if (t < TT) gbar(base + (unsigned)(2*t+2)*NB_DEC);
    }
}

// -------- x_cur classifier halves + first row + decode barrier base snapshot ---
__global__ void ccur_kernel(const float* __restrict__ clsW, const float* __restrict__ clsb,
                            float* __restrict__ out)
{
    int gt = blockIdx.x*blockDim.x + threadIdx.x;
    if (gt == 0) g_base_dec = g_tick;
    int gw = gt >> 5, lane = gt & 31;
    if (gw < TT*BB*2) {
        int t = gw >> 7, rem = gw & 127, b = rem >> 1, c = rem & 1;
        const float* x = g_lstm_out + ((size_t)b*SS + t + 1)*(2*HH);
        const float* w = clsW + c*(3*HH) + HH;
        float s = 0.f;
        for (int k = lane; k < 2*HH; k += 32) s += x[k]*w[k];
        #pragma unroll
        for (int o = 16; o; o >>= 1) s += __shfl_xor_sync(0xffffffffu, s, o);
        if (lane == 0) g_ccur[gw] = s + clsb[c];
    }
    if (gt < 128) {
        int b = gt >> 1, c = gt & 1;
        out[(size_t)b*SS*2 + c] = c ? 1.f : -1.f;
    }
}

// ------------------- launch -------------------
extern "C" void kernel_launch(void* const* d_in, const int* in_sizes, int n_in,
                              void* d_out, int out_size)
{
    const int dictOrder = (in_sizes[1] == BB*SS);
    const float* hsin = (const float*)d_in[0];
    const int* golds;
    const float *Wih_f,*Whh_f,*b_f,*Wih_b,*Whh_b,*b_b;
    const float *subw_Wih,*subw_Whh,*subw_b,*word_Wih,*word_Whh,*word_b,*clsW,*clsb;
    if (dictOrder) {
        golds    = (const int*)  d_in[1];
        Wih_f    = (const float*)d_in[2];  Whh_f   = (const float*)d_in[3];
        b_f      = (const float*)d_in[4];  Wih_b   = (const float*)d_in[5];
        Whh_b    = (const float*)d_in[6];  b_b     = (const float*)d_in[7];
        subw_Wih = (const float*)d_in[8];  subw_Whh= (const float*)d_in[9];
        subw_b   = (const float*)d_in[10]; word_Wih= (const float*)d_in[11];
        word_Whh = (const float*)d_in[12]; word_b  = (const float*)d_in[13];
        clsW     = (const float*)d_in[14]; clsb    = (const float*)d_in[15];
    } else {
        Wih_f    = (const float*)d_in[1];  Whh_f   = (const float*)d_in[2];
        b_f      = (const float*)d_in[3];  Wih_b   = (const float*)d_in[4];
        Whh_b    = (const float*)d_in[5];  b_b     = (const float*)d_in[6];
        subw_Wih = (const float*)d_in[7];  subw_Whh= (const float*)d_in[8];
        subw_b   = (const float*)d_in[9];  word_Wih= (const float*)d_in[10];
        word_Whh = (const float*)d_in[11]; word_b  = (const float*)d_in[12];
        clsW     = (const float*)d_in[13]; clsb    = (const float*)d_in[14];
        golds    = (const int*)  d_in[15];
    }
    float* out = (float*)d_out;

    float *p_gif, *p_gib, *p_lo, *p_pre1;
    cudaGetSymbolAddress((void**)&p_gif,  g_gi_f);
    cudaGetSymbolAddress((void**)&p_gib,  g_gi_b);
    cudaGetSymbolAddress((void**)&p_lo,   g_lstm_out);
    cudaGetSymbolAddress((void**)&p_pre1, g_pre1);
    __nv_bfloat16 *p_Ah, *p_Al, *p_Wh, *p_Wl;
    cudaGetSymbolAddress((void**)&p_Ah, g_Ah);
    cudaGetSymbolAddress((void**)&p_Al, g_Al);
    cudaGetSymbolAddress((void**)&p_Wh, g_Wbh);
    cudaGetSymbolAddress((void**)&p_Wl, g_Wbl);
    __nv_bfloat16 *p_PLh, *p_PLl, *p_PSh, *p_PSl, *p_PWihh, *p_PWihl, *p_PWhhh, *p_PWhhl;
    cudaGetSymbolAddress((void**)&p_PLh, g_PL_h);
    cudaGetSymbolAddress((void**)&p_PLl, g_PL_l);
    cudaGetSymbolAddress((void**)&p_PSh, g_PS_h);
    cudaGetSymbolAddress((void**)&p_PSl, g_PS_l);
    cudaGetSymbolAddress((void**)&p_PWihh, g_PWih_h);
    cudaGetSymbolAddress((void**)&p_PWihl, g_PWih_l);
    cudaGetSymbolAddress((void**)&p_PWhhh, g_PWhh_h);
    cudaGetSymbolAddress((void**)&p_PWhhl, g_PWhh_l);

    zero_states<<<96, 256>>>();
    ptr_kernel<<<1, 64>>>(golds);

    // big tensor GEMMs for gate precompute
    conv_split<<<2048, 256>>>(hsin, p_Ah, p_Al, BB*SS*HH);
    conv_split<<<2048, 256>>>(Wih_f, p_Wh, p_Wl, G4*HH);
    gemm_mma<<<dim3(24, 128), 256>>>(p_Ah, p_Al, p_Wh, p_Wl, b_f, p_gif, HH, BB*SS);
    conv_split<<<2048, 256>>>(Wih_b, p_Wh, p_Wl, G4*HH);
    gemm_mma<<<dim3(24, 128), 256>>>(p_Ah, p_Al, p_Wh, p_Wl, b_b, p_gib, HH, BB*SS);

    // lstm recurrence weights: split + permute
    conv_split_perm<<<dim3(3, G4), 256>>>(Whh_f, p_PLh, p_PLl, HH);
    conv_split_perm<<<dim3(3, G4), 256>>>(Whh_b, p_PLh + (size_t)G4*HH, p_PLl + (size_t)G4*HH, HH);

    // persistent BiLSTM recurrence (256 steps inside), on tensor cores
    lstm_persist<<<NB_LSTM, 256>>>();

    // subword input precompute: (16320,1536)@(1536,3072)+b
    conv_split<<<4096, 256>>>(p_lo, p_Ah, p_Al, BB*SS*2*HH);
    conv_split<<<2048, 256>>>(subw_Wih, p_Wh, p_Wl, G4*2*HH);
    gemm_mma<<<dim3(24, 128), 256>>>(p_Ah, p_Al, p_Wh, p_Wl, subw_b, p_pre1, 2*HH, TT*BB);

    // decode weights: split + permute
    conv_split_perm<<<dim3(3, G4), 256>>>(subw_Whh, p_PSh, p_PSl, HH);
    conv_split_perm<<<dim3(6, G4), 256>>>(word_Wih, p_PWihh, p_PWihl, 2*HH);
    conv_split_perm<<<dim3(3, G4), 256>>>(word_Whh, p_PWhhh, p_PWhhl, HH);

    // classifier x_cur halves + first output row + decode barrier base
    ccur_kernel<<<4080, 256>>>(clsW, clsb, out);

    // persistent decode (255 steps + tail inside), on tensor cores
    decode_persist<<<NB_DEC, 256>>>(word_b, clsW, out);
}

// round 16
// speedup vs baseline: 2.6137x; 1.0645x over previous
#include <cuda_runtime.h>
#include <cuda_bf16.h>
#include <cstdint>
#include <math.h>

#define BB 64
#define SS 256
#define HH 768
#define G4 3072          // 4*H
#define TT 255           // decode steps
#define SLEN (2*SS+2)    // 514
#define WLEN (SS+1)      // 257
#define NB_LSTM 192
#define NB_DEC  289
#define SBSZ 27648       // helper smem: A hi/lo (18432B) + W hi/lo (9216B)

// ------------------- device scratch (BSS zero-initialized) -------------------
__device__ float g_gi_f[(size_t)SS*BB*G4];
__device__ float g_gi_b[(size_t)SS*BB*G4];
__device__ float g_lstm_out[(size_t)BB*SS*2*HH];  // [b][t][2H]
__device__ float g_pre1[(size_t)TT*BB*G4];        // x_prev @ subw_Wih.T + b
__device__ float g_sc[(size_t)BB*SLEN*HH];
__device__ float g_wc[(size_t)BB*WLEN*HH];
__device__ float g_bpart[(size_t)3*BB*G4];        // word pre-act partials, PERMUTED cols
__device__ float g_hstate[4*BB*HH];
__device__ float g_cstate[2*BB*HH];
__device__ float g_whbuf[BB*HH];
__device__ float g_ccur[TT*BB*2];
__device__ int   g_spa[TT*BB];
__device__ int   g_wpa[TT*BB];

// bf16 hi/lo activation stacks (decode)
__device__ __align__(16) __nv_bfloat16 g_shH[(size_t)BB*SLEN*HH];
__device__ __align__(16) __nv_bfloat16 g_shL[(size_t)BB*SLEN*HH];
__device__ __align__(16) __nv_bfloat16 g_whH[(size_t)BB*WLEN*HH];
__device__ __align__(16) __nv_bfloat16 g_whL[(size_t)BB*WLEN*HH];
__device__ __align__(16) __nv_bfloat16 g_h1H[BB*HH], g_h1L[BB*HH];
__device__ __align__(16) __nv_bfloat16 g_c1H[BB*HH], g_c1L[BB*HH];

// split-bf16 operand buffers for big tensor GEMMs
__device__ __align__(16) __nv_bfloat16 g_Ah[(size_t)16384*1536];
__device__ __align__(16) __nv_bfloat16 g_Al[(size_t)16384*1536];
__device__ __align__(16) __nv_bfloat16 g_Wbh[(size_t)3072*1536];
__device__ __align__(16) __nv_bfloat16 g_Wbl[(size_t)3072*1536];

// split + row-permuted (r' = j*4 + gate) weights for persistent kernels
__device__ __align__(16) __nv_bfloat16 g_PL_h[(size_t)2*G4*HH];   // lstm Whh f,b
__device__ __align__(16) __nv_bfloat16 g_PL_l[(size_t)2*G4*HH];
__device__ __align__(16) __nv_bfloat16 g_PS_h[(size_t)G4*HH];     // subw_Whh
__device__ __align__(16) __nv_bfloat16 g_PS_l[(size_t)G4*HH];
__device__ __align__(16) __nv_bfloat16 g_PWih_h[(size_t)G4*2*HH]; // word_Wih
__device__ __align__(16) __nv_bfloat16 g_PWih_l[(size_t)G4*2*HH];
__device__ __align__(16) __nv_bfloat16 g_PWhh_h[(size_t)G4*HH];   // word_Whh
__device__ __align__(16) __nv_bfloat16 g_PWhh_l[(size_t)G4*HH];

// monotonic grid-barrier ticket (never reset; replay-safe via base snapshots)
__device__ unsigned g_tick;
__device__ unsigned g_base_lstm;
__device__ unsigned g_base_dec;

__device__ __forceinline__ float sigf(float x){ return 1.f/(1.f+expf(-x)); }

__device__ __forceinline__ void gbar(unsigned target)
{
    __syncthreads();
    if (threadIdx.x == 0) {
        __threadfence();
        atomicAdd(&g_tick, 1u);
        volatile unsigned* vt = &g_tick;
        while (*vt < target) __nanosleep(64);
        __threadfence();
    }
    __syncthreads();
}

// ---------------- split fp32 -> bf16 hi/lo ------------------------------------
__global__ void conv_split(const float* __restrict__ src,
                           __nv_bfloat16* __restrict__ hi, __nv_bfloat16* __restrict__ lo, int n)
{
    int stride = gridDim.x*blockDim.x;
    for (int i = blockIdx.x*blockDim.x + threadIdx.x; i < n; i += stride) {
        float x = src[i];
        __nv_bfloat16 h = __float2bfloat16(x);
        hi[i] = h;
        lo[i] = __float2bfloat16(x - __bfloat162float(h));
    }
}

// ------- split + permute rows: dst row (j*4+g) = src row (g*HH+j) -------------
__global__ void conv_split_perm(const float* __restrict__ src,
    __nv_bfloat16* __restrict__ hi, __nv_bfloat16* __restrict__ lo, int K)
{
    int r = blockIdx.y;
    int k = blockIdx.x*blockDim.x + threadIdx.x;
    if (k >= K) return;
    int gq = r / HH, jq = r - gq*HH;
    size_t di = (size_t)(jq*4 + gq)*K + k;
    float x = src[(size_t)r*K + k];
    __nv_bfloat16 h = __float2bfloat16(x);
    hi[di] = h;
    lo[di] = __float2bfloat16(x - __bfloat162float(h));
}

// ---------------- mma.sync bf16 helper ----------------------------------------
__device__ __forceinline__ void mma16816(float c[4],
    uint32_t a0, uint32_t a1, uint32_t a2, uint32_t a3, uint32_t b0, uint32_t b1)
{
    asm volatile(
        "mma.sync.aligned.m16n8k16.row.col.f32.bf16.bf16.f32 "
        "{%0,%1,%2,%3}, {%4,%5,%6,%7}, {%8,%9}, {%0,%1,%2,%3};"
        : "+f"(c[0]), "+f"(c[1]), "+f"(c[2]), "+f"(c[3])
        : "r"(a0), "r"(a1), "r"(a2), "r"(a3), "r"(b0), "r"(b1));
}

#define MSA 72   // smem row stride (bf16 elems)

// shared inner MMA for 64Mx32N tile (8 warps: wm=(wid/2)*16, wn=(wid&1)*16)
__device__ __forceinline__ void mma_inner(float (&acc)[2][4],
    const __nv_bfloat16* sA, const __nv_bfloat16* sW, int wm, int wn2, int g, int tg)
{
    #pragma unroll
    for (int kh = 0; kh < 4; kh++) {
        const int kb = kh*16 + tg*2;
        const __nv_bfloat16* ar_ = sA + (wm+g)*MSA + kb;
        uint32_t ah0=*(const uint32_t*)(ar_);
        uint32_t ah1=*(const uint32_t*)(ar_ + 8*MSA);
        uint32_t ah2=*(const uint32_t*)(ar_ + 8);
        uint32_t ah3=*(const uint32_t*)(ar_ + 8*MSA + 8);
        const __nv_bfloat16* al_ = ar_ + 64*MSA;
        uint32_t bl0=*(const uint32_t*)(al_);
        uint32_t bl1=*(const uint32_t*)(al_ + 8*MSA);
        uint32_t bl2=*(const uint32_t*)(al_ + 8);
        uint32_t bl3=*(const uint32_t*)(al_ + 8*MSA + 8);
        #pragma unroll
        for (int nf = 0; nf < 2; nf++) {
            const __nv_bfloat16* br_ = sW + (wn2+nf*8+g)*MSA + kb;
            uint32_t b0=*(const uint32_t*)(br_), b1=*(const uint32_t*)(br_+8);
            const __nv_bfloat16* bw_ = br_ + 32*MSA;
            uint32_t c0=*(const uint32_t*)(bw_), c1=*(const uint32_t*)(bw_+8);
            mma16816(acc[nf], ah0,ah1,ah2,ah3, b0,b1);
            mma16816(acc[nf], ah0,ah1,ah2,ah3, c0,c1);
            mma16816(acc[nf], bl0,bl1,bl2,bl3, b0,b1);
        }
    }
}

// ===== fp32-A variant (lstm): on-the-fly split =====
__device__ __forceinline__ void mma_seg(
    float (&acc)[2][4], const float* const* aptrs,
    const __nv_bfloat16* __restrict__ Wh8, const __nv_bfloat16* __restrict__ Wl8,
    int wK, char* sb, int tid)
{
    __nv_bfloat16* sA = (__nv_bfloat16*)sb;
    __nv_bfloat16* sW = (__nv_bfloat16*)(sb + 18432);
    const int arow = tid >> 2, akq = (tid & 3) << 4;
    const int wrow = tid >> 3, wkq = (tid & 7) << 3;
    const int lane = tid & 31, wid = tid >> 5;
    const int g = lane >> 2, tg = lane & 3;
    const int wm = (wid >> 1) << 4;
    const int wn2 = (wid & 1) << 4;
    const float* ap = aptrs[arow] + akq;
    const __nv_bfloat16* wph = Wh8 + (size_t)wrow*wK + wkq;
    const __nv_bfloat16* wpl = Wl8 + (size_t)wrow*wK + wkq;
    float4 f0 = *(const float4*)(ap),     f1 = *(const float4*)(ap+4);
    float4 f2 = *(const float4*)(ap+8),   f3 = *(const float4*)(ap+12);
    uint4 wh = *(const uint4*)wph, wl = *(const uint4*)wpl;
    #pragma unroll 1
    for (int k0 = 0; k0 < HH; k0 += 64) {
        __syncthreads();
        {
            float fs[16];
            *(float4*)&fs[0]=f0; *(float4*)&fs[4]=f1; *(float4*)&fs[8]=f2; *(float4*)&fs[12]=f3;
            __nv_bfloat16 hb[16], lb[16];
            #pragma unroll
            for (int i2=0;i2<16;i2++){
                __nv_bfloat16 h = __float2bfloat16(fs[i2]);
                hb[i2]=h; lb[i2]=__float2bfloat16(fs[i2]-__bfloat162float(h));
            }
            __nv_bfloat16* da = sA + arow*MSA + akq;
            *(uint4*)(da)   = *(uint4*)&hb[0]; *(uint4*)(da+8) = *(uint4*)&hb[8];
            __nv_bfloat16* dl = da + 64*MSA;
            *(uint4*)(dl)   = *(uint4*)&lb[0]; *(uint4*)(dl+8) = *(uint4*)&lb[8];
            __nv_bfloat16* dw = sW + wrow*MSA + wkq;
            *(uint4*)dw = wh;
            *(uint4*)(dw + 32*MSA) = wl;
        }
        __syncthreads();
        if (k0 + 64 < HH) {
            const float* ap2 = ap + k0 + 64;
            f0=*(const float4*)(ap2);   f1=*(const float4*)(ap2+4);
            f2=*(const float4*)(ap2+8); f3=*(const float4*)(ap2+12);
            wh=*(const uint4*)(wph + k0 + 64); wl=*(const uint4*)(wpl + k0 + 64);
        }
        mma_inner(acc, sA, sW, wm, wn2, g, tg);
    }
}

// ===== bf16-A variant (decode): A pre-split hi/lo, pure copies =====
__device__ __forceinline__ void mma_seg_b(
    float (&acc)[2][4],
    const __nv_bfloat16* const* aph, const __nv_bfloat16* const* apl,
    const __nv_bfloat16* __restrict__ Wh8, const __nv_bfloat16* __restrict__ Wl8,
    int wK, char* sb, int tid)
{
    __nv_bfloat16* sA = (__nv_bfloat16*)sb;
    __nv_bfloat16* sW = (__nv_bfloat16*)(sb + 18432);
    const int arow = tid >> 2, akq = (tid & 3) << 4;
    const int wrow = tid >> 3, wkq = (tid & 7) << 3;
    const int lane = tid & 31, wid = tid >> 5;
    const int g = lane >> 2, tg = lane & 3;
    const int wm = (wid >> 1) << 4;
    const int wn2 = (wid & 1) << 4;
    const __nv_bfloat16* pah = aph[arow] + akq;
    const __nv_bfloat16* pal = apl[arow] + akq;
    const __nv_bfloat16* wph = Wh8 + (size_t)wrow*wK + wkq;
    const __nv_bfloat16* wpl = Wl8 + (size_t)wrow*wK + wkq;
    uint4 h0 = *(const uint4*)pah, h1 = *(const uint4*)(pah+8);
    uint4 l0 = *(const uint4*)pal, l1 = *(const uint4*)(pal+8);
    uint4 wh = *(const uint4*)wph, wl = *(const uint4*)wpl;
    #pragma unroll 1
    for (int k0 = 0; k0 < HH; k0 += 64) {
        __syncthreads();
        {
            __nv_bfloat16* da = sA + arow*MSA + akq;
            *(uint4*)(da)   = h0; *(uint4*)(da+8) = h1;
            __nv_bfloat16* dl = da + 64*MSA;
            *(uint4*)(dl)   = l0; *(uint4*)(dl+8) = l1;
            __nv_bfloat16* dw = sW + wrow*MSA + wkq;
            *(uint4*)dw = wh;
            *(uint4*)(dw + 32*MSA) = wl;
        }
        __syncthreads();
        if (k0 + 64 < HH) {
            h0 = *(const uint4*)(pah + k0 + 64); h1 = *(const uint4*)(pah + k0 + 72);
            l0 = *(const uint4*)(pal + k0 + 64); l1 = *(const uint4*)(pal + k0 + 72);
            wh = *(const uint4*)(wph + k0 + 64); wl = *(const uint4*)(wpl + k0 + 64);
        }
        mma_inner(acc, sA, sW, wm, wn2, g, tg);
    }
}

__device__ __forceinline__ void dump_acc(float* sOut, float (&acc)[2][4], int tid)
{
    const int lane=tid&31, wid=tid>>5, g=lane>>2, tg=lane&3;
    const int wm=(wid>>1)<<4, wn2=(wid&1)<<4;
    #pragma unroll
    for (int nf=0; nf<2; nf++) {
        int col = wn2 + nf*8 + tg*2;
        sOut[(wm+g)*36+col]   = acc[nf][0];
        sOut[(wm+g)*36+col+1] = acc[nf][1];
        sOut[(wm+g+8)*36+col]   = acc[nf][2];
        sOut[(wm+g+8)*36+col+1] = acc[nf][3];
    }
}

// -------- big tensor GEMM via mma.sync ----------------------------------------
#define MM_SA 40
__global__ __launch_bounds__(256) void gemm_mma(
    const __nv_bfloat16* __restrict__ Ah, const __nv_bfloat16* __restrict__ Al,
    const __nv_bfloat16* __restrict__ Wh, const __nv_bfloat16* __restrict__ Wl,
    const float* __restrict__ bias, float* __restrict__ C, int K, int Mtot)
{
    __shared__ __nv_bfloat16 sAh[128*MM_SA], sAl[128*MM_SA];
    __shared__ __nv_bfloat16 sWh[128*MM_SA], sWl[128*MM_SA];
    const int tid = threadIdx.x, wid = tid >> 5, lane = tid & 31;
    const int g = lane >> 2, tg = lane & 3;
    const int bm = blockIdx.y << 7, bn = blockIdx.x << 7;
    const int wm = (wid >> 2) << 6, wn = (wid & 3) << 5;
    const int lrow = tid >> 1, lhalf = tid & 1;

    const int arow_i = bm + lrow;
    const bool aval = arow_i < Mtot;
    const size_t a_off = ((size_t)(arow_i & 63)*SS + (arow_i >> 6))*K + lhalf*16;
    const size_t w_off = (size_t)(bn + lrow)*K + lhalf*16;
    const uint32_t s_st = lrow*MM_SA + lhalf*16;

    float acc[4][4][4];
    #pragma unroll
    for (int mf=0; mf<4; mf++)
        #pragma unroll
        for (int nf=0; nf<4; nf++)
            #pragma unroll
            for (int q=0; q<4; q++) acc[mf][nf][q] = 0.f;

    const uint4 z4 = make_uint4(0u,0u,0u,0u);
    uint4 pah0, pah1, pal0, pal1, pwh0, pwh1, pwl0, pwl1;
    pah0 = aval ? *(const uint4*)(Ah + a_off)     : z4;
    pah1 = aval ? *(const uint4*)(Ah + a_off + 8) : z4;
    pal0 = aval ? *(const uint4*)(Al + a_off)     : z4;
    pal1 = aval ? *(const uint4*)(Al + a_off + 8) : z4;
    pwh0 = *(const uint4*)(Wh + w_off);     pwh1 = *(const uint4*)(Wh + w_off + 8);
    pwl0 = *(const uint4*)(Wl + w_off);     pwl1 = *(const uint4*)(Wl + w_off + 8);

    for (int k0 = 0; k0 < K; k0 += 32) {
        __syncthreads();
        *(uint4*)(sAh + s_st) = pah0; *(uint4*)(sAh + s_st + 8) = pah1;
        *(uint4*)(sAl + s_st) = pal0; *(uint4*)(sAl + s_st + 8) = pal1;
        *(uint4*)(sWh + s_st) = pwh0; *(uint4*)(sWh + s_st + 8) = pwh1;
        *(uint4*)(sWl + s_st) = pwl0; *(uint4*)(sWl + s_st + 8) = pwl1;
        __syncthreads();
        if (k0 + 32 < K) {
            size_t an = a_off + k0 + 32, wn2 = w_off + k0 + 32;
            pah0 = aval ? *(const uint4*)(Ah + an)     : z4;
            pah1 = aval ? *(const uint4*)(Ah + an + 8) : z4;
            pal0 = aval ? *(const uint4*)(Al + an)     : z4;
            pal1 = aval ? *(const uint4*)(Al + an + 8) : z4;
            pwh0 = *(const uint4*)(Wh + wn2);  pwh1 = *(const uint4*)(Wh + wn2 + 8);
            pwl0 = *(const uint4*)(Wl + wn2);  pwl1 = *(const uint4*)(Wl + wn2 + 8);
        }
        #pragma unroll
        for (int kh = 0; kh < 2; kh++) {
            const int kb = kh*16 + tg*2;
            uint32_t bh[4][2], bl2[4][2];
            #pragma unroll
            for (int nf = 0; nf < 4; nf++) {
                const __nv_bfloat16* wr = sWh + (wn + nf*8 + g)*MM_SA;
                const __nv_bfloat16* wl3 = sWl + (wn + nf*8 + g)*MM_SA;
                bh[nf][0] = *(const uint32_t*)(wr + kb);
                bh[nf][1] = *(const uint32_t*)(wr + kb + 8);
                bl2[nf][0] = *(const uint32_t*)(wl3 + kb);
                bl2[nf][1] = *(const uint32_t*)(wl3 + kb + 8);
            }
            #pragma unroll
            for (int mf = 0; mf < 4; mf++) {
                const __nv_bfloat16* arh = sAh + (wm + mf*16 + g)*MM_SA;
                const __nv_bfloat16* arl = sAl + (wm + mf*16 + g)*MM_SA;
                uint32_t ah0 = *(const uint32_t*)(arh + kb);
                uint32_t ah1 = *(const uint32_t*)(arh + 8*MM_SA + kb);
                uint32_t ah2 = *(const uint32_t*)(arh + kb + 8);
                uint32_t ah3 = *(const uint32_t*)(arh + 8*MM_SA + kb + 8);
                uint32_t al0 = *(const uint32_t*)(arl + kb);
                uint32_t al1 = *(const uint32_t*)(arl + 8*MM_SA + kb);
                uint32_t al2 = *(const uint32_t*)(arl + kb + 8);
                uint32_t al3 = *(const uint32_t*)(arl + 8*MM_SA + kb + 8);
                #pragma unroll
                for (int nf = 0; nf < 4; nf++) {
                    mma16816(acc[mf][nf], ah0, ah1, ah2, ah3, bh[nf][0], bh[nf][1]);
                    mma16816(acc[mf][nf], ah0, ah1, ah2, ah3, bl2[nf][0], bl2[nf][1]);
                    mma16816(acc[mf][nf], al0, al1, al2, al3, bh[nf][0], bh[nf][1]);
                }
            }
        }
    }

    #pragma unroll
    for (int mf = 0; mf < 4; mf++) {
        int r0 = bm + wm + mf*16 + g;
        #pragma unroll
        for (int nf = 0; nf < 4; nf++) {
            int col = bn + wn + nf*8 + tg*2;
            float b0 = bias[col], b1 = bias[col+1];
            if (r0 < Mtot) {
                float2 v = make_float2(acc[mf][nf][0] + b0, acc[mf][nf][1] + b1);
                *(float2*)(C + (size_t)r0*G4 + col) = v;
            }
            if (r0 + 8 < Mtot) {
                float2 v = make_float2(acc[mf][nf][2] + b0, acc[mf][nf][3] + b1);
                *(float2*)(C + (size_t)(r0+8)*G4 + col) = v;
            }
        }
    }
}

// ------------------- zero per-launch states + snapshot lstm barrier base ------
__global__ void zero_states()
{
    int gt = blockIdx.x*blockDim.x + threadIdx.x;
    if (gt == 0) g_base_lstm = g_tick;
    int stride = gridDim.x*blockDim.x;
    for (int i = gt; i < 4*BB*HH; i += stride) g_hstate[i]=0.f;
    for (int i = gt; i < 2*BB*HH; i += stride) g_cstate[i]=0.f;
}

// ------------------- precompute stack pointers from golds -------------------
__global__ void ptr_kernel(const int* __restrict__ golds)
{
    int b = threadIdx.x;
    if (b >= BB) return;
    int sp = 0, wp = 0;
    for (int t = 0; t < TT; t++) {
        g_spa[t*BB+b] = sp;
        g_wpa[t*BB+b] = wp;
        int g = golds[b*SS + t + 1];
        sp += (g==0) ? 1 : 2;
        wp += (g==0) ? 0 : 1;
    }
}

// ------------------- persistent BiLSTM: 192 blocks, 256 steps -----------------
__global__ __launch_bounds__(256, 2) void lstm_persist()
{
    __shared__ __align__(16) char sb[SBSZ];
    __shared__ const float* aptrs[BB];
    const int tid = threadIdx.x, bid = blockIdx.x;
    const int dir = bid / 96;
    const int j0 = (bid % 96) << 3;
    const unsigned base = g_base_lstm;
    const float* gibase = dir ? g_gi_b : g_gi_f;
    float* cst = g_cstate + (size_t)dir*BB*HH;
    const __nv_bfloat16* Wh8 = g_PL_h + ((size_t)dir*G4 + j0*4)*HH;
    const __nv_bfloat16* Wl8 = g_PL_l + ((size_t)dir*G4 + j0*4)*HH;
    const int jj = tid & 7, mg = tid >> 3;
    const int j = j0 + jj;

    for (int t = 0; t < SS; t++) {
        const int tt = dir ? (SS-1-t) : t;
        const float* gi = gibase + (size_t)tt*BB*G4;
        const float* hin = g_hstate + (size_t)(dir*2 + (t&1))*BB*HH;
        float* hout = g_hstate + (size_t)(dir*2 + ((t&1)^1))*BB*HH;
        if (tid < BB) aptrs[tid] = hin + tid*HH;
        __syncthreads();
        float acc[2][4] = {};
        mma_seg(acc, aptrs, Wh8, Wl8, HH, sb, tid);
        float* sOut = (float*)sb;
        __syncthreads();
        dump_acc(sOut, acc, tid);
        __syncthreads();
        #pragma unroll
        for (int mi=0; mi<2; mi++) {
            int b = (mg<<1) + mi;
            float vi = gi[b*G4 +        j] + sOut[b*36 + jj*4 + 0];
            float vf = gi[b*G4 + HH +   j] + sOut[b*36 + jj*4 + 1];
            float vg = gi[b*G4 + 2*HH + j] + sOut[b*36 + jj*4 + 2];
            float vo = gi[b*G4 + 3*HH + j] + sOut[b*36 + jj*4 + 3];
            float c = sigf(vf)*cst[b*HH+j] + sigf(vi)*tanhf(vg);
            float h = sigf(vo)*tanhf(c);
            cst[b*HH+j] = c;
            hout[b*HH+j] = h;
            g_lstm_out[((size_t)b*SS + tt)*(2*HH) + dir*HH + j] = h;
        }
        if (t < SS-1) gbar(base + (unsigned)(t+1)*NB_LSTM);
    }
}

// ------------------- persistent decode: 289 blocks, 255 steps -----------------
__global__ __launch_bounds__(256, 2) void decode_persist(
    const float* __restrict__ word_b, const float* __restrict__ clsW,
    float* __restrict__ out)
{
    __shared__ __align__(16) char sb[SBSZ];
    __shared__ const __nv_bfloat16* aph[BB];
    __shared__ const __nv_bfloat16* apl[BB];
    __shared__ int idx_s[BB];
    const int tid = threadIdx.x, bid = blockIdx.x;
    const unsigned base = g_base_dec;

    for (int t = 0; t <= TT; t++) {
        // ---- phase A: subword cell (blocks 0-95) + word epilogue of t-1 (96-287) --
        if (bid < 96 && t < TT) {
            const int j0 = bid << 3;
            if (tid < BB) {
                int sp = g_spa[t*BB + tid];
                idx_s[tid] = sp;
                aph[tid] = g_shH + ((size_t)tid*SLEN + sp)*HH;
                apl[tid] = g_shL + ((size_t)tid*SLEN + sp)*HH;
            }
            __syncthreads();
            float acc[2][4] = {};
            mma_seg_b(acc, aph, apl, g_PS_h + (size_t)(j0*4)*HH, g_PS_l + (size_t)(j0*4)*HH,
                      HH, sb, tid);
            float* sOut = (float*)sb;
            __syncthreads();
            dump_acc(sOut, acc, tid);
            __syncthreads();
            const float* gi = g_pre1 + (size_t)t*BB*G4;
            const int jj = tid & 7, mg = tid >> 3;
            const int j = j0 + jj;
            #pragma unroll
            for (int mi=0; mi<2; mi++) {
                int b = (mg<<1) + mi;
                int sp = idx_s[b];
                float vi = gi[b*G4 +        j] + sOut[b*36 + jj*4 + 0];
                float vf = gi[b*G4 + HH +   j] + sOut[b*36 + jj*4 + 1];
                float vg = gi[b*G4 + 2*HH + j] + sOut[b*36 + jj*4 + 2];
                float vo = gi[b*G4 + 3*HH + j] + sOut[b*36 + jj*4 + 3];
                float c = sigf(vf)*g_sc[((size_t)b*SLEN + sp)*HH + j] + sigf(vi)*tanhf(vg);
                float h = sigf(vo)*tanhf(c);
                size_t si = ((size_t)b*SLEN + sp + 1)*HH + j;
                g_sc[si] = c;
                __nv_bfloat16 hh = __float2bfloat16(h);
                __nv_bfloat16 hl = __float2bfloat16(h - __bfloat162float(hh));
                g_shH[si] = hh; g_shL[si] = hl;
                g_h1H[b*HH+j] = hh; g_h1L[b*HH+j] = hl;
                __nv_bfloat16 ch = __float2bfloat16(c);
                g_c1H[b*HH+j] = ch;
                g_c1L[b*HH+j] = __float2bfloat16(c - __bfloat162float(ch));
            }
        } else if (bid >= 96 && bid < 288 && t > 0) {
            // word-cell epilogue for step u = t-1; sums 3 permuted partial segs
            const int u = t - 1;
            const int tile = bid - 96;          // 0..191
            const int b = tile / 3;
            const int j = (tile % 3)*256 + tid;
            const int wp = g_wpa[u*BB + b];
            float4 p0 = *(const float4*)&g_bpart[(size_t)b*G4 + j*4];
            float4 p1 = *(const float4*)&g_bpart[(size_t)(BB + b)*G4 + j*4];
            float4 p2 = *(const float4*)&g_bpart[(size_t)(2*BB + b)*G4 + j*4];
            float vi = word_b[j]        + p0.x + p1.x + p2.x;
            float vf = word_b[HH + j]   + p0.y + p1.y + p2.y;
            float vg = word_b[2*HH + j] + p0.z + p1.z + p2.z;
            float vo = word_b[3*HH + j] + p0.w + p1.w + p2.w;
            float c = sigf(vf)*g_wc[((size_t)b*WLEN + wp)*HH + j] + sigf(vi)*tanhf(vg);
            float h = sigf(vo)*tanhf(c);
            size_t wi = ((size_t)b*WLEN + wp + 1)*HH + j;
            g_wc[wi] = c;
            __nv_bfloat16 hh = __float2bfloat16(h);
            g_whH[wi] = hh;
            g_whL[wi] = __float2bfloat16(h - __bfloat162float(hh));
            g_whbuf[b*HH + j] = h;
        }
        gbar(base + (unsigned)(2*t+1)*NB_DEC);

        // ---- phase B: word GEMM K-split over 288 blocks + classifier (288) --------
        if (bid < 288 && t < TT) {
            const int seg = bid / 96;
            const int j0 = (bid % 96) << 3;
            if (tid < BB) {
                int wp = g_wpa[t*BB + tid];
                idx_s[tid] = wp;
                if (seg == 0)      { aph[tid] = g_h1H + tid*HH; apl[tid] = g_h1L + tid*HH; }
                else if (seg == 1) { aph[tid] = g_c1H + tid*HH; apl[tid] = g_c1L + tid*HH; }
                else               { aph[tid] = g_whH + ((size_t)tid*WLEN + wp)*HH;
                                     apl[tid] = g_whL + ((size_t)tid*WLEN + wp)*HH; }
            }
            __syncthreads();
            const __nv_bfloat16 *Wh8, *Wl8;
            int wK;
            if (seg == 0)      { Wh8 = g_PWih_h + (size_t)(j0*4)*(2*HH);
                                 Wl8 = g_PWih_l + (size_t)(j0*4)*(2*HH); wK = 2*HH; }
            else if (seg == 1) { Wh8 = g_PWih_h + (size_t)(j0*4)*(2*HH) + HH;
                                 Wl8 = g_PWih_l + (size_t)(j0*4)*(2*HH) + HH; wK = 2*HH; }
            else               { Wh8 = g_PWhh_h + (size_t)(j0*4)*HH;
                                 Wl8 = g_PWhh_l + (size_t)(j0*4)*HH; wK = HH; }
            float acc[2][4] = {};
            mma_seg_b(acc, aph, apl, Wh8, Wl8, wK, sb, tid);
            // store partial pre-activations (permuted cols) to g_bpart[seg]
            float* part = g_bpart + (size_t)seg*BB*G4;
            const int lane=tid&31, wid2=tid>>5, g2=lane>>2, tg=lane&3;
            const int wm=(wid2>>1)<<4, wn2=(wid2&1)<<4;
            #pragma unroll
            for (int nf=0; nf<2; nf++) {
                int col = j0*4 + wn2 + nf*8 + tg*2;
                *(float2*)&part[(size_t)(wm+g2)*G4 + col]   = make_float2(acc[nf][0], acc[nf][1]);
                *(float2*)&part[(size_t)(wm+g2+8)*G4 + col] = make_float2(acc[nf][2], acc[nf][3]);
            }
        } else if (bid == 288 && t > 0) {
            // classifier for step u = t-1 -> output position t
            const int u = t - 1;
            if (tid < 128) {
                int b = tid >> 1, c = tid & 1;
                const float* w = clsW + c*(3*HH);
                const float* hb = g_whbuf + b*HH;
                float s0 = g_ccur[u*BB*2 + (b<<1) + c], s1=0.f, s2=0.f, s3=0.f;
                #pragma unroll 4
                for (int k = 0; k < HH; k += 4) {
                    s0 += hb[k]*w[k];     s1 += hb[k+1]*w[k+1];
                    s2 += hb[k+2]*w[k+2]; s3 += hb[k+3]*w[k+3];
                }
                out[((size_t)b*SS + u + 1)*2 + c] = s0+s1+s2+s3;
            }
        }
        if (t < TT) gbar(base + (unsigned)(2*t+2)*NB_DEC);
    }
}

// -------- x_cur classifier halves + first row + decode barrier base snapshot ---
__global__ void ccur_kernel(const float* __restrict__ clsW, const float* __restrict__ clsb,
                            float* __restrict__ out)
{
    int gt = blockIdx.x*blockDim.x + threadIdx.x;
    if (gt == 0) g_base_dec = g_tick;
    int gw = gt >> 5, lane = gt & 31;
    if (gw < TT*BB*2) {
        int t = gw >> 7, rem = gw & 127, b = rem >> 1, c = rem & 1;
        const float* x = g_lstm_out + ((size_t)b*SS + t + 1)*(2*HH);
        const float* w = clsW + c*(3*HH) + HH;
        float s = 0.f;
        for (int k = lane; k < 2*HH; k += 32) s += x[k]*w[k];
        #pragma unroll
        for (int o = 16; o; o >>= 1) s += __shfl_xor_sync(0xffffffffu, s, o);
        if (lane == 0) g_ccur[gw] = s + clsb[c];
    }
    if (gt < 128) {
        int b = gt >> 1, c = gt & 1;
        out[(size_t)b*SS*2 + c] = c ? 1.f : -1.f;
    }
}

// ------------------- launch -------------------
extern "C" void kernel_launch(void* const* d_in, const int* in_sizes, int n_in,
                              void* d_out, int out_size)
{
    const int dictOrder = (in_sizes[1] == BB*SS);
    const float* hsin = (const float*)d_in[0];
    const int* golds;
    const float *Wih_f,*Whh_f,*b_f,*Wih_b,*Whh_b,*b_b;
    const float *subw_Wih,*subw_Whh,*subw_b,*word_Wih,*word_Whh,*word_b,*clsW,*clsb;
    if (dictOrder) {
        golds    = (const int*)  d_in[1];
        Wih_f    = (const float*)d_in[2];  Whh_f   = (const float*)d_in[3];
        b_f      = (const float*)d_in[4];  Wih_b   = (const float*)d_in[5];
        Whh_b    = (const float*)d_in[6];  b_b     = (const float*)d_in[7];
        subw_Wih = (const float*)d_in[8];  subw_Whh= (const float*)d_in[9];
        subw_b   = (const float*)d_in[10]; word_Wih= (const float*)d_in[11];
        word_Whh = (const float*)d_in[12]; word_b  = (const float*)d_in[13];
        clsW     = (const float*)d_in[14]; clsb    = (const float*)d_in[15];
    } else {
        Wih_f    = (const float*)d_in[1];  Whh_f   = (const float*)d_in[2];
        b_f      = (const float*)d_in[3];  Wih_b   = (const float*)d_in[4];
        Whh_b    = (const float*)d_in[5];  b_b     = (const float*)d_in[6];
        subw_Wih = (const float*)d_in[7];  subw_Whh= (const float*)d_in[8];
        subw_b   = (const float*)d_in[9];  word_Wih= (const float*)d_in[10];
        word_Whh = (const float*)d_in[11]; word_b  = (const float*)d_in[12];
        clsW     = (const float*)d_in[13]; clsb    = (const float*)d_in[14];
        golds    = (const int*)  d_in[15];
    }
    float* out = (float*)d_out;

    float *p_gif, *p_gib, *p_lo, *p_pre1;
    cudaGetSymbolAddress((void**)&p_gif,  g_gi_f);
    cudaGetSymbolAddress((void**)&p_gib,  g_gi_b);
    cudaGetSymbolAddress((void**)&p_lo,   g_lstm_out);
    cudaGetSymbolAddress((void**)&p_pre1, g_pre1);
    __nv_bfloat16 *p_Ah, *p_Al, *p_Wh, *p_Wl;
    cudaGetSymbolAddress((void**)&p_Ah, g_Ah);
    cudaGetSymbolAddress((void**)&p_Al, g_Al);
    cudaGetSymbolAddress((void**)&p_Wh, g_Wbh);
    cudaGetSymbolAddress((void**)&p_Wl, g_Wbl);
    __nv_bfloat16 *p_PLh, *p_PLl, *p_PSh, *p_PSl, *p_PWihh, *p_PWihl, *p_PWhhh, *p_PWhhl;
    cudaGetSymbolAddress((void**)&p_PLh, g_PL_h);
    cudaGetSymbolAddress((void**)&p_PLl, g_PL_l);
    cudaGetSymbolAddress((void**)&p_PSh, g_PS_h);
    cudaGetSymbolAddress((void**)&p_PSl, g_PS_l);
    cudaGetSymbolAddress((void**)&p_PWihh, g_PWih_h);
    cudaGetSymbolAddress((void**)&p_PWihl, g_PWih_l);
    cudaGetSymbolAddress((void**)&p_PWhhh, g_PWhh_h);
    cudaGetSymbolAddress((void**)&p_PWhhl, g_PWhh_l);

    zero_states<<<96, 256>>>();
    ptr_kernel<<<1, 64>>>(golds);

    // big tensor GEMMs for gate precompute
    conv_split<<<2048, 256>>>(hsin, p_Ah, p_Al, BB*SS*HH);
    conv_split<<<2048, 256>>>(Wih_f, p_Wh, p_Wl, G4*HH);
    gemm_mma<<<dim3(24, 128), 256>>>(p_Ah, p_Al, p_Wh, p_Wl, b_f, p_gif, HH, BB*SS);
    conv_split<<<2048, 256>>>(Wih_b, p_Wh, p_Wl, G4*HH);
    gemm_mma<<<dim3(24, 128), 256>>>(p_Ah, p_Al, p_Wh, p_Wl, b_b, p_gib, HH, BB*SS);

    // lstm recurrence weights: split + permute
    conv_split_perm<<<dim3(3, G4), 256>>>(Whh_f, p_PLh, p_PLl, HH);
    conv_split_perm<<<dim3(3, G4), 256>>>(Whh_b, p_PLh + (size_t)G4*HH, p_PLl + (size_t)G4*HH, HH);

    // persistent BiLSTM recurrence (256 steps inside), on tensor cores
    lstm_persist<<<NB_LSTM, 256>>>();

    // subword input precompute: (16320,1536)@(1536,3072)+b
    conv_split<<<4096, 256>>>(p_lo, p_Ah, p_Al, BB*SS*2*HH);
    conv_split<<<2048, 256>>>(subw_Wih, p_Wh, p_Wl, G4*2*HH);
    gemm_mma<<<dim3(24, 128), 256>>>(p_Ah, p_Al, p_Wh, p_Wl, subw_b, p_pre1, 2*HH, TT*BB);

    // decode weights: split + permute
    conv_split_perm<<<dim3(3, G4), 256>>>(subw_Whh, p_PSh, p_PSl, HH);
    conv_split_perm<<<dim3(6, G4), 256>>>(word_Wih, p_PWihh, p_PWihl, 2*HH);
    conv_split_perm<<<dim3(3, G4), 256>>>(word_Whh, p_PWhhh, p_PWhhl, HH);

    // classifier x_cur halves + first output row + decode barrier base
    ccur_kernel<<<4080, 256>>>(clsW, clsb, out);

    // persistent decode (255 steps + tail inside), on tensor cores
    decode_persist<<<NB_DEC, 256>>>(word_b, clsW, out);
}

// round 17
// speedup vs baseline: 2.6937x; 1.0306x over previous
#include <cuda_runtime.h>
#include <cuda_bf16.h>
#include <cstdint>
#include <math.h>

#define BB 64
#define SS 256
#define HH 768
#define G4 3072          // 4*H
#define TT 255           // decode steps
#define SLEN (2*SS+2)    // 514
#define WLEN (SS+1)      // 257
#define NB_LSTM 192
#define NB_DEC  289
#define SBSZ 27648       // helper smem: A hi/lo (18432B) + W hi/lo (9216B)

// ------------------- device scratch (BSS zero-initialized) -------------------
__device__ float g_gi_f[(size_t)SS*BB*G4];
__device__ float g_gi_b[(size_t)SS*BB*G4];
__device__ float g_lstm_out[(size_t)BB*SS*2*HH];  // [b][t][2H]
__device__ float g_pre1[(size_t)TT*BB*G4];        // x_prev @ subw_Wih.T + b
__device__ float g_sc[(size_t)BB*SLEN*HH];
__device__ float g_wc[(size_t)BB*WLEN*HH];
__device__ float g_bpart[(size_t)3*BB*G4];        // word pre-act partials, PERMUTED cols
__device__ float g_cstate[2*BB*HH];
__device__ float g_whbuf[BB*HH];
__device__ float g_ccur[TT*BB*2];
__device__ int   g_spa[TT*BB];
__device__ int   g_wpa[TT*BB];

// bf16 hi/lo lstm h-state: [dir*2 + parity][BB][HH]
__device__ __align__(16) __nv_bfloat16 g_lsH[(size_t)4*BB*HH];
__device__ __align__(16) __nv_bfloat16 g_lsL[(size_t)4*BB*HH];

// bf16 hi/lo activation stacks (decode)
__device__ __align__(16) __nv_bfloat16 g_shH[(size_t)BB*SLEN*HH];
__device__ __align__(16) __nv_bfloat16 g_shL[(size_t)BB*SLEN*HH];
__device__ __align__(16) __nv_bfloat16 g_whH[(size_t)BB*WLEN*HH];
__device__ __align__(16) __nv_bfloat16 g_whL[(size_t)BB*WLEN*HH];
__device__ __align__(16) __nv_bfloat16 g_h1H[BB*HH], g_h1L[BB*HH];
__device__ __align__(16) __nv_bfloat16 g_c1H[BB*HH], g_c1L[BB*HH];

// split-bf16 operand buffers for big tensor GEMMs
__device__ __align__(16) __nv_bfloat16 g_Ah[(size_t)16384*1536];
__device__ __align__(16) __nv_bfloat16 g_Al[(size_t)16384*1536];
__device__ __align__(16) __nv_bfloat16 g_Wbh[(size_t)3072*1536];
__device__ __align__(16) __nv_bfloat16 g_Wbl[(size_t)3072*1536];

// split + row-permuted (r' = j*4 + gate) weights for persistent kernels
__device__ __align__(16) __nv_bfloat16 g_PL_h[(size_t)2*G4*HH];   // lstm Whh f,b
__device__ __align__(16) __nv_bfloat16 g_PL_l[(size_t)2*G4*HH];
__device__ __align__(16) __nv_bfloat16 g_PS_h[(size_t)G4*HH];     // subw_Whh
__device__ __align__(16) __nv_bfloat16 g_PS_l[(size_t)G4*HH];
__device__ __align__(16) __nv_bfloat16 g_PWih_h[(size_t)G4*2*HH]; // word_Wih
__device__ __align__(16) __nv_bfloat16 g_PWih_l[(size_t)G4*2*HH];
__device__ __align__(16) __nv_bfloat16 g_PWhh_h[(size_t)G4*HH];   // word_Whh
__device__ __align__(16) __nv_bfloat16 g_PWhh_l[(size_t)G4*HH];

// monotonic barrier tickets (never reset; replay-safe via base snapshots)
__device__ unsigned g_tick_f, g_tick_b, g_tick_dec;
__device__ unsigned g_base_f, g_base_b, g_base_dec;

__device__ __forceinline__ float sigf(float x){ return 1.f/(1.f+expf(-x)); }

__device__ __forceinline__ void gbar2(unsigned* tick, unsigned target)
{
    __syncthreads();
    if (threadIdx.x == 0) {
        __threadfence();
        atomicAdd(tick, 1u);
        volatile unsigned* vt = tick;
        int spins = 0;
        while (*vt < target) { if (++spins > 2048) __nanosleep(128); }
        __threadfence();
    }
    __syncthreads();
}

// ---------------- split fp32 -> bf16 hi/lo ------------------------------------
__global__ void conv_split(const float* __restrict__ src,
                           __nv_bfloat16* __restrict__ hi, __nv_bfloat16* __restrict__ lo, int n)
{
    int stride = gridDim.x*blockDim.x;
    for (int i = blockIdx.x*blockDim.x + threadIdx.x; i < n; i += stride) {
        float x = src[i];
        __nv_bfloat16 h = __float2bfloat16(x);
        hi[i] = h;
        lo[i] = __float2bfloat16(x - __bfloat162float(h));
    }
}

// ------- split + permute rows: dst row (j*4+g) = src row (g*HH+j) -------------
__global__ void conv_split_perm(const float* __restrict__ src,
    __nv_bfloat16* __restrict__ hi, __nv_bfloat16* __restrict__ lo, int K)
{
    int r = blockIdx.y;
    int k = blockIdx.x*blockDim.x + threadIdx.x;
    if (k >= K) return;
    int gq = r / HH, jq = r - gq*HH;
    size_t di = (size_t)(jq*4 + gq)*K + k;
    float x = src[(size_t)r*K + k];
    __nv_bfloat16 h = __float2bfloat16(x);
    hi[di] = h;
    lo[di] = __float2bfloat16(x - __bfloat162float(h));
}

// ---------------- mma.sync bf16 helper ----------------------------------------
__device__ __forceinline__ void mma16816(float c[4],
    uint32_t a0, uint32_t a1, uint32_t a2, uint32_t a3, uint32_t b0, uint32_t b1)
{
    asm volatile(
        "mma.sync.aligned.m16n8k16.row.col.f32.bf16.bf16.f32 "
        "{%0,%1,%2,%3}, {%4,%5,%6,%7}, {%8,%9}, {%0,%1,%2,%3};"
        : "+f"(c[0]), "+f"(c[1]), "+f"(c[2]), "+f"(c[3])
        : "r"(a0), "r"(a1), "r"(a2), "r"(a3), "r"(b0), "r"(b1));
}

#define MSA 72   // smem row stride (bf16 elems)

// shared inner MMA for 64Mx32N tile (8 warps: wm=(wid/2)*16, wn=(wid&1)*16)
__device__ __forceinline__ void mma_inner(float (&acc)[2][4],
    const __nv_bfloat16* sA, const __nv_bfloat16* sW, int wm, int wn2, int g, int tg)
{
    #pragma unroll
    for (int kh = 0; kh < 4; kh++) {
        const int kb = kh*16 + tg*2;
        const __nv_bfloat16* ar_ = sA + (wm+g)*MSA + kb;
        uint32_t ah0=*(const uint32_t*)(ar_);
        uint32_t ah1=*(const uint32_t*)(ar_ + 8*MSA);
        uint32_t ah2=*(const uint32_t*)(ar_ + 8);
        uint32_t ah3=*(const uint32_t*)(ar_ + 8*MSA + 8);
        const __nv_bfloat16* al_ = ar_ + 64*MSA;
        uint32_t bl0=*(const uint32_t*)(al_);
        uint32_t bl1=*(const uint32_t*)(al_ + 8*MSA);
        uint32_t bl2=*(const uint32_t*)(al_ + 8);
        uint32_t bl3=*(const uint32_t*)(al_ + 8*MSA + 8);
        #pragma unroll
        for (int nf = 0; nf < 2; nf++) {
            const __nv_bfloat16* br_ = sW + (wn2+nf*8+g)*MSA + kb;
            uint32_t b0=*(const uint32_t*)(br_), b1=*(const uint32_t*)(br_+8);
            const __nv_bfloat16* bw_ = br_ + 32*MSA;
            uint32_t c0=*(const uint32_t*)(bw_), c1=*(const uint32_t*)(bw_+8);
            mma16816(acc[nf], ah0,ah1,ah2,ah3, b0,b1);
            mma16816(acc[nf], ah0,ah1,ah2,ah3, c0,c1);
            mma16816(acc[nf], bl0,bl1,bl2,bl3, b0,b1);
        }
    }
}

// ===== bf16-A accumulator: A pre-split hi/lo (gathered rows), pure copies =====
__device__ __forceinline__ void mma_seg_b(
    float (&acc)[2][4],
    const __nv_bfloat16* const* aph, const __nv_bfloat16* const* apl,
    const __nv_bfloat16* __restrict__ Wh8, const __nv_bfloat16* __restrict__ Wl8,
    int wK, char* sb, int tid)
{
    __nv_bfloat16* sA = (__nv_bfloat16*)sb;
    __nv_bfloat16* sW = (__nv_bfloat16*)(sb + 18432);
    const int arow = tid >> 2, akq = (tid & 3) << 4;
    const int wrow = tid >> 3, wkq = (tid & 7) << 3;
    const int lane = tid & 31, wid = tid >> 5;
    const int g = lane >> 2, tg = lane & 3;
    const int wm = (wid >> 1) << 4;
    const int wn2 = (wid & 1) << 4;
    const __nv_bfloat16* pah = aph[arow] + akq;
    const __nv_bfloat16* pal = apl[arow] + akq;
    const __nv_bfloat16* wph = Wh8 + (size_t)wrow*wK + wkq;
    const __nv_bfloat16* wpl = Wl8 + (size_t)wrow*wK + wkq;
    uint4 h0 = *(const uint4*)pah, h1 = *(const uint4*)(pah+8);
    uint4 l0 = *(const uint4*)pal, l1 = *(const uint4*)(pal+8);
    uint4 wh = *(const uint4*)wph, wl = *(const uint4*)wpl;
    #pragma unroll 1
    for (int k0 = 0; k0 < HH; k0 += 64) {
        __syncthreads();
        {
            __nv_bfloat16* da = sA + arow*MSA + akq;
            *(uint4*)(da)   = h0; *(uint4*)(da+8) = h1;
            __nv_bfloat16* dl = da + 64*MSA;
            *(uint4*)(dl)   = l0; *(uint4*)(dl+8) = l1;
            __nv_bfloat16* dw = sW + wrow*MSA + wkq;
            *(uint4*)dw = wh;
            *(uint4*)(dw + 32*MSA) = wl;
        }
        __syncthreads();
        if (k0 + 64 < HH) {
            h0 = *(const uint4*)(pah + k0 + 64); h1 = *(const uint4*)(pah + k0 + 72);
            l0 = *(const uint4*)(pal + k0 + 64); l1 = *(const uint4*)(pal + k0 + 72);
            wh = *(const uint4*)(wph + k0 + 64); wl = *(const uint4*)(wpl + k0 + 64);
        }
        mma_inner(acc, sA, sW, wm, wn2, g, tg);
    }
}

__device__ __forceinline__ void dump_acc(float* sOut, float (&acc)[2][4], int tid)
{
    const int lane=tid&31, wid=tid>>5, g=lane>>2, tg=lane&3;
    const int wm=(wid>>1)<<4, wn2=(wid&1)<<4;
    #pragma unroll
    for (int nf=0; nf<2; nf++) {
        int col = wn2 + nf*8 + tg*2;
        sOut[(wm+g)*36+col]   = acc[nf][0];
        sOut[(wm+g)*36+col+1] = acc[nf][1];
        sOut[(wm+g+8)*36+col]   = acc[nf][2];
        sOut[(wm+g+8)*36+col+1] = acc[nf][3];
    }
}

// -------- big tensor GEMM via mma.sync ----------------------------------------
#define MM_SA 40
__global__ __launch_bounds__(256) void gemm_mma(
    const __nv_bfloat16* __restrict__ Ah, const __nv_bfloat16* __restrict__ Al,
    const __nv_bfloat16* __restrict__ Wh, const __nv_bfloat16* __restrict__ Wl,
    const float* __restrict__ bias, float* __restrict__ C, int K, int Mtot)
{
    __shared__ __nv_bfloat16 sAh[128*MM_SA], sAl[128*MM_SA];
    __shared__ __nv_bfloat16 sWh[128*MM_SA], sWl[128*MM_SA];
    const int tid = threadIdx.x, wid = tid >> 5, lane = tid & 31;
    const int g = lane >> 2, tg = lane & 3;
    const int bm = blockIdx.y << 7, bn = blockIdx.x << 7;
    const int wm = (wid >> 2) << 6, wn = (wid & 3) << 5;
    const int lrow = tid >> 1, lhalf = tid & 1;

    const int arow_i = bm + lrow;
    const bool aval = arow_i < Mtot;
    const size_t a_off = ((size_t)(arow_i & 63)*SS + (arow_i >> 6))*K + lhalf*16;
    const size_t w_off = (size_t)(bn + lrow)*K + lhalf*16;
    const uint32_t s_st = lrow*MM_SA + lhalf*16;

    float acc[4][4][4];
    #pragma unroll
    for (int mf=0; mf<4; mf++)
        #pragma unroll
        for (int nf=0; nf<4; nf++)
            #pragma unroll
            for (int q=0; q<4; q++) acc[mf][nf][q] = 0.f;

    const uint4 z4 = make_uint4(0u,0u,0u,0u);
    uint4 pah0, pah1, pal0, pal1, pwh0, pwh1, pwl0, pwl1;
    pah0 = aval ? *(const uint4*)(Ah + a_off)     : z4;
    pah1 = aval ? *(const uint4*)(Ah + a_off + 8) : z4;
    pal0 = aval ? *(const uint4*)(Al + a_off)     : z4;
    pal1 = aval ? *(const uint4*)(Al + a_off + 8) : z4;
    pwh0 = *(const uint4*)(Wh + w_off);     pwh1 = *(const uint4*)(Wh + w_off + 8);
    pwl0 = *(const uint4*)(Wl + w_off);     pwl1 = *(const uint4*)(Wl + w_off + 8);

    for (int k0 = 0; k0 < K; k0 += 32) {
        __syncthreads();
        *(uint4*)(sAh + s_st) = pah0; *(uint4*)(sAh + s_st + 8) = pah1;
        *(uint4*)(sAl + s_st) = pal0; *(uint4*)(sAl + s_st + 8) = pal1;
        *(uint4*)(sWh + s_st) = pwh0; *(uint4*)(sWh + s_st + 8) = pwh1;
        *(uint4*)(sWl + s_st) = pwl0; *(uint4*)(sWl + s_st + 8) = pwl1;
        __syncthreads();
        if (k0 + 32 < K) {
            size_t an = a_off + k0 + 32, wn2 = w_off + k0 + 32;
            pah0 = aval ? *(const uint4*)(Ah + an)     : z4;
            pah1 = aval ? *(const uint4*)(Ah + an + 8) : z4;
            pal0 = aval ? *(const uint4*)(Al + an)     : z4;
            pal1 = aval ? *(const uint4*)(Al + an + 8) : z4;
            pwh0 = *(const uint4*)(Wh + wn2);  pwh1 = *(const uint4*)(Wh + wn2 + 8);
            pwl0 = *(const uint4*)(Wl + wn2);  pwl1 = *(const uint4*)(Wl + wn2 + 8);
        }
        #pragma unroll
        for (int kh = 0; kh < 2; kh++) {
            const int kb = kh*16 + tg*2;
            uint32_t bh[4][2], bl2[4][2];
            #pragma unroll
            for (int nf = 0; nf < 4; nf++) {
                const __nv_bfloat16* wr = sWh + (wn + nf*8 + g)*MM_SA;
                const __nv_bfloat16* wl3 = sWl + (wn + nf*8 + g)*MM_SA;
                bh[nf][0] = *(const uint32_t*)(wr + kb);
                bh[nf][1] = *(const uint32_t*)(wr + kb + 8);
                bl2[nf][0] = *(const uint32_t*)(wl3 + kb);
                bl2[nf][1] = *(const uint32_t*)(wl3 + kb + 8);
            }
            #pragma unroll
            for (int mf = 0; mf < 4; mf++) {
                const __nv_bfloat16* arh = sAh + (wm + mf*16 + g)*MM_SA;
                const __nv_bfloat16* arl = sAl + (wm + mf*16 + g)*MM_SA;
                uint32_t ah0 = *(const uint32_t*)(arh + kb);
                uint32_t ah1 = *(const uint32_t*)(arh + 8*MM_SA + kb);
                uint32_t ah2 = *(const uint32_t*)(arh + kb + 8);
                uint32_t ah3 = *(const uint32_t*)(arh + 8*MM_SA + kb + 8);
                uint32_t al0 = *(const uint32_t*)(arl + kb);
                uint32_t al1 = *(const uint32_t*)(arl + 8*MM_SA + kb);
                uint32_t al2 = *(const uint32_t*)(arl + kb + 8);
                uint32_t al3 = *(const uint32_t*)(arl + 8*MM_SA + kb + 8);
                #pragma unroll
                for (int nf = 0; nf < 4; nf++) {
                    mma16816(acc[mf][nf], ah0, ah1, ah2, ah3, bh[nf][0], bh[nf][1]);
                    mma16816(acc[mf][nf], ah0, ah1, ah2, ah3, bl2[nf][0], bl2[nf][1]);
                    mma16816(acc[mf][nf], al0, al1, al2, al3, bh[nf][0], bh[nf][1]);
                }
            }
        }
    }

    #pragma unroll
    for (int mf = 0; mf < 4; mf++) {
        int r0 = bm + wm + mf*16 + g;
        #pragma unroll
        for (int nf = 0; nf < 4; nf++) {
            int col = bn + wn + nf*8 + tg*2;
            float b0 = bias[col], b1 = bias[col+1];
            if (r0 < Mtot) {
                float2 v = make_float2(acc[mf][nf][0] + b0, acc[mf][nf][1] + b1);
                *(float2*)(C + (size_t)r0*G4 + col) = v;
            }
            if (r0 + 8 < Mtot) {
                float2 v = make_float2(acc[mf][nf][2] + b0, acc[mf][nf][3] + b1);
                *(float2*)(C + (size_t)(r0+8)*G4 + col) = v;
            }
        }
    }
}

// ------------- zero per-launch states + snapshot lstm barrier bases -----------
__global__ void zero_states()
{
    int gt = blockIdx.x*blockDim.x + threadIdx.x;
    if (gt == 0) { g_base_f = g_tick_f; g_base_b = g_tick_b; }
    int stride = gridDim.x*blockDim.x;
    for (int i = gt; i < 4*BB*HH; i += stride) {
        g_lsH[i] = __float2bfloat16(0.f);
        g_lsL[i] = __float2bfloat16(0.f);
    }
    for (int i = gt; i < 2*BB*HH; i += stride) g_cstate[i]=0.f;
}

// ------------------- precompute stack pointers from golds -------------------
__global__ void ptr_kernel(const int* __restrict__ golds)
{
    int b = threadIdx.x;
    if (b >= BB) return;
    int sp = 0, wp = 0;
    for (int t = 0; t < TT; t++) {
        g_spa[t*BB+b] = sp;
        g_wpa[t*BB+b] = wp;
        int g = golds[b*SS + t + 1];
        sp += (g==0) ? 1 : 2;
        wp += (g==0) ? 0 : 1;
    }
}

// ---------- persistent BiLSTM: 192 blocks (96/dir), 256 steps, bf16 state -----
__global__ __launch_bounds__(256, 2) void lstm_persist()
{
    __shared__ __align__(16) char sb[SBSZ];
    __shared__ const __nv_bfloat16* aph[BB];
    __shared__ const __nv_bfloat16* apl[BB];
    const int tid = threadIdx.x, bid = blockIdx.x;
    const int dir = bid / 96;
    const int j0 = (bid % 96) << 3;
    unsigned* tick = dir ? &g_tick_b : &g_tick_f;
    const unsigned base = dir ? g_base_b : g_base_f;
    const float* gibase = dir ? g_gi_b : g_gi_f;
    float* cst = g_cstate + (size_t)dir*BB*HH;
    const __nv_bfloat16* Wh8 = g_PL_h + ((size_t)dir*G4 + j0*4)*HH;
    const __nv_bfloat16* Wl8 = g_PL_l + ((size_t)dir*G4 + j0*4)*HH;
    const int jj = tid & 7, mg = tid >> 3;
    const int j = j0 + jj;

    for (int t = 0; t < SS; t++) {
        const int tt = dir ? (SS-1-t) : t;
        const float* gi = gibase + (size_t)tt*BB*G4;
        const size_t inb  = (size_t)(dir*2 + (t&1))*BB*HH;
        const size_t outb = (size_t)(dir*2 + ((t&1)^1))*BB*HH;
        if (tid < BB) {
            aph[tid] = g_lsH + inb + (size_t)tid*HH;
            apl[tid] = g_lsL + inb + (size_t)tid*HH;
        }
        __syncthreads();
        float acc[2][4] = {};
        mma_seg_b(acc, aph, apl, Wh8, Wl8, HH, sb, tid);
        float* sOut = (float*)sb;
        __syncthreads();
        dump_acc(sOut, acc, tid);
        __syncthreads();
        #pragma unroll
        for (int mi=0; mi<2; mi++) {
            int b = (mg<<1) + mi;
            float vi = gi[b*G4 +        j] + sOut[b*36 + jj*4 + 0];
            float vf = gi[b*G4 + HH +   j] + sOut[b*36 + jj*4 + 1];
            float vg = gi[b*G4 + 2*HH + j] + sOut[b*36 + jj*4 + 2];
            float vo = gi[b*G4 + 3*HH + j] + sOut[b*36 + jj*4 + 3];
            float c = sigf(vf)*cst[b*HH+j] + sigf(vi)*tanhf(vg);
            float h = sigf(vo)*tanhf(c);
            cst[b*HH+j] = c;
            __nv_bfloat16 hh = __float2bfloat16(h);
            g_lsH[outb + (size_t)b*HH + j] = hh;
            g_lsL[outb + (size_t)b*HH + j] = __float2bfloat16(h - __bfloat162float(hh));
            g_lstm_out[((size_t)b*SS + tt)*(2*HH) + dir*HH + j] = h;
        }
        if (t < SS-1) gbar2(tick, base + (unsigned)(t+1)*96);
    }
}

// ------------------- persistent decode: 289 blocks, 255 steps -----------------
__global__ __launch_bounds__(256, 2) void decode_persist(
    const float* __restrict__ word_b, const float* __restrict__ clsW,
    float* __restrict__ out)
{
    __shared__ __align__(16) char sb[SBSZ];
    __shared__ const __nv_bfloat16* aph[BB];
    __shared__ const __nv_bfloat16* apl[BB];
    __shared__ int idx_s[BB];
    const int tid = threadIdx.x, bid = blockIdx.x;
    const unsigned base = g_base_dec;

    for (int t = 0; t <= TT; t++) {
        // ---- phase A: subword cell (blocks 0-95) + word epilogue of t-1 (96-287) --
        if (bid < 96 && t < TT) {
            const int j0 = bid << 3;
            if (tid < BB) {
                int sp = g_spa[t*BB + tid];
                idx_s[tid] = sp;
                aph[tid] = g_shH + ((size_t)tid*SLEN + sp)*HH;
                apl[tid] = g_shL + ((size_t)tid*SLEN + sp)*HH;
            }
            __syncthreads();
            float acc[2][4] = {};
            mma_seg_b(acc, aph, apl, g_PS_h + (size_t)(j0*4)*HH, g_PS_l + (size_t)(j0*4)*HH,
                      HH, sb, tid);
            float* sOut = (float*)sb;
            __syncthreads();
            dump_acc(sOut, acc, tid);
            __syncthreads();
            const float* gi = g_pre1 + (size_t)t*BB*G4;
            const int jj = tid & 7, mg = tid >> 3;
            const int j = j0 + jj;
            #pragma unroll
            for (int mi=0; mi<2; mi++) {
                int b = (mg<<1) + mi;
                int sp = idx_s[b];
                float vi = gi[b*G4 +        j] + sOut[b*36 + jj*4 + 0];
                float vf = gi[b*G4 + HH +   j] + sOut[b*36 + jj*4 + 1];
                float vg = gi[b*G4 + 2*HH + j] + sOut[b*36 + jj*4 + 2];
                float vo = gi[b*G4 + 3*HH + j] + sOut[b*36 + jj*4 + 3];
                float c = sigf(vf)*g_sc[((size_t)b*SLEN + sp)*HH + j] + sigf(vi)*tanhf(vg);
                float h = sigf(vo)*tanhf(c);
                size_t si = ((size_t)b*SLEN + sp + 1)*HH + j;
                g_sc[si] = c;
                __nv_bfloat16 hh = __float2bfloat16(h);
                __nv_bfloat16 hl = __float2bfloat16(h - __bfloat162float(hh));
                g_shH[si] = hh; g_shL[si] = hl;
                g_h1H[b*HH+j] = hh; g_h1L[b*HH+j] = hl;
                __nv_bfloat16 ch = __float2bfloat16(c);
                g_c1H[b*HH+j] = ch;
                g_c1L[b*HH+j] = __float2bfloat16(c - __bfloat162float(ch));
            }
        } else if (bid >= 96 && bid < 288 && t > 0) {
            // word-cell epilogue for step u = t-1; sums 3 permuted partial segs
            const int u = t - 1;
            const int tile = bid - 96;          // 0..191
            const int b = tile / 3;
            const int j = (tile % 3)*256 + tid;
            const int wp = g_wpa[u*BB + b];
            float4 p0 = *(const float4*)&g_bpart[(size_t)b*G4 + j*4];
            float4 p1 = *(const float4*)&g_bpart[(size_t)(BB + b)*G4 + j*4];
            float4 p2 = *(const float4*)&g_bpart[(size_t)(2*BB + b)*G4 + j*4];
            float vi = word_b[j]        + p0.x + p1.x + p2.x;
            float vf = word_b[HH + j]   + p0.y + p1.y + p2.y;
            float vg = word_b[2*HH + j] + p0.z + p1.z + p2.z;
            float vo = word_b[3*HH + j] + p0.w + p1.w + p2.w;
            float c = sigf(vf)*g_wc[((size_t)b*WLEN + wp)*HH + j] + sigf(vi)*tanhf(vg);
            float h = sigf(vo)*tanhf(c);
            size_t wi = ((size_t)b*WLEN + wp + 1)*HH + j;
            g_wc[wi] = c;
            __nv_bfloat16 hh = __float2bfloat16(h);
            g_whH[wi] = hh;
            g_whL[wi] = __float2bfloat16(h - __bfloat162float(hh));
            g_whbuf[b*HH + j] = h;
        }
        gbar2(&g_tick_dec, base + (unsigned)(2*t+1)*NB_DEC);

        // ---- phase B: word GEMM K-split over 288 blocks + classifier (288) --------
        if (bid < 288 && t < TT) {
            const int seg = bid / 96;
            const int j0 = (bid % 96) << 3;
            if (tid < BB) {
                int wp = g_wpa[t*BB + tid];
                idx_s[tid] = wp;
                if (seg == 0)      { aph[tid] = g_h1H + tid*HH; apl[tid] = g_h1L + tid*HH; }
                else if (seg == 1) { aph[tid] = g_c1H + tid*HH; apl[tid] = g_c1L + tid*HH; }
                else               { aph[tid] = g_whH + ((size_t)tid*WLEN + wp)*HH;
                                     apl[tid] = g_whL + ((size_t)tid*WLEN + wp)*HH; }
            }
            __syncthreads();
            const __nv_bfloat16 *Wh8, *Wl8;
            int wK;
            if (seg == 0)      { Wh8 = g_PWih_h + (size_t)(j0*4)*(2*HH);
                                 Wl8 = g_PWih_l + (size_t)(j0*4)*(2*HH); wK = 2*HH; }
            else if (seg == 1) { Wh8 = g_PWih_h + (size_t)(j0*4)*(2*HH) + HH;
                                 Wl8 = g_PWih_l + (size_t)(j0*4)*(2*HH) + HH; wK = 2*HH; }
            else               { Wh8 = g_PWhh_h + (size_t)(j0*4)*HH;
                                 Wl8 = g_PWhh_l + (size_t)(j0*4)*HH; wK = HH; }
            float acc[2][4] = {};
            mma_seg_b(acc, aph, apl, Wh8, Wl8, wK, sb, tid);
            // store partial pre-activations (permuted cols) to g_bpart[seg]
            float* part = g_bpart + (size_t)seg*BB*G4;
            const int lane=tid&31, wid2=tid>>5, g2=lane>>2, tg=lane&3;
            const int wm=(wid2>>1)<<4, wn2=(wid2&1)<<4;
            #pragma unroll
            for (int nf=0; nf<2; nf++) {
                int col = j0*4 + wn2 + nf*8 + tg*2;
                *(float2*)&part[(size_t)(wm+g2)*G4 + col]   = make_float2(acc[nf][0], acc[nf][1]);
                *(float2*)&part[(size_t)(wm+g2+8)*G4 + col] = make_float2(acc[nf][2], acc[nf][3]);
            }
        } else if (bid == 288 && t > 0) {
            // classifier for step u = t-1 -> output position t
            const int u = t - 1;
            if (tid < 128) {
                int b = tid >> 1, c = tid & 1;
                const float* w = clsW + c*(3*HH);
                const float* hb = g_whbuf + b*HH;
                float s0 = g_ccur[u*BB*2 + (b<<1) + c], s1=0.f, s2=0.f, s3=0.f;
                #pragma unroll 4
                for (int k = 0; k < HH; k += 4) {
                    s0 += hb[k]*w[k];     s1 += hb[k+1]*w[k+1];
                    s2 += hb[k+2]*w[k+2]; s3 += hb[k+3]*w[k+3];
                }
                out[((size_t)b*SS + u + 1)*2 + c] = s0+s1+s2+s3;
            }
        }
        if (t < TT) gbar2(&g_tick_dec, base + (unsigned)(2*t+2)*NB_DEC);
    }
}

// -------- x_cur classifier halves + first row + decode barrier base snapshot ---
__global__ void ccur_kernel(const float* __restrict__ clsW, const float* __restrict__ clsb,
                            float* __restrict__ out)
{
    int gt = blockIdx.x*blockDim.x + threadIdx.x;
    if (gt == 0) g_base_dec = g_tick_dec;
    int gw = gt >> 5, lane = gt & 31;
    if (gw < TT*BB*2) {
        int t = gw >> 7, rem = gw & 127, b = rem >> 1, c = rem & 1;
        const float* x = g_lstm_out + ((size_t)b*SS + t + 1)*(2*HH);
        const float* w = clsW + c*(3*HH) + HH;
        float s = 0.f;
        for (int k = lane; k < 2*HH; k += 32) s += x[k]*w[k];
        #pragma unroll
        for (int o = 16; o; o >>= 1) s += __shfl_xor_sync(0xffffffffu, s, o);
        if (lane == 0) g_ccur[gw] = s + clsb[c];
    }
    if (gt < 128) {
        int b = gt >> 1, c = gt & 1;
        out[(size_t)b*SS*2 + c] = c ? 1.f : -1.f;
    }
}

// ------------------- launch -------------------
extern "C" void kernel_launch(void* const* d_in, const int* in_sizes, int n_in,
                              void* d_out, int out_size)
{
    const int dictOrder = (in_sizes[1] == BB*SS);
    const float* hsin = (const float*)d_in[0];
    const int* golds;
    const float *Wih_f,*Whh_f,*b_f,*Wih_b,*Whh_b,*b_b;
    const float *subw_Wih,*subw_Whh,*subw_b,*word_Wih,*word_Whh,*word_b,*clsW,*clsb;
    if (dictOrder) {
        golds    = (const int*)  d_in[1];
        Wih_f    = (const float*)d_in[2];  Whh_f   = (const float*)d_in[3];
        b_f      = (const float*)d_in[4];  Wih_b   = (const float*)d_in[5];
        Whh_b    = (const float*)d_in[6];  b_b     = (const float*)d_in[7];
        subw_Wih = (const float*)d_in[8];  subw_Whh= (const float*)d_in[9];
        subw_b   = (const float*)d_in[10]; word_Wih= (const float*)d_in[11];
        word_Whh = (const float*)d_in[12]; word_b  = (const float*)d_in[13];
        clsW     = (const float*)d_in[14]; clsb    = (const float*)d_in[15];
    } else {
        Wih_f    = (const float*)d_in[1];  Whh_f   = (const float*)d_in[2];
        b_f      = (const float*)d_in[3];  Wih_b   = (const float*)d_in[4];
        Whh_b    = (const float*)d_in[5];  b_b     = (const float*)d_in[6];
        subw_Wih = (const float*)d_in[7];  subw_Whh= (const float*)d_in[8];
        subw_b   = (const float*)d_in[9];  word_Wih= (const float*)d_in[10];
        word_Whh = (const float*)d_in[11]; word_b  = (const float*)d_in[12];
        clsW     = (const float*)d_in[13]; clsb    = (const float*)d_in[14];
        golds    = (const int*)  d_in[15];
    }
    float* out = (float*)d_out;

    float *p_gif, *p_gib, *p_lo, *p_pre1;
    cudaGetSymbolAddress((void**)&p_gif,  g_gi_f);
    cudaGetSymbolAddress((void**)&p_gib,  g_gi_b);
    cudaGetSymbolAddress((void**)&p_lo,   g_lstm_out);
    cudaGetSymbolAddress((void**)&p_pre1, g_pre1);
    __nv_bfloat16 *p_Ah, *p_Al, *p_Wh, *p_Wl;
    cudaGetSymbolAddress((void**)&p_Ah, g_Ah);
    cudaGetSymbolAddress((void**)&p_Al, g_Al);
    cudaGetSymbolAddress((void**)&p_Wh, g_Wbh);
    cudaGetSymbolAddress((void**)&p_Wl, g_Wbl);
    __nv_bfloat16 *p_PLh, *p_PLl, *p_PSh, *p_PSl, *p_PWihh, *p_PWihl, *p_PWhhh, *p_PWhhl;
    cudaGetSymbolAddress((void**)&p_PLh, g_PL_h);
    cudaGetSymbolAddress((void**)&p_PLl, g_PL_l);
    cudaGetSymbolAddress((void**)&p_PSh, g_PS_h);
    cudaGetSymbolAddress((void**)&p_PSl, g_PS_l);
    cudaGetSymbolAddress((void**)&p_PWihh, g_PWih_h);
    cudaGetSymbolAddress((void**)&p_PWihl, g_PWih_l);
    cudaGetSymbolAddress((void**)&p_PWhhh, g_PWhh_h);
    cudaGetSymbolAddress((void**)&p_PWhhl, g_PWhh_l);

    zero_states<<<96, 256>>>();
    ptr_kernel<<<1, 64>>>(golds);

    // big tensor GEMMs for gate precompute
    conv_split<<<2048, 256>>>(hsin, p_Ah, p_Al, BB*SS*HH);
    conv_split<<<2048, 256>>>(Wih_f, p_Wh, p_Wl, G4*HH);
    gemm_mma<<<dim3(24, 128), 256>>>(p_Ah, p_Al, p_Wh, p_Wl, b_f, p_gif, HH, BB*SS);
    conv_split<<<2048, 256>>>(Wih_b, p_Wh, p_Wl, G4*HH);
    gemm_mma<<<dim3(24, 128), 256>>>(p_Ah, p_Al, p_Wh, p_Wl, b_b, p_gib, HH, BB*SS);

    // lstm recurrence weights: split + permute
    conv_split_perm<<<dim3(3, G4), 256>>>(Whh_f, p_PLh, p_PLl, HH);
    conv_split_perm<<<dim3(3, G4), 256>>>(Whh_b, p_PLh + (size_t)G4*HH, p_PLl + (size_t)G4*HH, HH);

    // persistent BiLSTM recurrence (256 steps inside), bf16 state, per-dir barriers
    lstm_persist<<<NB_LSTM, 256>>>();

    // subword input precompute: (16320,1536)@(1536,3072)+b
    conv_split<<<4096, 256>>>(p_lo, p_Ah, p_Al, BB*SS*2*HH);
    conv_split<<<2048, 256>>>(subw_Wih, p_Wh, p_Wl, G4*2*HH);
    gemm_mma<<<dim3(24, 128), 256>>>(p_Ah, p_Al, p_Wh, p_Wl, subw_b, p_pre1, 2*HH, TT*BB);

    // decode weights: split + permute
    conv_split_perm<<<dim3(3, G4), 256>>>(subw_Whh, p_PSh, p_PSl, HH);
    conv_split_perm<<<dim3(6, G4), 256>>>(word_Wih, p_PWihh, p_PWihl, 2*HH);
    conv_split_perm<<<dim3(3, G4), 256>>>(word_Whh, p_PWhhh, p_PWhhl, HH);

    // classifier x_cur halves + first output row + decode barrier base
    ccur_kernel<<<4080, 256>>>(clsW, clsb, out);

    // persistent decode (255 steps + tail inside), on tensor cores
    decode_persist<<<NB_DEC, 256>>>(word_b, clsW, out);
}